// round 1
// baseline (speedup 1.0000x reference)
#include <cuda_runtime.h>
#include <math.h>

#define BATCH 32
#define NNODE 33
#define NPAD  36
#define CH    64

// ---------------- device scratch (no runtime allocation allowed) ----------------
__device__ float g_bufA[(size_t)BATCH * 510 * NNODE * CH];   // ~138 MB
__device__ float g_bufB[(size_t)BATCH * 510 * NNODE * CH];   // ~138 MB
__device__ float g_L[NPAD * NPAD];
__device__ float g_w1a[3 * 3 * 3 * 64];      // reordered s1_tc1 (Ci=3)
__device__ float g_w1b[3 * 64 * 3 * 64];     // reordered s1_tc2
__device__ float g_w2a[3 * 64 * 3 * 64];     // reordered s2_tc1
__device__ float g_w2b[3 * 64 * 3 * 64];     // reordered s2_tc2
__device__ float g_scl1[NNODE], g_shf1[NNODE];
__device__ float g_scl2[NNODE], g_shf2[NNODE];
__device__ float g_M[BATCH * NNODE * CH];

// ---------------- small setup kernels ----------------

// Build dense normalized Laplacian-ish operator L[tgt][src] = -dinv[src]*dinv[tgt]
// (accumulated over duplicate edges), zero-padded to NPAD.
__global__ void setup_L_kernel(const int* __restrict__ ei, int ne) {
    double deg[NNODE];
    for (int i = 0; i < NNODE; i++) deg[i] = 0.0;
    for (int e = 0; e < ne; e++) deg[ei[e]] += 1.0;
    double dinv[NNODE];
    for (int i = 0; i < NNODE; i++) dinv[i] = (deg[i] > 0.0) ? (1.0 / sqrt(deg[i])) : 0.0;
    for (int i = 0; i < NPAD * NPAD; i++) g_L[i] = 0.0f;
    for (int e = 0; e < ne; e++) {
        int s = ei[e];
        int t = ei[ne + e];
        g_L[t * NPAD + s] += (float)(-dinv[s] * dinv[t]);
    }
}

// (3, O=64, Ci, 1, ks=3)  ->  [g][ci][k][o]
__global__ void reorder_w_kernel(const float* __restrict__ win, float* __restrict__ wout, int CI) {
    int i = blockIdx.x * blockDim.x + threadIdx.x;
    int n = 3 * CI * 3 * 64;
    if (i >= n) return;
    int o  = i & 63;
    int k  = (i >> 6) % 3;
    int ci = (i / 192) % CI;
    int g  = i / (192 * CI);
    wout[i] = win[((g * 64 + o) * CI + ci) * 3 + k];
}

// ---------------- gated temporal conv (implicit GEMM) ----------------
// out[b,t',n,o] = relu(P * sigmoid(Q) + R), gate_g = sum_{ci,k} in[b,t'+k,n,ci]*w[g,o,ci,k] + b[g,o]
// mode=1: per-node affine (BN) + relu applied to the input while loading (fused BN of previous layer).
template <int CI>
__global__ void __launch_bounds__(512)
tconv_kernel(const float* __restrict__ xin, int Tin,
             const float* __restrict__ wre,   // [3][CI][3][64] reordered
             const float* __restrict__ bias,  // [3][64]
             const float* __restrict__ scl, const float* __restrict__ shf, int mode,
             float* __restrict__ out) {
    constexpr int CT = 64;  // time steps per CTA
    constexpr int TO = 8;   // time steps per thread
    extern __shared__ float sm[];
    float* ws = sm;                      // 3*CI*3*64
    float* xs = sm + 3 * CI * 3 * 64;    // (CT+2)*CI

    const int tid  = threadIdx.y * 64 + threadIdx.x;
    const int nth  = 64 * (CT / TO);
    const int Tout = Tin - 2;
    const int t0   = blockIdx.x * CT;
    const int n    = blockIdx.y;
    const int b    = blockIdx.z;

    for (int i = tid; i < 3 * CI * 3 * 64; i += nth) ws[i] = wre[i];

    float sc = 1.f, sh = 0.f;
    if (mode) { sc = scl[n]; sh = shf[n]; }
    for (int i = tid; i < (CT + 2) * CI; i += nth) {
        int tt = i / CI, ci = i % CI;
        int t = t0 + tt;
        float v = 0.f;
        if (t < Tin) v = xin[(((size_t)b * Tin + t) * NNODE + n) * CI + ci];
        if (mode) v = fmaxf(fmaf(v, sc, sh), 0.f);
        xs[i] = v;
    }
    __syncthreads();

    const int o  = threadIdx.x;
    const int tb = threadIdx.y * TO;

    float acc[3][TO];
#pragma unroll
    for (int g = 0; g < 3; g++)
#pragma unroll
        for (int tt = 0; tt < TO; tt++) acc[g][tt] = 0.f;

#pragma unroll 2
    for (int ci = 0; ci < CI; ci++) {
        float xv[TO + 2];
#pragma unroll
        for (int j = 0; j < TO + 2; j++) xv[j] = xs[(tb + j) * CI + ci];
#pragma unroll
        for (int g = 0; g < 3; g++) {
#pragma unroll
            for (int k = 0; k < 3; k++) {
                float w = ws[((g * CI + ci) * 3 + k) * 64 + o];
#pragma unroll
                for (int tt = 0; tt < TO; tt++) acc[g][tt] = fmaf(xv[tt + k], w, acc[g][tt]);
            }
        }
    }

    const float bP = bias[o], bQ = bias[64 + o], bR = bias[128 + o];
#pragma unroll
    for (int tt = 0; tt < TO; tt++) {
        int t = t0 + tb + tt;
        if (t < Tout) {
            float P = acc[0][tt] + bP;
            float Q = acc[1][tt] + bQ;
            float R = acc[2][tt] + bR;
            float sg = 1.f / (1.f + __expf(-Q));
            float h = fmaxf(fmaf(P, sg, R), 0.f);
            out[(((size_t)b * Tout + t) * NNODE + n) * CH + o] = h;
        }
    }
}

// ---------------- ChebConv K=3 + relu ----------------
__device__ __forceinline__ void fma8(float (&acc)[8], float s, const float4& va, const float4& vb) {
    acc[0] = fmaf(s, va.x, acc[0]);
    acc[1] = fmaf(s, va.y, acc[1]);
    acc[2] = fmaf(s, va.z, acc[2]);
    acc[3] = fmaf(s, va.w, acc[3]);
    acc[4] = fmaf(s, vb.x, acc[4]);
    acc[5] = fmaf(s, vb.y, acc[5]);
    acc[6] = fmaf(s, vb.z, acc[6]);
    acc[7] = fmaf(s, vb.w, acc[7]);
}

__global__ void __launch_bounds__(288)
cheb_kernel(const float* __restrict__ zin, int T,
            const float* __restrict__ cw,  // (3,64,64) = [k][c][d]
            const float* __restrict__ cb,  // (64,)
            float* __restrict__ out) {
    constexpr int TT  = 4;
    constexpr int STR = 68;  // padded channel stride (bank-conflict mitigation, float4-aligned)
    extern __shared__ float sm[];
    float* Wsm = sm;                    // 12288
    float* bsm = Wsm + 3 * 64 * 64;     // 64
    float* Lsm = bsm + 64;              // NPAD*NPAD
    float* Z   = Lsm + NPAD * NPAD;     // TT*NPAD*STR
    float* X1  = Z + TT * NPAD * STR;
    float* X2  = X1 + TT * NPAD * STR;

    const int tid = threadIdx.x;
    const int b   = blockIdx.y;
    const int t0  = blockIdx.x * TT;

    for (int i = tid; i < 3 * 64 * 64; i += 288) Wsm[i] = cw[i];
    if (tid < 64) bsm[tid] = cb[tid];
    for (int i = tid; i < NPAD * NPAD; i += 288) Lsm[i] = g_L[i];
    for (int i = tid; i < TT * NPAD * CH; i += 288) {
        int tt = i / (NPAD * CH);
        int r  = i % (NPAD * CH);
        int nn = r / CH, c = r % CH;
        int t = t0 + tt;
        float v = 0.f;
        if (t < T && nn < NNODE) v = zin[(((size_t)b * T + t) * NNODE + nn) * CH + c];
        Z[(tt * NPAD + nn) * STR + c] = v;
    }
    __syncthreads();

    const int tt = tid / 72;
    const int r  = tid % 72;
    const int n0 = (r / 8) * 4;
    const int q0 = (r % 8) * 8;

    // ---- prop1: X1 = L * Z
    {
        float acc[4][8];
#pragma unroll
        for (int a = 0; a < 4; a++)
#pragma unroll
            for (int j = 0; j < 8; j++) acc[a][j] = 0.f;
        for (int m = 0; m < NPAD; m++) {
            const float* zr = &Z[(tt * NPAD + m) * STR + q0];
            float4 za = *reinterpret_cast<const float4*>(zr);
            float4 zb = *reinterpret_cast<const float4*>(zr + 4);
#pragma unroll
            for (int a = 0; a < 4; a++) {
                float lv = Lsm[(n0 + a) * NPAD + m];
                fma8(acc[a], lv, za, zb);
            }
        }
#pragma unroll
        for (int a = 0; a < 4; a++) {
            float* xp = &X1[(tt * NPAD + n0 + a) * STR + q0];
            *reinterpret_cast<float4*>(xp)     = make_float4(acc[a][0], acc[a][1], acc[a][2], acc[a][3]);
            *reinterpret_cast<float4*>(xp + 4) = make_float4(acc[a][4], acc[a][5], acc[a][6], acc[a][7]);
        }
    }
    __syncthreads();

    // ---- prop2: X2 = 2*(L * X1) - Z
    {
        float acc[4][8];
#pragma unroll
        for (int a = 0; a < 4; a++)
#pragma unroll
            for (int j = 0; j < 8; j++) acc[a][j] = 0.f;
        for (int m = 0; m < NPAD; m++) {
            const float* xr = &X1[(tt * NPAD + m) * STR + q0];
            float4 xa = *reinterpret_cast<const float4*>(xr);
            float4 xb = *reinterpret_cast<const float4*>(xr + 4);
#pragma unroll
            for (int a = 0; a < 4; a++) {
                float lv = Lsm[(n0 + a) * NPAD + m];
                fma8(acc[a], lv, xa, xb);
            }
        }
#pragma unroll
        for (int a = 0; a < 4; a++) {
            int base = (tt * NPAD + n0 + a) * STR + q0;
            float4 z0 = *reinterpret_cast<const float4*>(&Z[base]);
            float4 z1 = *reinterpret_cast<const float4*>(&Z[base + 4]);
            *reinterpret_cast<float4*>(&X2[base]) =
                make_float4(2.f * acc[a][0] - z0.x, 2.f * acc[a][1] - z0.y,
                            2.f * acc[a][2] - z0.z, 2.f * acc[a][3] - z0.w);
            *reinterpret_cast<float4*>(&X2[base + 4]) =
                make_float4(2.f * acc[a][4] - z1.x, 2.f * acc[a][5] - z1.y,
                            2.f * acc[a][6] - z1.z, 2.f * acc[a][7] - z1.w);
        }
    }
    __syncthreads();

    // ---- GEMM: out = relu(Z*W0 + X1*W1 + X2*W2 + bias)
    {
        float acc[4][8];
#pragma unroll
        for (int a = 0; a < 4; a++)
#pragma unroll
            for (int j = 0; j < 8; j++) acc[a][j] = 0.f;
        for (int c = 0; c < 64; c++) {
            const float* w0p = &Wsm[(0 * 64 + c) * 64 + q0];
            const float* w1p = &Wsm[(1 * 64 + c) * 64 + q0];
            const float* w2p = &Wsm[(2 * 64 + c) * 64 + q0];
            float4 w0a = *reinterpret_cast<const float4*>(w0p);
            float4 w0b = *reinterpret_cast<const float4*>(w0p + 4);
            float4 w1a = *reinterpret_cast<const float4*>(w1p);
            float4 w1b = *reinterpret_cast<const float4*>(w1p + 4);
            float4 w2a = *reinterpret_cast<const float4*>(w2p);
            float4 w2b = *reinterpret_cast<const float4*>(w2p + 4);
#pragma unroll
            for (int a = 0; a < 4; a++) {
                int base = (tt * NPAD + n0 + a) * STR + c;
                float zv  = Z[base];
                float x1v = X1[base];
                float x2v = X2[base];
                fma8(acc[a], zv,  w0a, w0b);
                fma8(acc[a], x1v, w1a, w1b);
                fma8(acc[a], x2v, w2a, w2b);
            }
        }
        int t = t0 + tt;
        if (t < T) {
#pragma unroll
            for (int a = 0; a < 4; a++) {
                int n = n0 + a;
                if (n < NNODE) {
                    float* op = &out[(((size_t)b * T + t) * NNODE + n) * CH + q0];
                    float4 o0, o1;
                    o0.x = fmaxf(acc[a][0] + bsm[q0 + 0], 0.f);
                    o0.y = fmaxf(acc[a][1] + bsm[q0 + 1], 0.f);
                    o0.z = fmaxf(acc[a][2] + bsm[q0 + 2], 0.f);
                    o0.w = fmaxf(acc[a][3] + bsm[q0 + 3], 0.f);
                    o1.x = fmaxf(acc[a][4] + bsm[q0 + 4], 0.f);
                    o1.y = fmaxf(acc[a][5] + bsm[q0 + 5], 0.f);
                    o1.z = fmaxf(acc[a][6] + bsm[q0 + 6], 0.f);
                    o1.w = fmaxf(acc[a][7] + bsm[q0 + 7], 0.f);
                    *reinterpret_cast<float4*>(op)     = o0;
                    *reinterpret_cast<float4*>(op + 4) = o1;
                }
            }
        }
    }
}

// ---------------- BN per-node stats -> affine coefficients ----------------
__global__ void __launch_bounds__(256)
bnstats_kernel(const float* __restrict__ x, int T,
               const float* __restrict__ gamma, const float* __restrict__ beta,
               float* __restrict__ scl, float* __restrict__ shf) {
    const int n   = blockIdx.x;
    const int tid = threadIdx.x;
    const size_t total = (size_t)BATCH * T * CH;
    double s = 0.0, s2 = 0.0;
    for (size_t i = tid; i < total; i += 256) {
        size_t bt = i >> 6;
        int c = (int)(i & 63);
        float v = x[(bt * NNODE + n) * CH + c];
        s  += v;
        s2 += (double)v * v;
    }
    __shared__ double rs[256], rs2[256];
    rs[tid] = s; rs2[tid] = s2;
    __syncthreads();
    for (int st = 128; st > 0; st >>= 1) {
        if (tid < st) { rs[tid] += rs[tid + st]; rs2[tid] += rs2[tid + st]; }
        __syncthreads();
    }
    if (tid == 0) {
        double mean = rs[0] / (double)total;
        double var  = rs2[0] / (double)total - mean * mean;
        double inv  = 1.0 / sqrt(var + 1e-5);
        double sc   = (double)gamma[n] * inv;
        scl[n] = (float)sc;
        shf[n] = (float)((double)beta[n] - mean * sc);
    }
}

// ---------------- fused BN+relu+time-mean ----------------
__global__ void timemean_kernel(const float* __restrict__ x, int T,
                                const float* __restrict__ scl, const float* __restrict__ shf) {
    const int n = blockIdx.x, b = blockIdx.y, c = threadIdx.x;
    const float sc = scl[n], sh = shf[n];
    double s = 0.0;
    for (int t = 0; t < T; t++) {
        float v = x[(((size_t)b * T + t) * NNODE + n) * CH + c];
        v = fmaxf(fmaf(v, sc, sh), 0.f);
        s += (double)v;
    }
    g_M[(b * NNODE + n) * CH + c] = (float)(s / (double)T);
}

// ---------------- classifier: fc1 + relu + fc2 (fused per batch row) ----------------
__global__ void __launch_bounds__(256)
fc_kernel(const float* __restrict__ w1, const float* __restrict__ b1,
          const float* __restrict__ w2, const float* __restrict__ b2,
          float* __restrict__ out) {
    __shared__ float ms[NNODE * CH];  // 2112
    __shared__ float h1[256];
    const int b = blockIdx.x, tid = threadIdx.x;
    for (int i = tid; i < NNODE * CH; i += 256) ms[i] = g_M[b * NNODE * CH + i];
    __syncthreads();
    double acc = (double)b1[tid];
    for (int i = 0; i < NNODE * CH; i++) acc += (double)ms[i] * (double)w1[i * 256 + tid];
    h1[tid] = fmaxf((float)acc, 0.f);
    __syncthreads();
    if (tid < 10) {
        double a2 = (double)b2[tid];
        for (int i = 0; i < 256; i++) a2 += (double)h1[i] * (double)w2[i * 10 + tid];
        out[b * 10 + tid] = (float)a2;
    }
}

// ---------------- launch ----------------
extern "C" void kernel_launch(void* const* d_in, const int* in_sizes, int n_in,
                              void* d_out, int out_size) {
    const float* x        = (const float*)d_in[0];
    const int*   ei       = (const int*)d_in[1];
    const float* s1_tc1_w = (const float*)d_in[2];
    const float* s1_tc1_b = (const float*)d_in[3];
    const float* s1_cheb_w= (const float*)d_in[4];
    const float* s1_cheb_b= (const float*)d_in[5];
    const float* s1_tc2_w = (const float*)d_in[6];
    const float* s1_tc2_b = (const float*)d_in[7];
    const float* s1_bn_g  = (const float*)d_in[8];
    const float* s1_bn_b  = (const float*)d_in[9];
    const float* s2_tc1_w = (const float*)d_in[10];
    const float* s2_tc1_b = (const float*)d_in[11];
    const float* s2_cheb_w= (const float*)d_in[12];
    const float* s2_cheb_b= (const float*)d_in[13];
    const float* s2_tc2_w = (const float*)d_in[14];
    const float* s2_tc2_b = (const float*)d_in[15];
    const float* s2_bn_g  = (const float*)d_in[16];
    const float* s2_bn_b  = (const float*)d_in[17];
    const float* fc1_w    = (const float*)d_in[18];
    const float* fc1_b    = (const float*)d_in[19];
    const float* fc2_w    = (const float*)d_in[20];
    const float* fc2_b    = (const float*)d_in[21];

    float *bufA, *bufB, *w1a, *w1b, *w2a, *w2b, *scl1, *shf1, *scl2, *shf2;
    cudaGetSymbolAddress((void**)&bufA, g_bufA);
    cudaGetSymbolAddress((void**)&bufB, g_bufB);
    cudaGetSymbolAddress((void**)&w1a, g_w1a);
    cudaGetSymbolAddress((void**)&w1b, g_w1b);
    cudaGetSymbolAddress((void**)&w2a, g_w2a);
    cudaGetSymbolAddress((void**)&w2b, g_w2b);
    cudaGetSymbolAddress((void**)&scl1, g_scl1);
    cudaGetSymbolAddress((void**)&shf1, g_shf1);
    cudaGetSymbolAddress((void**)&scl2, g_scl2);
    cudaGetSymbolAddress((void**)&shf2, g_shf2);

    const size_t sm3  = (size_t)(3 * 3 * 3 * 64 + 66 * 3) * sizeof(float);
    const size_t sm64 = (size_t)(3 * 64 * 3 * 64 + 66 * 64) * sizeof(float);
    const size_t smC  = (size_t)(3 * 64 * 64 + 64 + NPAD * NPAD + 3 * 4 * NPAD * 68) * sizeof(float);

    cudaFuncSetAttribute(tconv_kernel<64>, cudaFuncAttributeMaxDynamicSharedMemorySize, (int)sm64);
    cudaFuncSetAttribute(cheb_kernel,      cudaFuncAttributeMaxDynamicSharedMemorySize, (int)smC);

    const int ne = in_sizes[1] / 2;  // 64 edges

    setup_L_kernel<<<1, 1>>>(ei, ne);
    reorder_w_kernel<<<(3 * 3 * 3 * 64 + 255) / 256, 256>>>(s1_tc1_w, w1a, 3);
    reorder_w_kernel<<<(3 * 64 * 3 * 64 + 255) / 256, 256>>>(s1_tc2_w, w1b, 64);
    reorder_w_kernel<<<(3 * 64 * 3 * 64 + 255) / 256, 256>>>(s2_tc1_w, w2a, 64);
    reorder_w_kernel<<<(3 * 64 * 3 * 64 + 255) / 256, 256>>>(s2_tc2_w, w2b, 64);

    dim3 tblk(64, 8);

    // ---- STConv 1 ----
    tconv_kernel<3><<<dim3(8, NNODE, BATCH), tblk, sm3>>>(x, 512, w1a, s1_tc1_b,
                                                          nullptr, nullptr, 0, bufA);           // -> T=510
    cheb_kernel<<<dim3((510 + 3) / 4, BATCH), 288, smC>>>(bufA, 510, s1_cheb_w, s1_cheb_b, bufB);
    tconv_kernel<64><<<dim3(8, NNODE, BATCH), tblk, sm64>>>(bufB, 510, w1b, s1_tc2_b,
                                                            nullptr, nullptr, 0, bufA);         // -> T=508
    bnstats_kernel<<<NNODE, 256>>>(bufA, 508, s1_bn_g, s1_bn_b, scl1, shf1);

    // ---- STConv 2 (BN1+relu fused into input load) ----
    tconv_kernel<64><<<dim3(8, NNODE, BATCH), tblk, sm64>>>(bufA, 508, w2a, s2_tc1_b,
                                                            scl1, shf1, 1, bufB);               // -> T=506
    cheb_kernel<<<dim3((506 + 3) / 4, BATCH), 288, smC>>>(bufB, 506, s2_cheb_w, s2_cheb_b, bufA);
    tconv_kernel<64><<<dim3(8, NNODE, BATCH), tblk, sm64>>>(bufA, 506, w2b, s2_tc2_b,
                                                            nullptr, nullptr, 0, bufB);         // -> T=504
    bnstats_kernel<<<NNODE, 256>>>(bufB, 504, s2_bn_g, s2_bn_b, scl2, shf2);

    // ---- head: BN2+relu+time-mean, then FCs ----
    timemean_kernel<<<dim3(NNODE, BATCH), 64>>>(bufB, 504, scl2, shf2);
    fc_kernel<<<BATCH, 256>>>(fc1_w, fc1_b, fc2_w, fc2_b, (float*)d_out);
}

// round 2
// speedup vs baseline: 1.4037x; 1.4037x over previous
#include <cuda_runtime.h>
#include <math.h>

#define BATCH 32
#define NNODE 33
#define NPAD  36
#define CH    64

typedef unsigned long long u64;

// ---------------- f32x2 helpers (sm_103a packed fp32 pipe) ----------------
__device__ __forceinline__ u64 pk2(float lo, float hi) {
    u64 r;
    asm("mov.b64 %0, {%1, %2};" : "=l"(r) : "r"(__float_as_uint(lo)), "r"(__float_as_uint(hi)));
    return r;
}
__device__ __forceinline__ u64 dup2(float v) { return pk2(v, v); }
__device__ __forceinline__ void unpk2(u64 v, float& lo, float& hi) {
    unsigned a, b;
    asm("mov.b64 {%0, %1}, %2;" : "=r"(a), "=r"(b) : "l"(v));
    lo = __uint_as_float(a);
    hi = __uint_as_float(b);
}
__device__ __forceinline__ void fma2(u64& d, u64 a, u64 b) {
    asm("fma.rn.f32x2 %0, %1, %2, %0;" : "+l"(d) : "l"(a), "l"(b));
}

// ---------------- device scratch ----------------
__device__ float g_bufA[(size_t)BATCH * 510 * NNODE * CH];
__device__ float g_bufB[(size_t)BATCH * 510 * NNODE * CH];
__device__ float g_L[NPAD * NPAD];
__device__ float g_w1a[3 * 3 * 3 * 64];
__device__ float g_w1b[3 * 64 * 3 * 64];
__device__ float g_w2a[3 * 64 * 3 * 64];
__device__ float g_w2b[3 * 64 * 3 * 64];
__device__ float g_scl1[NNODE], g_shf1[NNODE];
__device__ float g_scl2[NNODE], g_shf2[NNODE];
__device__ double g_sum1[NNODE], g_sqs1[NNODE];
__device__ double g_sum2[NNODE], g_sqs2[NNODE];
__device__ float g_M[BATCH * NNODE * CH];

// ---------------- setup ----------------
__global__ void zero_acc_kernel() {
    int i = threadIdx.x;
    if (i < NNODE) { g_sum1[i] = 0.0; g_sqs1[i] = 0.0; g_sum2[i] = 0.0; g_sqs2[i] = 0.0; }
}

__global__ void setup_L_kernel(const int* __restrict__ ei, int ne) {
    double deg[NNODE];
    for (int i = 0; i < NNODE; i++) deg[i] = 0.0;
    for (int e = 0; e < ne; e++) deg[ei[e]] += 1.0;
    double dinv[NNODE];
    for (int i = 0; i < NNODE; i++) dinv[i] = (deg[i] > 0.0) ? (1.0 / sqrt(deg[i])) : 0.0;
    for (int i = 0; i < NPAD * NPAD; i++) g_L[i] = 0.0f;
    for (int e = 0; e < ne; e++) {
        int s = ei[e];
        int t = ei[ne + e];
        g_L[t * NPAD + s] += (float)(-dinv[s] * dinv[t]);
    }
}

// (3, O=64, Ci, 1, 3) -> [g][ci][k][o]
__global__ void reorder_w_kernel(const float* __restrict__ win, float* __restrict__ wout, int CI) {
    int i = blockIdx.x * blockDim.x + threadIdx.x;
    int n = 3 * CI * 3 * 64;
    if (i >= n) return;
    int o  = i & 63;
    int k  = (i >> 6) % 3;
    int ci = (i / 192) % CI;
    int g  = i / (192 * CI);
    wout[i] = win[((g * 64 + o) * CI + ci) * 3 + k];
}

// ---------------- gated temporal conv, f32x2-packed over time pairs ----------------
template <int CI>
__global__ void __launch_bounds__(512)
tconv_kernel(const float* __restrict__ xin, int Tin,
             const float* __restrict__ wre,   // [3][CI][3][64]
             const float* __restrict__ bias,  // [3][64]
             const float* __restrict__ scl, const float* __restrict__ shf, int mode,
             float* __restrict__ out,
             double* __restrict__ bnsum, double* __restrict__ bnsqs) {
    constexpr int CT = 128;
    constexpr int TO = 16;
    constexpr int ST = CT + 4;   // 132: even & mult-of-4 (LDS.64 alignment for even pairs)
    constexpr int HP = TO / 2;   // 8 accumulator pairs per gate

    extern __shared__ float sm[];
    float* ws = sm;                      // 3*CI*3*64
    float* xs = sm + 3 * CI * 3 * 64;    // [ci][ST] transposed

    const int tid  = threadIdx.y * 64 + threadIdx.x;
    const int Tout = Tin - 2;
    const int t0   = blockIdx.x * CT;
    const int n    = blockIdx.y;
    const int b    = blockIdx.z;

    for (int i = tid; i < 3 * CI * 3 * 64; i += 512) ws[i] = wre[i];

    float sc = 1.f, sh = 0.f;
    if (mode) { sc = scl[n]; sh = shf[n]; }
    for (int i = tid; i < (CT + 2) * CI; i += 512) {
        int tt = i / CI, ci = i % CI;
        int t = t0 + tt;
        float v = 0.f;
        if (t < Tin) v = xin[(((size_t)b * Tin + t) * NNODE + n) * CI + ci];
        if (mode) v = fmaxf(fmaf(v, sc, sh), 0.f);
        xs[ci * ST + tt] = v;
    }
    __syncthreads();

    const int o  = threadIdx.x;
    const int tb = threadIdx.y * TO;

    u64 accP[3][HP];
#pragma unroll
    for (int g = 0; g < 3; g++)
#pragma unroll
        for (int p = 0; p < HP; p++) accP[g][p] = 0ull;

#pragma unroll 2
    for (int ci = 0; ci < CI; ci++) {
        const float* xp = &xs[ci * ST + tb];
        u64 ep[HP + 1];      // even pairs: (xv[2p], xv[2p+1]), aligned LDS.64
#pragma unroll
        for (int p = 0; p <= HP; p++) ep[p] = *reinterpret_cast<const u64*>(xp + 2 * p);
        float xl[HP + 1], xh[HP + 1];
#pragma unroll
        for (int p = 0; p <= HP; p++) unpk2(ep[p], xl[p], xh[p]);
        u64 op[HP];          // odd pairs: (xv[2p+1], xv[2p+2])
#pragma unroll
        for (int p = 0; p < HP; p++) op[p] = pk2(xh[p], xl[p + 1]);

#pragma unroll
        for (int g = 0; g < 3; g++) {
#pragma unroll
            for (int k = 0; k < 3; k++) {
                u64 wd = dup2(ws[((g * CI + ci) * 3 + k) * 64 + o]);
                const u64* xq = (k == 0) ? ep : (k == 1) ? op : (ep + 1);
#pragma unroll
                for (int p = 0; p < HP; p++) fma2(accP[g][p], xq[p], wd);
            }
        }
    }

    const float bP = bias[o], bQ = bias[64 + o], bR = bias[128 + o];
    float s1 = 0.f, s2 = 0.f;
#pragma unroll
    for (int p = 0; p < HP; p++) {
        float P0, P1, Q0, Q1, R0, R1;
        unpk2(accP[0][p], P0, P1);
        unpk2(accP[1][p], Q0, Q1);
        unpk2(accP[2][p], R0, R1);
#pragma unroll
        for (int half = 0; half < 2; half++) {
            int t = t0 + tb + 2 * p + half;
            if (t < Tout) {
                float P = (half ? P1 : P0) + bP;
                float Q = (half ? Q1 : Q0) + bQ;
                float R = (half ? R1 : R0) + bR;
                float sg = 1.f / (1.f + __expf(-Q));
                float h = fmaxf(fmaf(P, sg, R), 0.f);
                out[(((size_t)b * Tout + t) * NNODE + n) * CH + o] = h;
                s1 += h;
                s2 += h * h;
            }
        }
    }

    if (bnsum != nullptr) {
#pragma unroll
        for (int off = 16; off > 0; off >>= 1) {
            s1 += __shfl_xor_sync(0xffffffffu, s1, off);
            s2 += __shfl_xor_sync(0xffffffffu, s2, off);
        }
        __shared__ double wsm1[16], wsm2[16];
        int wid = tid >> 5, lane = tid & 31;
        if (lane == 0) { wsm1[wid] = (double)s1; wsm2[wid] = (double)s2; }
        __syncthreads();
        if (tid == 0) {
            double a = 0.0, c = 0.0;
#pragma unroll
            for (int i = 0; i < 16; i++) { a += wsm1[i]; c += wsm2[i]; }
            atomicAdd(&bnsum[n], a);
            atomicAdd(&bnsqs[n], c);
        }
    }
}

// ---------------- BN finalize: stats -> affine ----------------
__global__ void finalize_bn_kernel(const double* __restrict__ sum, const double* __restrict__ sqs,
                                   const float* __restrict__ gamma, const float* __restrict__ beta,
                                   double cnt, float* __restrict__ scl, float* __restrict__ shf) {
    int nn = threadIdx.x;
    if (nn < NNODE) {
        double m = sum[nn] / cnt;
        double v = sqs[nn] / cnt - m * m;
        double inv = 1.0 / sqrt(v + 1e-5);
        double sc = (double)gamma[nn] * inv;
        scl[nn] = (float)sc;
        shf[nn] = (float)((double)beta[nn] - m * sc);
    }
}

// ---------------- ChebConv K=3 + relu, f32x2-packed ----------------
__global__ void __launch_bounds__(288)
cheb_kernel(const float* __restrict__ zin, int T,
            const float* __restrict__ cw, const float* __restrict__ cb,
            float* __restrict__ out) {
    constexpr int TT  = 4;
    constexpr int STR = 68;
    extern __shared__ float sm[];
    float* Wsm = sm;                    // 12288
    float* bsm = Wsm + 3 * 64 * 64;     // 64
    float* Lsm = bsm + 64;              // 1296
    float* Z   = Lsm + NPAD * NPAD;     // TT*NPAD*STR each
    float* X1  = Z + TT * NPAD * STR;
    float* X2  = X1 + TT * NPAD * STR;

    const int tid = threadIdx.x;
    const int b   = blockIdx.y;
    const int t0  = blockIdx.x * TT;

    for (int i = tid; i < 3 * 64 * 64; i += 288) Wsm[i] = cw[i];
    if (tid < 64) bsm[tid] = cb[tid];
    for (int i = tid; i < NPAD * NPAD; i += 288) Lsm[i] = g_L[i];
    for (int i = tid; i < TT * NPAD * CH; i += 288) {
        int tt = i / (NPAD * CH);
        int r  = i % (NPAD * CH);
        int nn = r / CH, c = r % CH;
        int t = t0 + tt;
        float v = 0.f;
        if (t < T && nn < NNODE) v = zin[(((size_t)b * T + t) * NNODE + nn) * CH + c];
        Z[(tt * NPAD + nn) * STR + c] = v;
    }
    __syncthreads();

    const int tt = tid / 72;
    const int r  = tid % 72;
    const int n0 = (r / 8) * 4;
    const int q0 = (r % 8) * 8;

    // ---- prop1: X1 = L * Z
    {
        u64 acc[4][4];
#pragma unroll
        for (int a = 0; a < 4; a++)
#pragma unroll
            for (int p = 0; p < 4; p++) acc[a][p] = 0ull;
#pragma unroll 2
        for (int m = 0; m < NPAD; m++) {
            const u64* zr = reinterpret_cast<const u64*>(&Z[(tt * NPAD + m) * STR + q0]);
            u64 z0 = zr[0], z1 = zr[1], z2 = zr[2], z3 = zr[3];
#pragma unroll
            for (int a = 0; a < 4; a++) {
                u64 ld = dup2(Lsm[(n0 + a) * NPAD + m]);
                fma2(acc[a][0], z0, ld);
                fma2(acc[a][1], z1, ld);
                fma2(acc[a][2], z2, ld);
                fma2(acc[a][3], z3, ld);
            }
        }
#pragma unroll
        for (int a = 0; a < 4; a++) {
            u64* xp = reinterpret_cast<u64*>(&X1[(tt * NPAD + n0 + a) * STR + q0]);
#pragma unroll
            for (int p = 0; p < 4; p++) xp[p] = acc[a][p];
        }
    }
    __syncthreads();

    // ---- prop2: X2 = 2*(L * X1) - Z
    {
        u64 acc[4][4];
#pragma unroll
        for (int a = 0; a < 4; a++)
#pragma unroll
            for (int p = 0; p < 4; p++) acc[a][p] = 0ull;
#pragma unroll 2
        for (int m = 0; m < NPAD; m++) {
            const u64* xr = reinterpret_cast<const u64*>(&X1[(tt * NPAD + m) * STR + q0]);
            u64 x0 = xr[0], x1 = xr[1], x2 = xr[2], x3 = xr[3];
#pragma unroll
            for (int a = 0; a < 4; a++) {
                u64 ld = dup2(Lsm[(n0 + a) * NPAD + m]);
                fma2(acc[a][0], x0, ld);
                fma2(acc[a][1], x1, ld);
                fma2(acc[a][2], x2, ld);
                fma2(acc[a][3], x3, ld);
            }
        }
#pragma unroll
        for (int a = 0; a < 4; a++) {
            int base = (tt * NPAD + n0 + a) * STR + q0;
#pragma unroll
            for (int p = 0; p < 4; p++) {
                float alo, ahi;
                unpk2(acc[a][p], alo, ahi);
                X2[base + 2 * p]     = 2.f * alo - Z[base + 2 * p];
                X2[base + 2 * p + 1] = 2.f * ahi - Z[base + 2 * p + 1];
            }
        }
    }
    __syncthreads();

    // ---- GEMM: out = relu(Z*W0 + X1*W1 + X2*W2 + b)
    {
        u64 acc[4][4];
#pragma unroll
        for (int a = 0; a < 4; a++)
#pragma unroll
            for (int p = 0; p < 4; p++) acc[a][p] = 0ull;
#pragma unroll 2
        for (int c = 0; c < 64; c++) {
            const u64* w0 = reinterpret_cast<const u64*>(&Wsm[(0 * 64 + c) * 64 + q0]);
            const u64* w1 = reinterpret_cast<const u64*>(&Wsm[(1 * 64 + c) * 64 + q0]);
            const u64* w2 = reinterpret_cast<const u64*>(&Wsm[(2 * 64 + c) * 64 + q0]);
            u64 w00 = w0[0], w01 = w0[1], w02 = w0[2], w03 = w0[3];
            u64 w10 = w1[0], w11 = w1[1], w12 = w1[2], w13 = w1[3];
            u64 w20 = w2[0], w21 = w2[1], w22 = w2[2], w23 = w2[3];
#pragma unroll
            for (int a = 0; a < 4; a++) {
                int base = (tt * NPAD + n0 + a) * STR + c;
                u64 zd  = dup2(Z[base]);
                u64 x1d = dup2(X1[base]);
                u64 x2d = dup2(X2[base]);
                fma2(acc[a][0], w00, zd);  fma2(acc[a][1], w01, zd);
                fma2(acc[a][2], w02, zd);  fma2(acc[a][3], w03, zd);
                fma2(acc[a][0], w10, x1d); fma2(acc[a][1], w11, x1d);
                fma2(acc[a][2], w12, x1d); fma2(acc[a][3], w13, x1d);
                fma2(acc[a][0], w20, x2d); fma2(acc[a][1], w21, x2d);
                fma2(acc[a][2], w22, x2d); fma2(acc[a][3], w23, x2d);
            }
        }
        int t = t0 + tt;
        if (t < T) {
#pragma unroll
            for (int a = 0; a < 4; a++) {
                int nn = n0 + a;
                if (nn < NNODE) {
                    float* op = &out[(((size_t)b * T + t) * NNODE + nn) * CH + q0];
#pragma unroll
                    for (int p = 0; p < 4; p++) {
                        float alo, ahi;
                        unpk2(acc[a][p], alo, ahi);
                        op[2 * p]     = fmaxf(alo + bsm[q0 + 2 * p], 0.f);
                        op[2 * p + 1] = fmaxf(ahi + bsm[q0 + 2 * p + 1], 0.f);
                    }
                }
            }
        }
    }
}

// ---------------- fused BN+relu+time-mean ----------------
__global__ void timemean_kernel(const float* __restrict__ x, int T,
                                const float* __restrict__ scl, const float* __restrict__ shf) {
    const int n = blockIdx.x, b = blockIdx.y, c = threadIdx.x;
    const float sc = scl[n], sh = shf[n];
    double s = 0.0;
    for (int t = 0; t < T; t++) {
        float v = x[(((size_t)b * T + t) * NNODE + n) * CH + c];
        v = fmaxf(fmaf(v, sc, sh), 0.f);
        s += (double)v;
    }
    g_M[(b * NNODE + n) * CH + c] = (float)(s / (double)T);
}

// ---------------- classifier ----------------
__global__ void __launch_bounds__(256)
fc_kernel(const float* __restrict__ w1, const float* __restrict__ b1,
          const float* __restrict__ w2, const float* __restrict__ b2,
          float* __restrict__ out) {
    __shared__ float ms[NNODE * CH];
    __shared__ float h1[256];
    const int b = blockIdx.x, tid = threadIdx.x;
    for (int i = tid; i < NNODE * CH; i += 256) ms[i] = g_M[b * NNODE * CH + i];
    __syncthreads();
    double acc = (double)b1[tid];
    for (int i = 0; i < NNODE * CH; i++) acc += (double)ms[i] * (double)w1[i * 256 + tid];
    h1[tid] = fmaxf((float)acc, 0.f);
    __syncthreads();
    if (tid < 10) {
        double a2 = (double)b2[tid];
        for (int i = 0; i < 256; i++) a2 += (double)h1[i] * (double)w2[i * 10 + tid];
        out[b * 10 + tid] = (float)a2;
    }
}

// ---------------- launch ----------------
extern "C" void kernel_launch(void* const* d_in, const int* in_sizes, int n_in,
                              void* d_out, int out_size) {
    const float* x        = (const float*)d_in[0];
    const int*   ei       = (const int*)d_in[1];
    const float* s1_tc1_w = (const float*)d_in[2];
    const float* s1_tc1_b = (const float*)d_in[3];
    const float* s1_cheb_w= (const float*)d_in[4];
    const float* s1_cheb_b= (const float*)d_in[5];
    const float* s1_tc2_w = (const float*)d_in[6];
    const float* s1_tc2_b = (const float*)d_in[7];
    const float* s1_bn_g  = (const float*)d_in[8];
    const float* s1_bn_b  = (const float*)d_in[9];
    const float* s2_tc1_w = (const float*)d_in[10];
    const float* s2_tc1_b = (const float*)d_in[11];
    const float* s2_cheb_w= (const float*)d_in[12];
    const float* s2_cheb_b= (const float*)d_in[13];
    const float* s2_tc2_w = (const float*)d_in[14];
    const float* s2_tc2_b = (const float*)d_in[15];
    const float* s2_bn_g  = (const float*)d_in[16];
    const float* s2_bn_b  = (const float*)d_in[17];
    const float* fc1_w    = (const float*)d_in[18];
    const float* fc1_b    = (const float*)d_in[19];
    const float* fc2_w    = (const float*)d_in[20];
    const float* fc2_b    = (const float*)d_in[21];

    float *bufA, *bufB, *w1a, *w1b, *w2a, *w2b, *scl1, *shf1, *scl2, *shf2;
    double *sum1, *sqs1, *sum2, *sqs2;
    cudaGetSymbolAddress((void**)&bufA, g_bufA);
    cudaGetSymbolAddress((void**)&bufB, g_bufB);
    cudaGetSymbolAddress((void**)&w1a, g_w1a);
    cudaGetSymbolAddress((void**)&w1b, g_w1b);
    cudaGetSymbolAddress((void**)&w2a, g_w2a);
    cudaGetSymbolAddress((void**)&w2b, g_w2b);
    cudaGetSymbolAddress((void**)&scl1, g_scl1);
    cudaGetSymbolAddress((void**)&shf1, g_shf1);
    cudaGetSymbolAddress((void**)&scl2, g_scl2);
    cudaGetSymbolAddress((void**)&shf2, g_shf2);
    cudaGetSymbolAddress((void**)&sum1, g_sum1);
    cudaGetSymbolAddress((void**)&sqs1, g_sqs1);
    cudaGetSymbolAddress((void**)&sum2, g_sum2);
    cudaGetSymbolAddress((void**)&sqs2, g_sqs2);

    const size_t sm3  = (size_t)(3 * 3 * 3 * 64 + 3 * 132) * sizeof(float);
    const size_t sm64 = (size_t)(3 * 64 * 3 * 64 + 64 * 132) * sizeof(float);
    const size_t smC  = (size_t)(3 * 64 * 64 + 64 + NPAD * NPAD + 3 * 4 * NPAD * 68) * sizeof(float);

    cudaFuncSetAttribute(tconv_kernel<3>,  cudaFuncAttributeMaxDynamicSharedMemorySize, (int)sm3);
    cudaFuncSetAttribute(tconv_kernel<64>, cudaFuncAttributeMaxDynamicSharedMemorySize, (int)sm64);
    cudaFuncSetAttribute(cheb_kernel,      cudaFuncAttributeMaxDynamicSharedMemorySize, (int)smC);

    const int ne = in_sizes[1] / 2;

    zero_acc_kernel<<<1, 64>>>();
    setup_L_kernel<<<1, 1>>>(ei, ne);
    reorder_w_kernel<<<(3 * 3 * 3 * 64 + 255) / 256, 256>>>(s1_tc1_w, w1a, 3);
    reorder_w_kernel<<<(3 * 64 * 3 * 64 + 255) / 256, 256>>>(s1_tc2_w, w1b, 64);
    reorder_w_kernel<<<(3 * 64 * 3 * 64 + 255) / 256, 256>>>(s2_tc1_w, w2a, 64);
    reorder_w_kernel<<<(3 * 64 * 3 * 64 + 255) / 256, 256>>>(s2_tc2_w, w2b, 64);

    dim3 tblk(64, 8);  // 512 threads, CT=128, TO=16

    // ---- STConv 1 ----
    tconv_kernel<3><<<dim3(4, NNODE, BATCH), tblk, sm3>>>(x, 512, w1a, s1_tc1_b,
                                                          nullptr, nullptr, 0, bufA,
                                                          nullptr, nullptr);                 // T=510
    cheb_kernel<<<dim3((510 + 3) / 4, BATCH), 288, smC>>>(bufA, 510, s1_cheb_w, s1_cheb_b, bufB);
    tconv_kernel<64><<<dim3(4, NNODE, BATCH), tblk, sm64>>>(bufB, 510, w1b, s1_tc2_b,
                                                            nullptr, nullptr, 0, bufA,
                                                            sum1, sqs1);                     // T=508 + stats
    finalize_bn_kernel<<<1, 64>>>(sum1, sqs1, s1_bn_g, s1_bn_b,
                                  (double)BATCH * 508.0 * 64.0, scl1, shf1);

    // ---- STConv 2 (BN1+relu fused into input load) ----
    tconv_kernel<64><<<dim3(4, NNODE, BATCH), tblk, sm64>>>(bufA, 508, w2a, s2_tc1_b,
                                                            scl1, shf1, 1, bufB,
                                                            nullptr, nullptr);               // T=506
    cheb_kernel<<<dim3((506 + 3) / 4, BATCH), 288, smC>>>(bufB, 506, s2_cheb_w, s2_cheb_b, bufA);
    tconv_kernel<64><<<dim3(4, NNODE, BATCH), tblk, sm64>>>(bufA, 506, w2b, s2_tc2_b,
                                                            nullptr, nullptr, 0, bufB,
                                                            sum2, sqs2);                     // T=504 + stats
    finalize_bn_kernel<<<1, 64>>>(sum2, sqs2, s2_bn_g, s2_bn_b,
                                  (double)BATCH * 504.0 * 64.0, scl2, shf2);

    // ---- head ----
    timemean_kernel<<<dim3(NNODE, BATCH), 64>>>(bufB, 504, scl2, shf2);
    fc_kernel<<<BATCH, 256>>>(fc1_w, fc1_b, fc2_w, fc2_b, (float*)d_out);
}

// round 3
// speedup vs baseline: 1.6629x; 1.1846x over previous
#include <cuda_runtime.h>
#include <math.h>

#define BATCH 32
#define NNODE 33
#define NPAD  36
#define CH    64

typedef unsigned long long u64;

// ---------------- f32x2 helpers ----------------
__device__ __forceinline__ u64 pk2(float lo, float hi) {
    u64 r;
    asm("mov.b64 %0, {%1, %2};" : "=l"(r) : "r"(__float_as_uint(lo)), "r"(__float_as_uint(hi)));
    return r;
}
__device__ __forceinline__ u64 dup2(float v) { return pk2(v, v); }
__device__ __forceinline__ void unpk2(u64 v, float& lo, float& hi) {
    unsigned a, b;
    asm("mov.b64 {%0, %1}, %2;" : "=r"(a), "=r"(b) : "l"(v));
    lo = __uint_as_float(a);
    hi = __uint_as_float(b);
}
__device__ __forceinline__ void fma2(u64& d, u64 a, u64 b) {
    asm("fma.rn.f32x2 %0, %1, %2, %0;" : "+l"(d) : "l"(a), "l"(b));
}

// ---------------- device scratch ----------------
__device__ float g_bufA[(size_t)BATCH * 510 * NNODE * CH];
__device__ float g_bufB[(size_t)BATCH * 510 * NNODE * CH];
__device__ float g_L[NPAD * NPAD];
__device__ float g_w1a[3 * 3 * 3 * 64];
__device__ float g_w1b[3 * 64 * 3 * 64];
__device__ float g_w2a[3 * 64 * 3 * 64];
__device__ float g_w2b[3 * 64 * 3 * 64];
__device__ float g_scl1[NNODE], g_shf1[NNODE];
__device__ float g_scl2[NNODE], g_shf2[NNODE];
__device__ double g_sum1[NNODE], g_sqs1[NNODE];
__device__ double g_sum2[NNODE], g_sqs2[NNODE];
__device__ float g_M[BATCH * NNODE * CH];

// ---------------- setup: zero BN accumulators + build dense L ----------------
__global__ void setup_kernel(const int* __restrict__ ei, int ne) {
    int i = threadIdx.x;
    if (i < NNODE) { g_sum1[i] = 0.0; g_sqs1[i] = 0.0; g_sum2[i] = 0.0; g_sqs2[i] = 0.0; }
    if (i == 0) {
        double deg[NNODE];
        for (int k = 0; k < NNODE; k++) deg[k] = 0.0;
        for (int e = 0; e < ne; e++) deg[ei[e]] += 1.0;
        double dinv[NNODE];
        for (int k = 0; k < NNODE; k++) dinv[k] = (deg[k] > 0.0) ? (1.0 / sqrt(deg[k])) : 0.0;
        for (int k = 0; k < NPAD * NPAD; k++) g_L[k] = 0.0f;
        for (int e = 0; e < ne; e++) {
            int s = ei[e];
            int t = ei[ne + e];
            g_L[t * NPAD + s] += (float)(-dinv[s] * dinv[t]);
        }
    }
}

// (3, O=64, CI, 1, 3) -> [g][ci][k][o], two tensors per launch
__device__ __forceinline__ void reorder_one(const float* __restrict__ in,
                                            float* __restrict__ outp, int CI, int i) {
    int o  = i & 63;
    int k  = (i >> 6) % 3;
    int ci = (i / 192) % CI;
    int g  = i / (192 * CI);
    outp[i] = in[((g * 64 + o) * CI + ci) * 3 + k];
}
__global__ void reorder2_kernel(const float* __restrict__ inA, float* __restrict__ outA, int CIA,
                                const float* __restrict__ inB, float* __restrict__ outB, int CIB) {
    int i  = blockIdx.x * blockDim.x + threadIdx.x;
    int nA = CIA * 576;
    int nB = CIB * 576;
    if (i < nA) reorder_one(inA, outA, CIA, i);
    else if (i < nA + nB) reorder_one(inB, outB, CIB, i - nA);
}

// ---------------- persistent gated temporal conv ----------------
template <int CI>
__global__ void __launch_bounds__(512)
tconv_kernel(const float* __restrict__ xin, int Tin,
             const float* __restrict__ wre,   // [3][CI][3][64]
             const float* __restrict__ bias,  // [3][64]
             const float* __restrict__ scl, const float* __restrict__ shf, int mode,
             float* __restrict__ out,
             double* __restrict__ bnsum, double* __restrict__ bnsqs) {
    constexpr int CT = 128;
    constexpr int TO = 16;
    constexpr int ST = CT + 4;
    constexpr int HP = TO / 2;

    extern __shared__ float sm[];
    float* ws = sm;                      // 3*CI*3*64
    float* xs = sm + 3 * CI * 3 * 64;    // [ci][ST]

    const int tid    = threadIdx.y * 64 + threadIdx.x;
    const int Tout   = Tin - 2;
    const int ntch   = (Tout + CT - 1) / CT;
    const int ntiles = ntch * NNODE * BATCH;

    // ---- weights: load ONCE per CTA (float4) ----
    {
        const float4* w4 = reinterpret_cast<const float4*>(wre);
        float4* s4 = reinterpret_cast<float4*>(ws);
        for (int i = tid; i < 3 * CI * 3 * 16; i += 512) s4[i] = w4[i];
    }

    const int o  = threadIdx.x;
    const int tb = threadIdx.y * TO;
    const float bP = bias[o], bQ = bias[64 + o], bR = bias[128 + o];

    __shared__ double wsm1[16], wsm2[16];

    for (int tile = blockIdx.x; tile < ntiles; tile += gridDim.x) {
        const int tch = tile % ntch;
        const int rem = tile / ntch;
        const int n   = rem % NNODE;
        const int b   = rem / NNODE;
        const int t0  = tch * CT;

        float sc = 1.f, sh = 0.f;
        if (mode) { sc = scl[n]; sh = shf[n]; }

        __syncthreads();   // protect xs (and first-iter weight load) vs prior reads

        if (CI == 64) {
            for (int i4 = tid; i4 < (CT + 2) * 16; i4 += 512) {
                int tt = i4 >> 4;
                int c4 = (i4 & 15) << 2;
                int t = t0 + tt;
                float4 v = make_float4(0.f, 0.f, 0.f, 0.f);
                if (t < Tin)
                    v = *reinterpret_cast<const float4*>(
                        &xin[(((size_t)b * Tin + t) * NNODE + n) * 64 + c4]);
                if (mode) {
                    v.x = fmaxf(fmaf(v.x, sc, sh), 0.f);
                    v.y = fmaxf(fmaf(v.y, sc, sh), 0.f);
                    v.z = fmaxf(fmaf(v.z, sc, sh), 0.f);
                    v.w = fmaxf(fmaf(v.w, sc, sh), 0.f);
                }
                xs[(c4 + 0) * ST + tt] = v.x;
                xs[(c4 + 1) * ST + tt] = v.y;
                xs[(c4 + 2) * ST + tt] = v.z;
                xs[(c4 + 3) * ST + tt] = v.w;
            }
        } else {
            for (int i = tid; i < (CT + 2) * CI; i += 512) {
                int tt = i / CI, ci = i % CI;
                int t = t0 + tt;
                float v = 0.f;
                if (t < Tin) v = xin[(((size_t)b * Tin + t) * NNODE + n) * CI + ci];
                xs[ci * ST + tt] = v;
            }
        }
        __syncthreads();

        u64 accP[3][HP];
#pragma unroll
        for (int g = 0; g < 3; g++)
#pragma unroll
            for (int p = 0; p < HP; p++) accP[g][p] = 0ull;

#pragma unroll 2
        for (int ci = 0; ci < CI; ci++) {
            const float* xp = &xs[ci * ST + tb];
            u64 ep[HP + 1];
#pragma unroll
            for (int p = 0; p <= HP; p++) ep[p] = *reinterpret_cast<const u64*>(xp + 2 * p);
            float xl[HP + 1], xh[HP + 1];
#pragma unroll
            for (int p = 0; p <= HP; p++) unpk2(ep[p], xl[p], xh[p]);
            u64 op[HP];
#pragma unroll
            for (int p = 0; p < HP; p++) op[p] = pk2(xh[p], xl[p + 1]);

#pragma unroll
            for (int g = 0; g < 3; g++) {
#pragma unroll
                for (int k = 0; k < 3; k++) {
                    u64 wd = dup2(ws[((g * CI + ci) * 3 + k) * 64 + o]);
                    const u64* xq = (k == 0) ? ep : (k == 1) ? op : (ep + 1);
#pragma unroll
                    for (int p = 0; p < HP; p++) fma2(accP[g][p], xq[p], wd);
                }
            }
        }

        float s1 = 0.f, s2 = 0.f;
#pragma unroll
        for (int p = 0; p < HP; p++) {
            float P0, P1, Q0, Q1, R0, R1;
            unpk2(accP[0][p], P0, P1);
            unpk2(accP[1][p], Q0, Q1);
            unpk2(accP[2][p], R0, R1);
#pragma unroll
            for (int half = 0; half < 2; half++) {
                int t = t0 + tb + 2 * p + half;
                if (t < Tout) {
                    float P = (half ? P1 : P0) + bP;
                    float Q = (half ? Q1 : Q0) + bQ;
                    float R = (half ? R1 : R0) + bR;
                    float sg = 1.f / (1.f + __expf(-Q));
                    float h = fmaxf(fmaf(P, sg, R), 0.f);
                    out[(((size_t)b * Tout + t) * NNODE + n) * CH + o] = h;
                    s1 += h;
                    s2 += h * h;
                }
            }
        }

        if (bnsum != nullptr) {
#pragma unroll
            for (int off = 16; off > 0; off >>= 1) {
                s1 += __shfl_xor_sync(0xffffffffu, s1, off);
                s2 += __shfl_xor_sync(0xffffffffu, s2, off);
            }
            int wid = tid >> 5, lane = tid & 31;
            if (lane == 0) { wsm1[wid] = (double)s1; wsm2[wid] = (double)s2; }
            __syncthreads();
            if (tid == 0) {
                double a = 0.0, c = 0.0;
#pragma unroll
                for (int i = 0; i < 16; i++) { a += wsm1[i]; c += wsm2[i]; }
                atomicAdd(&bnsum[n], a);
                atomicAdd(&bnsqs[n], c);
            }
        }
    }
}

// ---------------- BN finalize ----------------
__global__ void finalize_bn_kernel(const double* __restrict__ sum, const double* __restrict__ sqs,
                                   const float* __restrict__ gamma, const float* __restrict__ beta,
                                   double cnt, float* __restrict__ scl, float* __restrict__ shf) {
    int nn = threadIdx.x;
    if (nn < NNODE) {
        double m = sum[nn] / cnt;
        double v = sqs[nn] / cnt - m * m;
        double inv = 1.0 / sqrt(v + 1e-5);
        double sc = (double)gamma[nn] * inv;
        scl[nn] = (float)sc;
        shf[nn] = (float)((double)beta[nn] - m * sc);
    }
}

// ---------------- persistent ChebConv K=3 + relu ----------------
__global__ void __launch_bounds__(288)
cheb_kernel(const float* __restrict__ zin, int T,
            const float* __restrict__ cw, const float* __restrict__ cb,
            float* __restrict__ out) {
    constexpr int TT  = 4;
    constexpr int STR = 68;
    extern __shared__ float sm[];
    float* Wsm = sm;                    // 12288
    float* bsm = Wsm + 3 * 64 * 64;     // 64
    float* Lsm = bsm + 64;              // 1296
    float* Z   = Lsm + NPAD * NPAD;
    float* X1  = Z + TT * NPAD * STR;
    float* X2  = X1 + TT * NPAD * STR;

    const int tid = threadIdx.x;

    // ---- static data: once per CTA ----
    {
        const float4* w4 = reinterpret_cast<const float4*>(cw);
        float4* s4 = reinterpret_cast<float4*>(Wsm);
        for (int i = tid; i < 3 * 64 * 16; i += 288) s4[i] = w4[i];
    }
    if (tid < 64) bsm[tid] = cb[tid];
    for (int i = tid; i < NPAD * NPAD; i += 288) Lsm[i] = g_L[i];

    const int tt = tid / 72;
    const int r  = tid % 72;
    const int n0 = (r / 8) * 4;
    const int q0 = (r % 8) * 8;

    const int ntt    = (T + TT - 1) / TT;
    const int ntiles = ntt * BATCH;

    for (int tile = blockIdx.x; tile < ntiles; tile += gridDim.x) {
        const int tch = tile % ntt;
        const int b   = tile / ntt;
        const int t0  = tch * TT;

        __syncthreads();
        for (int i4 = tid; i4 < TT * NPAD * 16; i4 += 288) {
            int ti = i4 / (NPAD * 16);
            int rr = i4 % (NPAD * 16);
            int nn = rr / 16;
            int c4 = (rr % 16) << 2;
            int t = t0 + ti;
            float4 v = make_float4(0.f, 0.f, 0.f, 0.f);
            if (t < T && nn < NNODE)
                v = *reinterpret_cast<const float4*>(
                    &zin[(((size_t)b * T + t) * NNODE + nn) * CH + c4]);
            *reinterpret_cast<float4*>(&Z[(ti * NPAD + nn) * STR + c4]) = v;
        }
        __syncthreads();

        // ---- prop1: X1 = L * Z   (cols 33..35 of L are zero -> loop to 33)
        {
            u64 acc[4][4];
#pragma unroll
            for (int a = 0; a < 4; a++)
#pragma unroll
                for (int p = 0; p < 4; p++) acc[a][p] = 0ull;
#pragma unroll 3
            for (int m = 0; m < NNODE; m++) {
                const u64* zr = reinterpret_cast<const u64*>(&Z[(tt * NPAD + m) * STR + q0]);
                u64 z0 = zr[0], z1 = zr[1], z2 = zr[2], z3 = zr[3];
#pragma unroll
                for (int a = 0; a < 4; a++) {
                    u64 ld = dup2(Lsm[(n0 + a) * NPAD + m]);
                    fma2(acc[a][0], z0, ld);
                    fma2(acc[a][1], z1, ld);
                    fma2(acc[a][2], z2, ld);
                    fma2(acc[a][3], z3, ld);
                }
            }
#pragma unroll
            for (int a = 0; a < 4; a++) {
                u64* xp = reinterpret_cast<u64*>(&X1[(tt * NPAD + n0 + a) * STR + q0]);
#pragma unroll
                for (int p = 0; p < 4; p++) xp[p] = acc[a][p];
            }
        }
        __syncthreads();

        // ---- prop2: X2 = 2*(L * X1) - Z
        {
            u64 acc[4][4];
#pragma unroll
            for (int a = 0; a < 4; a++)
#pragma unroll
                for (int p = 0; p < 4; p++) acc[a][p] = 0ull;
#pragma unroll 3
            for (int m = 0; m < NNODE; m++) {
                const u64* xr = reinterpret_cast<const u64*>(&X1[(tt * NPAD + m) * STR + q0]);
                u64 x0 = xr[0], x1 = xr[1], x2 = xr[2], x3 = xr[3];
#pragma unroll
                for (int a = 0; a < 4; a++) {
                    u64 ld = dup2(Lsm[(n0 + a) * NPAD + m]);
                    fma2(acc[a][0], x0, ld);
                    fma2(acc[a][1], x1, ld);
                    fma2(acc[a][2], x2, ld);
                    fma2(acc[a][3], x3, ld);
                }
            }
#pragma unroll
            for (int a = 0; a < 4; a++) {
                int base = (tt * NPAD + n0 + a) * STR + q0;
#pragma unroll
                for (int p = 0; p < 4; p++) {
                    float alo, ahi;
                    unpk2(acc[a][p], alo, ahi);
                    X2[base + 2 * p]     = 2.f * alo - Z[base + 2 * p];
                    X2[base + 2 * p + 1] = 2.f * ahi - Z[base + 2 * p + 1];
                }
            }
        }
        __syncthreads();

        // ---- GEMM: out = relu(Z*W0 + X1*W1 + X2*W2 + b)
        {
            u64 acc[4][4];
#pragma unroll
            for (int a = 0; a < 4; a++)
#pragma unroll
                for (int p = 0; p < 4; p++) acc[a][p] = 0ull;
#pragma unroll 2
            for (int c = 0; c < 64; c++) {
                const u64* w0 = reinterpret_cast<const u64*>(&Wsm[(0 * 64 + c) * 64 + q0]);
                const u64* w1 = reinterpret_cast<const u64*>(&Wsm[(1 * 64 + c) * 64 + q0]);
                const u64* w2 = reinterpret_cast<const u64*>(&Wsm[(2 * 64 + c) * 64 + q0]);
                u64 w00 = w0[0], w01 = w0[1], w02 = w0[2], w03 = w0[3];
                u64 w10 = w1[0], w11 = w1[1], w12 = w1[2], w13 = w1[3];
                u64 w20 = w2[0], w21 = w2[1], w22 = w2[2], w23 = w2[3];
#pragma unroll
                for (int a = 0; a < 4; a++) {
                    int base = (tt * NPAD + n0 + a) * STR + c;
                    u64 zd  = dup2(Z[base]);
                    u64 x1d = dup2(X1[base]);
                    u64 x2d = dup2(X2[base]);
                    fma2(acc[a][0], w00, zd);  fma2(acc[a][1], w01, zd);
                    fma2(acc[a][2], w02, zd);  fma2(acc[a][3], w03, zd);
                    fma2(acc[a][0], w10, x1d); fma2(acc[a][1], w11, x1d);
                    fma2(acc[a][2], w12, x1d); fma2(acc[a][3], w13, x1d);
                    fma2(acc[a][0], w20, x2d); fma2(acc[a][1], w21, x2d);
                    fma2(acc[a][2], w22, x2d); fma2(acc[a][3], w23, x2d);
                }
            }
            int t = t0 + tt;
            if (t < T) {
#pragma unroll
                for (int a = 0; a < 4; a++) {
                    int nn = n0 + a;
                    if (nn < NNODE) {
                        float* op = &out[(((size_t)b * T + t) * NNODE + nn) * CH + q0];
                        float v[8];
#pragma unroll
                        for (int p = 0; p < 4; p++) {
                            float alo, ahi;
                            unpk2(acc[a][p], alo, ahi);
                            v[2 * p]     = fmaxf(alo + bsm[q0 + 2 * p], 0.f);
                            v[2 * p + 1] = fmaxf(ahi + bsm[q0 + 2 * p + 1], 0.f);
                        }
                        *reinterpret_cast<float4*>(op)     = make_float4(v[0], v[1], v[2], v[3]);
                        *reinterpret_cast<float4*>(op + 4) = make_float4(v[4], v[5], v[6], v[7]);
                    }
                }
            }
        }
    }
}

// ---------------- fused BN+relu+time-mean ----------------
__global__ void timemean_kernel(const float* __restrict__ x, int T,
                                const float* __restrict__ scl, const float* __restrict__ shf) {
    const int n = blockIdx.x, b = blockIdx.y, c = threadIdx.x;
    const float sc = scl[n], sh = shf[n];
    double s = 0.0;
#pragma unroll 4
    for (int t = 0; t < T; t++) {
        float v = x[(((size_t)b * T + t) * NNODE + n) * CH + c];
        v = fmaxf(fmaf(v, sc, sh), 0.f);
        s += (double)v;
    }
    g_M[(b * NNODE + n) * CH + c] = (float)(s / (double)T);
}

// ---------------- classifier ----------------
__global__ void __launch_bounds__(256)
fc_kernel(const float* __restrict__ w1, const float* __restrict__ b1,
          const float* __restrict__ w2, const float* __restrict__ b2,
          float* __restrict__ out) {
    __shared__ float ms[NNODE * CH];
    __shared__ float h1[256];
    const int b = blockIdx.x, tid = threadIdx.x;
    for (int i = tid; i < NNODE * CH; i += 256) ms[i] = g_M[b * NNODE * CH + i];
    __syncthreads();
    double acc = (double)b1[tid];
    for (int i = 0; i < NNODE * CH; i++) acc += (double)ms[i] * (double)w1[i * 256 + tid];
    h1[tid] = fmaxf((float)acc, 0.f);
    __syncthreads();
    if (tid < 10) {
        double a2 = (double)b2[tid];
        for (int i = 0; i < 256; i++) a2 += (double)h1[i] * (double)w2[i * 10 + tid];
        out[b * 10 + tid] = (float)a2;
    }
}

// ---------------- launch ----------------
extern "C" void kernel_launch(void* const* d_in, const int* in_sizes, int n_in,
                              void* d_out, int out_size) {
    const float* x        = (const float*)d_in[0];
    const int*   ei       = (const int*)d_in[1];
    const float* s1_tc1_w = (const float*)d_in[2];
    const float* s1_tc1_b = (const float*)d_in[3];
    const float* s1_cheb_w= (const float*)d_in[4];
    const float* s1_cheb_b= (const float*)d_in[5];
    const float* s1_tc2_w = (const float*)d_in[6];
    const float* s1_tc2_b = (const float*)d_in[7];
    const float* s1_bn_g  = (const float*)d_in[8];
    const float* s1_bn_b  = (const float*)d_in[9];
    const float* s2_tc1_w = (const float*)d_in[10];
    const float* s2_tc1_b = (const float*)d_in[11];
    const float* s2_cheb_w= (const float*)d_in[12];
    const float* s2_cheb_b= (const float*)d_in[13];
    const float* s2_tc2_w = (const float*)d_in[14];
    const float* s2_tc2_b = (const float*)d_in[15];
    const float* s2_bn_g  = (const float*)d_in[16];
    const float* s2_bn_b  = (const float*)d_in[17];
    const float* fc1_w    = (const float*)d_in[18];
    const float* fc1_b    = (const float*)d_in[19];
    const float* fc2_w    = (const float*)d_in[20];
    const float* fc2_b    = (const float*)d_in[21];

    float *bufA, *bufB, *w1a, *w1b, *w2a, *w2b, *scl1, *shf1, *scl2, *shf2;
    double *sum1, *sqs1, *sum2, *sqs2;
    cudaGetSymbolAddress((void**)&bufA, g_bufA);
    cudaGetSymbolAddress((void**)&bufB, g_bufB);
    cudaGetSymbolAddress((void**)&w1a, g_w1a);
    cudaGetSymbolAddress((void**)&w1b, g_w1b);
    cudaGetSymbolAddress((void**)&w2a, g_w2a);
    cudaGetSymbolAddress((void**)&w2b, g_w2b);
    cudaGetSymbolAddress((void**)&scl1, g_scl1);
    cudaGetSymbolAddress((void**)&shf1, g_shf1);
    cudaGetSymbolAddress((void**)&scl2, g_scl2);
    cudaGetSymbolAddress((void**)&shf2, g_shf2);
    cudaGetSymbolAddress((void**)&sum1, g_sum1);
    cudaGetSymbolAddress((void**)&sqs1, g_sqs1);
    cudaGetSymbolAddress((void**)&sum2, g_sum2);
    cudaGetSymbolAddress((void**)&sqs2, g_sqs2);

    const size_t sm3  = (size_t)(3 * 3 * 3 * 64 + 3 * 132) * sizeof(float);
    const size_t sm64 = (size_t)(3 * 64 * 3 * 64 + 64 * 132) * sizeof(float);
    const size_t smC  = (size_t)(3 * 64 * 64 + 64 + NPAD * NPAD + 3 * 4 * NPAD * 68) * sizeof(float);

    cudaFuncSetAttribute(tconv_kernel<3>,  cudaFuncAttributeMaxDynamicSharedMemorySize, (int)sm3);
    cudaFuncSetAttribute(tconv_kernel<64>, cudaFuncAttributeMaxDynamicSharedMemorySize, (int)sm64);
    cudaFuncSetAttribute(cheb_kernel,      cudaFuncAttributeMaxDynamicSharedMemorySize, (int)smC);

    const int ne = in_sizes[1] / 2;
    const int GRID = 148;
    dim3 tblk(64, 8);

    // launch indices (for ncu -s 5: #5 = first big tconv<64>)
    setup_kernel<<<1, 64>>>(ei, ne);                                                  // 0
    reorder2_kernel<<<(3 * 576 + 64 * 576 + 255) / 256, 256>>>(s1_tc1_w, w1a, 3,
                                                               s1_tc2_w, w1b, 64);    // 1
    reorder2_kernel<<<(2 * 64 * 576 + 255) / 256, 256>>>(s2_tc1_w, w2a, 64,
                                                         s2_tc2_w, w2b, 64);          // 2

    // ---- STConv 1 ----
    tconv_kernel<3><<<GRID, tblk, sm3>>>(x, 512, w1a, s1_tc1_b,
                                         nullptr, nullptr, 0, bufA, nullptr, nullptr); // 3: T=510
    cheb_kernel<<<GRID, 288, smC>>>(bufA, 510, s1_cheb_w, s1_cheb_b, bufB);            // 4
    tconv_kernel<64><<<GRID, tblk, sm64>>>(bufB, 510, w1b, s1_tc2_b,
                                           nullptr, nullptr, 0, bufA, sum1, sqs1);     // 5: T=508 (profiled)
    finalize_bn_kernel<<<1, 64>>>(sum1, sqs1, s1_bn_g, s1_bn_b,
                                  (double)BATCH * 508.0 * 64.0, scl1, shf1);           // 6

    // ---- STConv 2 (BN1+relu fused into input load) ----
    tconv_kernel<64><<<GRID, tblk, sm64>>>(bufA, 508, w2a, s2_tc1_b,
                                           scl1, shf1, 1, bufB, nullptr, nullptr);     // 7: T=506
    cheb_kernel<<<GRID, 288, smC>>>(bufB, 506, s2_cheb_w, s2_cheb_b, bufA);            // 8
    tconv_kernel<64><<<GRID, tblk, sm64>>>(bufA, 506, w2b, s2_tc2_b,
                                           nullptr, nullptr, 0, bufB, sum2, sqs2);     // 9: T=504
    finalize_bn_kernel<<<1, 64>>>(sum2, sqs2, s2_bn_g, s2_bn_b,
                                  (double)BATCH * 504.0 * 64.0, scl2, shf2);           // 10

    // ---- head ----
    timemean_kernel<<<dim3(NNODE, BATCH), 64>>>(bufB, 504, scl2, shf2);                // 11
    fc_kernel<<<BATCH, 256>>>(fc1_w, fc1_b, fc2_w, fc2_b, (float*)d_out);              // 12
}

// round 5
// speedup vs baseline: 1.9899x; 1.1966x over previous
#include <cuda_runtime.h>
#include <cuda_bf16.h>
#include <math.h>

#define BATCH 32
#define NNODE 33
#define NSTR  40      // padded node stride: +1 time tap = +40 rows = 5120 B (swizzle-atom aligned)
#define NPAD  36
#define CH    64

typedef unsigned long long u64;
typedef unsigned int u32;

// ---------------- f32x2 helpers (SIMT kernels) ----------------
__device__ __forceinline__ u64 pk2(float lo, float hi) {
    u64 r;
    asm("mov.b64 %0, {%1, %2};" : "=l"(r) : "r"(__float_as_uint(lo)), "r"(__float_as_uint(hi)));
    return r;
}
__device__ __forceinline__ u64 dup2(float v) { return pk2(v, v); }
__device__ __forceinline__ void unpk2(u64 v, float& lo, float& hi) {
    u32 a, b;
    asm("mov.b64 {%0, %1}, %2;" : "=r"(a), "=r"(b) : "l"(v));
    lo = __uint_as_float(a);
    hi = __uint_as_float(b);
}
__device__ __forceinline__ void fma2(u64& d, u64 a, u64 b) {
    asm("fma.rn.f32x2 %0, %1, %2, %0;" : "+l"(d) : "l"(a), "l"(b));
}

// ---------------- mma.sync / ldmatrix helpers (arch-neutral PTX) ----------------
__device__ __forceinline__ u32 smem_u32(const void* p) {
    u32 a;
    asm("{ .reg .u64 t; cvta.to.shared.u64 t, %1; cvt.u32.u64 %0, t; }" : "=r"(a) : "l"(p));
    return a;
}
__device__ __forceinline__ void ldsm_x4(u32* r, u32 addr) {
    asm volatile("ldmatrix.sync.aligned.m8n8.x4.shared.b16 {%0,%1,%2,%3}, [%4];"
                 : "=r"(r[0]), "=r"(r[1]), "=r"(r[2]), "=r"(r[3]) : "r"(addr));
}
__device__ __forceinline__ void mma_bf16(float* c, const u32* a, u32 b0, u32 b1) {
    asm volatile("mma.sync.aligned.m16n8k16.row.col.f32.bf16.bf16.f32 "
                 "{%0,%1,%2,%3}, {%4,%5,%6,%7}, {%8,%9}, {%0,%1,%2,%3};"
                 : "+f"(c[0]), "+f"(c[1]), "+f"(c[2]), "+f"(c[3])
                 : "r"(a[0]), "r"(a[1]), "r"(a[2]), "r"(a[3]), "r"(b0), "r"(b1));
}
__device__ __forceinline__ u64 pack4bf(__nv_bfloat16 a, __nv_bfloat16 b,
                                       __nv_bfloat16 c, __nv_bfloat16 d) {
    u32 u0 = ((u32)__bfloat16_as_ushort(b) << 16) | (u32)__bfloat16_as_ushort(a);
    u32 u1 = ((u32)__bfloat16_as_ushort(d) << 16) | (u32)__bfloat16_as_ushort(c);
    return (u64)u0 | ((u64)u1 << 32);
}

// ---------------- device scratch ----------------
#define BUF_ELEMS ((size_t)BATCH * 510 * NSTR * CH)
__device__ float g_bufA[BUF_ELEMS];
__device__ float g_bufB[BUF_ELEMS];
__device__ float g_L[NPAD * NPAD];
__device__ float g_w1a[3 * 3 * 3 * 64];
__device__ u32   g_Bw1[36864], g_Bw2[36864], g_Bw3[36864];
__device__ float g_scl1[NNODE], g_shf1[NNODE];
__device__ float g_scl2[NNODE], g_shf2[NNODE];
__device__ double g_sum1[NNODE], g_sqs1[NNODE];
__device__ double g_sum2[NNODE], g_sqs2[NNODE];
__device__ float g_M[BATCH * NNODE * CH];

// ---------------- setup ----------------
__global__ void setup_kernel(const int* __restrict__ ei, int ne, const float* __restrict__ w3) {
    int i = threadIdx.x;
    if (i < NNODE) { g_sum1[i] = 0.0; g_sqs1[i] = 0.0; g_sum2[i] = 0.0; g_sqs2[i] = 0.0; }
    for (int j = i; j < 3 * 3 * 3 * 64; j += 64) {
        int o  = j & 63;
        int k  = (j >> 6) % 3;
        int ci = (j / 192) % 3;
        int g  = j / (192 * 3);
        g_w1a[j] = w3[((g * 64 + o) * 3 + ci) * 3 + k];
    }
    if (i == 0) {
        double deg[NNODE];
        for (int k = 0; k < NNODE; k++) deg[k] = 0.0;
        for (int e = 0; e < ne; e++) deg[ei[e]] += 1.0;
        double dinv[NNODE];
        for (int k = 0; k < NNODE; k++) dinv[k] = (deg[k] > 0.0) ? (1.0 / sqrt(deg[k])) : 0.0;
        for (int k = 0; k < NPAD * NPAD; k++) g_L[k] = 0.0f;
        for (int e = 0; e < ne; e++) {
            int s = ei[e];
            int t = ei[ne + e];
            g_L[t * NPAD + s] += (float)(-dinv[s] * dinv[t]);
        }
    }
}

// ---- convert 64-ci tconv weights -> bf16 hi/lo; region r=(g*3+k)*2+s, row=o, 32 ci-pair words
__global__ void convert_w_kernel(const float* __restrict__ w, u32* __restrict__ outw) {
    int i = blockIdx.x * blockDim.x + threadIdx.x;
    if (i >= 36864) return;
    int region = i >> 11;
    int rem    = i & 2047;
    int o      = rem >> 5;
    int c2     = rem & 31;
    int s  = region & 1;
    int gk = region >> 1;
    int g  = gk / 3, k = gk % 3;
    int ci0 = 2 * c2;
    float v0 = w[((g * 64 + o) * 64 + ci0) * 3 + k];
    float v1 = w[((g * 64 + o) * 64 + ci0 + 1) * 3 + k];
    __nv_bfloat16 h0 = __float2bfloat16(v0), h1 = __float2bfloat16(v1);
    __nv_bfloat16 b0, b1;
    if (s == 0) { b0 = h0; b1 = h1; }
    else {
        b0 = __float2bfloat16(v0 - __bfloat162float(h0));
        b1 = __float2bfloat16(v1 - __bfloat162float(h1));
    }
    outw[i] = ((u32)__bfloat16_as_ushort(b1) << 16) | (u32)__bfloat16_as_ushort(b0);
}

// ---------------- SIMT gated tconv CI=3 (first layer), out stride NSTR ----------------
__global__ void __launch_bounds__(512)
tconv3_kernel(const float* __restrict__ xin,
              const float* __restrict__ bias,
              float* __restrict__ out) {
    constexpr int CI = 3, CT = 128, TO = 16, ST = CT + 4, HP = TO / 2;
    constexpr int Tin = 512, Tout = 510;
    __shared__ float ws[3 * CI * 3 * 64];
    __shared__ float xs[CI * ST];

    const int tid = threadIdx.y * 64 + threadIdx.x;
    const int ntch = (Tout + CT - 1) / CT;
    const int ntiles = ntch * NNODE * BATCH;

    for (int i = tid; i < 3 * CI * 3 * 64; i += 512) ws[i] = g_w1a[i];

    const int o  = threadIdx.x;
    const int tb = threadIdx.y * TO;
    const float bP = bias[o], bQ = bias[64 + o], bR = bias[128 + o];

    for (int tile = blockIdx.x; tile < ntiles; tile += gridDim.x) {
        const int tch = tile % ntch;
        const int rem = tile / ntch;
        const int n   = rem % NNODE;
        const int b   = rem / NNODE;
        const int t0  = tch * CT;

        __syncthreads();
        for (int i = tid; i < (CT + 2) * CI; i += 512) {
            int tt = i / CI, ci = i % CI;
            int t = t0 + tt;
            float v = 0.f;
            if (t < Tin) v = xin[(((size_t)b * Tin + t) * NNODE + n) * CI + ci];
            xs[ci * ST + tt] = v;
        }
        __syncthreads();

        u64 accP[3][HP];
#pragma unroll
        for (int g = 0; g < 3; g++)
#pragma unroll
            for (int p = 0; p < HP; p++) accP[g][p] = 0ull;

#pragma unroll
        for (int ci = 0; ci < CI; ci++) {
            const float* xp = &xs[ci * ST + tb];
            u64 ep[HP + 1];
#pragma unroll
            for (int p = 0; p <= HP; p++) ep[p] = *reinterpret_cast<const u64*>(xp + 2 * p);
            float xl[HP + 1], xh[HP + 1];
#pragma unroll
            for (int p = 0; p <= HP; p++) unpk2(ep[p], xl[p], xh[p]);
            u64 op[HP];
#pragma unroll
            for (int p = 0; p < HP; p++) op[p] = pk2(xh[p], xl[p + 1]);

#pragma unroll
            for (int g = 0; g < 3; g++) {
#pragma unroll
                for (int k = 0; k < 3; k++) {
                    u64 wd = dup2(ws[((g * CI + ci) * 3 + k) * 64 + o]);
                    const u64* xq = (k == 0) ? ep : (k == 1) ? op : (ep + 1);
#pragma unroll
                    for (int p = 0; p < HP; p++) fma2(accP[g][p], xq[p], wd);
                }
            }
        }

#pragma unroll
        for (int p = 0; p < HP; p++) {
            float P0, P1, Q0, Q1, R0, R1;
            unpk2(accP[0][p], P0, P1);
            unpk2(accP[1][p], Q0, Q1);
            unpk2(accP[2][p], R0, R1);
#pragma unroll
            for (int half = 0; half < 2; half++) {
                int t = t0 + tb + 2 * p + half;
                if (t < Tout) {
                    float P = (half ? P1 : P0) + bP;
                    float Q = (half ? Q1 : Q0) + bQ;
                    float R = (half ? R1 : R0) + bR;
                    float sg = 1.f / (1.f + __expf(-Q));
                    float h = fmaxf(fmaf(P, sg, R), 0.f);
                    out[(((size_t)b * Tout + t) * NSTR + n) * CH + o] = h;
                }
            }
        }
    }
}

// ---------------- mma.sync gated tconv CI=64 ----------------
// out[(t,n),192] = sum_k A[(t+k,n),64]*W_k[64,192]; rows padded to NSTR=40 nodes.
// bf16 hi/lo split: D = Ah*Bh + Al*Bh + Ah*Bl (fp32 accumulate).
#define ROWS_A 208
#define A_SPLIT_B (ROWS_A * 128)        // 26624
#define B_BYTES   (18 * 8192)           // 147456
#define OFF_B     1024
#define OFF_A     (OFF_B + B_BYTES)
#define TC_SMEM   (OFF_A + 2 * A_SPLIT_B + 1024)

__global__ void __launch_bounds__(256, 1)
tconv_mma_kernel(const float* __restrict__ xin, int Tin,
                 const u32* __restrict__ Bw,
                 const float* __restrict__ bias,
                 const float* __restrict__ scl, const float* __restrict__ shf, int mode,
                 float* __restrict__ out) {
    extern __shared__ char smraw[];
    __shared__ float sbias[192];

    const u32 sb0 = smem_u32(smraw);
    const u32 sbase = (sb0 + 1023) & ~1023u;
    char* sm = smraw + (sbase - sb0);

    const int tid = threadIdx.x;
    const int wid = tid >> 5, lane = tid & 31;
    const int Tout = Tin - 2;
    const int RowsIn = Tin * NSTR, RowsOut = Tout * NSTR;
    const int ntb = (RowsOut + 127) / 128;
    const int ntiles = ntb * BATCH;

    // B (weights) -> smem, SW128-swizzled, once per CTA
    for (int i = tid; i < 36864; i += 256) {
        int r = i >> 11, rem = i & 2047, row = rem >> 5, c2 = rem & 31;
        u32 byte = row * 128 + c2 * 4;
        *(u32*)(sm + OFF_B + r * 8192 + (byte ^ ((byte >> 3) & 0x70))) = Bw[i];
    }
    if (tid < 192) sbias[tid] = bias[tid];
    __syncthreads();

    const int warp_m = wid & 3;          // m32 block
    const int o0 = (wid >> 2) * 32;      // o32 block (per gate)

    // per-lane ldmatrix address components
    const u32 a_row_l = lane & 15;
    const u32 a_koff  = (lane & 16) ? 16u : 0u;
    const u32 b_row_l = lane & 7;
    const u32 b_koff  = (lane & 8) ? 16u : 0u;
    const u32 b_sreg  = (lane & 16) ? 8192u : 0u;   // lanes 16-31 fetch the lo-split region

    const int trow = lane >> 2;
    const int tcol = (lane & 3) * 2;

    for (int tile = blockIdx.x; tile < ntiles; tile += gridDim.x) {
        const int bidx = tile / ntb, tl = tile % ntb;
        const int local0 = tl * 128;
        const float* xb = xin + (size_t)bidx * RowsIn * 64;

        __syncthreads();   // protect A smem against previous iteration's readers

        // ---- A fill: 208 rows x 64ci, bf16 hi/lo, SW128-swizzled ----
        for (int i4 = tid; i4 < ROWS_A * 16; i4 += 256) {
            int r = i4 >> 4, c4 = (i4 & 15) << 2;
            int il = local0 + r;
            float4 v = make_float4(0.f, 0.f, 0.f, 0.f);
            if (il < RowsIn) {
                int n = il % NSTR;
                if (n < NNODE) {
                    v = *(const float4*)(xb + (size_t)il * 64 + c4);
                    if (mode) {
                        float sc = scl[n], sh = shf[n];
                        v.x = fmaxf(fmaf(v.x, sc, sh), 0.f);
                        v.y = fmaxf(fmaf(v.y, sc, sh), 0.f);
                        v.z = fmaxf(fmaf(v.z, sc, sh), 0.f);
                        v.w = fmaxf(fmaf(v.w, sc, sh), 0.f);
                    }
                }
            }
            __nv_bfloat16 hx = __float2bfloat16(v.x), hy = __float2bfloat16(v.y);
            __nv_bfloat16 hz = __float2bfloat16(v.z), hw = __float2bfloat16(v.w);
            u32 byte = r * 128 + (c4 << 1);
            u32 sw = byte ^ ((byte >> 3) & 0x70);
            *(u64*)(sm + OFF_A + sw) = pack4bf(hx, hy, hz, hw);
            __nv_bfloat16 lx = __float2bfloat16(v.x - __bfloat162float(hx));
            __nv_bfloat16 ly = __float2bfloat16(v.y - __bfloat162float(hy));
            __nv_bfloat16 lz = __float2bfloat16(v.z - __bfloat162float(hz));
            __nv_bfloat16 lw = __float2bfloat16(v.w - __bfloat162float(hw));
            *(u64*)(sm + OFF_A + A_SPLIT_B + sw) = pack4bf(lx, ly, lz, lw);
        }
        __syncthreads();

        // ---- GEMM: warp tile m32 x (3 gates x o32) ----
        float acc[2][3][4][4];
#pragma unroll
        for (int h = 0; h < 2; h++)
#pragma unroll
            for (int g = 0; g < 3; g++)
#pragma unroll
                for (int ot = 0; ot < 4; ot++)
#pragma unroll
                    for (int c = 0; c < 4; c++) acc[h][g][ot][c] = 0.f;

#pragma unroll
        for (int tap = 0; tap < 3; tap++) {
#pragma unroll
            for (int kc = 0; kc < 4; kc++) {
                u32 ah[2][4], al[2][4];
#pragma unroll
                for (int h = 0; h < 2; h++) {
                    u32 rb = (u32)(tap * 40 + warp_m * 32 + h * 16) + a_row_l;
                    u32 byte = rb * 128 + (u32)(kc * 32) + a_koff;
                    u32 sw = byte ^ ((byte >> 3) & 0x70);
                    ldsm_x4(ah[h], sbase + OFF_A + sw);
                    ldsm_x4(al[h], sbase + OFF_A + A_SPLIT_B + sw);
                }
#pragma unroll
                for (int g = 0; g < 3; g++) {
                    u32 breg = sbase + OFF_B + (u32)((g * 3 + tap) * 2) * 8192 + b_sreg;
                    u32 bf[4][4];   // [ot]{bh0,bh1,bl0,bl1}
#pragma unroll
                    for (int ot = 0; ot < 4; ot++) {
                        u32 byte = (u32)(o0 + 8 * ot + (int)b_row_l) * 128 + (u32)(kc * 32) + b_koff;
                        ldsm_x4(bf[ot], breg + (byte ^ ((byte >> 3) & 0x70)));
                    }
                    // hh pass
#pragma unroll
                    for (int ot = 0; ot < 4; ot++) {
                        mma_bf16(acc[0][g][ot], ah[0], bf[ot][0], bf[ot][1]);
                        mma_bf16(acc[1][g][ot], ah[1], bf[ot][0], bf[ot][1]);
                    }
                    // lh pass
#pragma unroll
                    for (int ot = 0; ot < 4; ot++) {
                        mma_bf16(acc[0][g][ot], al[0], bf[ot][0], bf[ot][1]);
                        mma_bf16(acc[1][g][ot], al[1], bf[ot][0], bf[ot][1]);
                    }
                    // hl pass
#pragma unroll
                    for (int ot = 0; ot < 4; ot++) {
                        mma_bf16(acc[0][g][ot], ah[0], bf[ot][2], bf[ot][3]);
                        mma_bf16(acc[1][g][ot], ah[1], bf[ot][2], bf[ot][3]);
                    }
                }
            }
        }

        // ---- epilogue: gate + store ----
#pragma unroll
        for (int h = 0; h < 2; h++) {
#pragma unroll
            for (int rs = 0; rs < 2; rs++) {
                int row = warp_m * 32 + h * 16 + trow + rs * 8;
                int ol = local0 + row;
                if (ol < RowsOut) {
                    float* op = out + ((size_t)bidx * RowsOut + ol) * 64;
#pragma unroll
                    for (int ot = 0; ot < 4; ot++) {
                        int o = o0 + 8 * ot + tcol;
                        float2 hv;
#pragma unroll
                        for (int e = 0; e < 2; e++) {
                            float P = acc[h][0][ot][rs * 2 + e] + sbias[o + e];
                            float Q = acc[h][1][ot][rs * 2 + e] + sbias[64 + o + e];
                            float R = acc[h][2][ot][rs * 2 + e] + sbias[128 + o + e];
                            float sg = 1.f / (1.f + __expf(-Q));
                            float hval = fmaxf(fmaf(P, sg, R), 0.f);
                            if (e == 0) hv.x = hval; else hv.y = hval;
                        }
                        *(float2*)(op + o) = hv;
                    }
                }
            }
        }
    }
}

// ---------------- BN stats (parallel over nodes x batches) ----------------
__global__ void __launch_bounds__(256)
bnstats_kernel(const float* __restrict__ x, int T,
               double* __restrict__ bnsum, double* __restrict__ bnsqs) {
    const int n = blockIdx.x, b = blockIdx.y, tid = threadIdx.x;
    const float* xp = x + ((size_t)b * T * NSTR + n) * 64;
    double s = 0.0, q = 0.0;
    for (int i = tid; i < T * 16; i += 256) {
        int t = i >> 4, c4 = (i & 15) << 2;
        float4 v = *(const float4*)(xp + (size_t)t * NSTR * 64 + c4);
        s += (double)v.x + (double)v.y + (double)v.z + (double)v.w;
        q += (double)v.x * v.x + (double)v.y * v.y + (double)v.z * v.z + (double)v.w * v.w;
    }
    __shared__ double r1[256], r2[256];
    r1[tid] = s; r2[tid] = q;
    __syncthreads();
    for (int st = 128; st > 0; st >>= 1) {
        if (tid < st) { r1[tid] += r1[tid + st]; r2[tid] += r2[tid + st]; }
        __syncthreads();
    }
    if (tid == 0) {
        atomicAdd(&bnsum[n], r1[0]);
        atomicAdd(&bnsqs[n], r2[0]);
    }
}

// ---------------- BN finalize ----------------
__global__ void finalize_bn_kernel(const double* __restrict__ sum, const double* __restrict__ sqs,
                                   const float* __restrict__ gamma, const float* __restrict__ beta,
                                   double cnt, float* __restrict__ scl, float* __restrict__ shf) {
    int nn = threadIdx.x;
    if (nn < NNODE) {
        double m = sum[nn] / cnt;
        double v = sqs[nn] / cnt - m * m;
        double inv = 1.0 / sqrt(v + 1e-5);
        double sc = (double)gamma[nn] * inv;
        scl[nn] = (float)sc;
        shf[nn] = (float)((double)beta[nn] - m * sc);
    }
}

// ---------------- persistent ChebConv K=3 + relu (NSTR layout) ----------------
__global__ void __launch_bounds__(288)
cheb_kernel(const float* __restrict__ zin, int T,
            const float* __restrict__ cw, const float* __restrict__ cb,
            float* __restrict__ out) {
    constexpr int TT  = 4;
    constexpr int STR = 68;
    extern __shared__ float smf[];
    float* Wsm = smf;
    float* bsm = Wsm + 3 * 64 * 64;
    float* Lsm = bsm + 64;
    float* Z   = Lsm + NPAD * NPAD;
    float* X1  = Z + TT * NPAD * STR;
    float* X2  = X1 + TT * NPAD * STR;

    const int tid = threadIdx.x;
    {
        const float4* w4 = reinterpret_cast<const float4*>(cw);
        float4* s4 = reinterpret_cast<float4*>(Wsm);
        for (int i = tid; i < 3 * 64 * 16; i += 288) s4[i] = w4[i];
    }
    if (tid < 64) bsm[tid] = cb[tid];
    for (int i = tid; i < NPAD * NPAD; i += 288) Lsm[i] = g_L[i];

    const int tt = tid / 72;
    const int r  = tid % 72;
    const int n0 = (r / 8) * 4;
    const int q0 = (r % 8) * 8;

    const int ntt    = (T + TT - 1) / TT;
    const int ntiles = ntt * BATCH;

    for (int tile = blockIdx.x; tile < ntiles; tile += gridDim.x) {
        const int tch = tile % ntt;
        const int b   = tile / ntt;
        const int t0  = tch * TT;

        __syncthreads();
        for (int i4 = tid; i4 < TT * NPAD * 16; i4 += 288) {
            int ti = i4 / (NPAD * 16);
            int rr = i4 % (NPAD * 16);
            int nn = rr / 16;
            int c4 = (rr % 16) << 2;
            int t = t0 + ti;
            float4 v = make_float4(0.f, 0.f, 0.f, 0.f);
            if (t < T && nn < NNODE)
                v = *reinterpret_cast<const float4*>(
                    &zin[(((size_t)b * T + t) * NSTR + nn) * CH + c4]);
            *reinterpret_cast<float4*>(&Z[(ti * NPAD + nn) * STR + c4]) = v;
        }
        __syncthreads();

        // prop1: X1 = L*Z
        {
            u64 acc[4][4];
#pragma unroll
            for (int a = 0; a < 4; a++)
#pragma unroll
                for (int p = 0; p < 4; p++) acc[a][p] = 0ull;
#pragma unroll 3
            for (int m = 0; m < NNODE; m++) {
                const u64* zr = reinterpret_cast<const u64*>(&Z[(tt * NPAD + m) * STR + q0]);
                u64 z0 = zr[0], z1 = zr[1], z2 = zr[2], z3 = zr[3];
#pragma unroll
                for (int a = 0; a < 4; a++) {
                    u64 ld = dup2(Lsm[(n0 + a) * NPAD + m]);
                    fma2(acc[a][0], z0, ld);
                    fma2(acc[a][1], z1, ld);
                    fma2(acc[a][2], z2, ld);
                    fma2(acc[a][3], z3, ld);
                }
            }
#pragma unroll
            for (int a = 0; a < 4; a++) {
                u64* xp = reinterpret_cast<u64*>(&X1[(tt * NPAD + n0 + a) * STR + q0]);
#pragma unroll
                for (int p = 0; p < 4; p++) xp[p] = acc[a][p];
            }
        }
        __syncthreads();

        // prop2: X2 = 2*(L*X1) - Z
        {
            u64 acc[4][4];
#pragma unroll
            for (int a = 0; a < 4; a++)
#pragma unroll
                for (int p = 0; p < 4; p++) acc[a][p] = 0ull;
#pragma unroll 3
            for (int m = 0; m < NNODE; m++) {
                const u64* xr = reinterpret_cast<const u64*>(&X1[(tt * NPAD + m) * STR + q0]);
                u64 x0 = xr[0], x1 = xr[1], x2 = xr[2], x3 = xr[3];
#pragma unroll
                for (int a = 0; a < 4; a++) {
                    u64 ld = dup2(Lsm[(n0 + a) * NPAD + m]);
                    fma2(acc[a][0], x0, ld);
                    fma2(acc[a][1], x1, ld);
                    fma2(acc[a][2], x2, ld);
                    fma2(acc[a][3], x3, ld);
                }
            }
#pragma unroll
            for (int a = 0; a < 4; a++) {
                int base = (tt * NPAD + n0 + a) * STR + q0;
#pragma unroll
                for (int p = 0; p < 4; p++) {
                    float alo, ahi;
                    unpk2(acc[a][p], alo, ahi);
                    X2[base + 2 * p]     = 2.f * alo - Z[base + 2 * p];
                    X2[base + 2 * p + 1] = 2.f * ahi - Z[base + 2 * p + 1];
                }
            }
        }
        __syncthreads();

        // GEMM: relu(Z*W0 + X1*W1 + X2*W2 + b)
        {
            u64 acc[4][4];
#pragma unroll
            for (int a = 0; a < 4; a++)
#pragma unroll
                for (int p = 0; p < 4; p++) acc[a][p] = 0ull;
#pragma unroll 2
            for (int c = 0; c < 64; c++) {
                const u64* w0 = reinterpret_cast<const u64*>(&Wsm[(0 * 64 + c) * 64 + q0]);
                const u64* w1 = reinterpret_cast<const u64*>(&Wsm[(1 * 64 + c) * 64 + q0]);
                const u64* w2 = reinterpret_cast<const u64*>(&Wsm[(2 * 64 + c) * 64 + q0]);
                u64 w00 = w0[0], w01 = w0[1], w02 = w0[2], w03 = w0[3];
                u64 w10 = w1[0], w11 = w1[1], w12 = w1[2], w13 = w1[3];
                u64 w20 = w2[0], w21 = w2[1], w22 = w2[2], w23 = w2[3];
#pragma unroll
                for (int a = 0; a < 4; a++) {
                    int base = (tt * NPAD + n0 + a) * STR + c;
                    u64 zd  = dup2(Z[base]);
                    u64 x1d = dup2(X1[base]);
                    u64 x2d = dup2(X2[base]);
                    fma2(acc[a][0], w00, zd);  fma2(acc[a][1], w01, zd);
                    fma2(acc[a][2], w02, zd);  fma2(acc[a][3], w03, zd);
                    fma2(acc[a][0], w10, x1d); fma2(acc[a][1], w11, x1d);
                    fma2(acc[a][2], w12, x1d); fma2(acc[a][3], w13, x1d);
                    fma2(acc[a][0], w20, x2d); fma2(acc[a][1], w21, x2d);
                    fma2(acc[a][2], w22, x2d); fma2(acc[a][3], w23, x2d);
                }
            }
            int t = t0 + tt;
            if (t < T) {
#pragma unroll
                for (int a = 0; a < 4; a++) {
                    int nn = n0 + a;
                    if (nn < NNODE) {
                        float* op = &out[(((size_t)b * T + t) * NSTR + nn) * CH + q0];
                        float v[8];
#pragma unroll
                        for (int p = 0; p < 4; p++) {
                            float alo, ahi;
                            unpk2(acc[a][p], alo, ahi);
                            v[2 * p]     = fmaxf(alo + bsm[q0 + 2 * p], 0.f);
                            v[2 * p + 1] = fmaxf(ahi + bsm[q0 + 2 * p + 1], 0.f);
                        }
                        *reinterpret_cast<float4*>(op)     = make_float4(v[0], v[1], v[2], v[3]);
                        *reinterpret_cast<float4*>(op + 4) = make_float4(v[4], v[5], v[6], v[7]);
                    }
                }
            }
        }
    }
}

// ---------------- fused BN+relu+time-mean ----------------
__global__ void timemean_kernel(const float* __restrict__ x, int T,
                                const float* __restrict__ scl, const float* __restrict__ shf) {
    const int n = blockIdx.x, b = blockIdx.y, c = threadIdx.x;
    const float sc = scl[n], sh = shf[n];
    double s = 0.0;
#pragma unroll 4
    for (int t = 0; t < T; t++) {
        float v = x[(((size_t)b * T + t) * NSTR + n) * CH + c];
        v = fmaxf(fmaf(v, sc, sh), 0.f);
        s += (double)v;
    }
    g_M[(b * NNODE + n) * CH + c] = (float)(s / (double)T);
}

// ---------------- classifier ----------------
__global__ void __launch_bounds__(256)
fc_kernel(const float* __restrict__ w1, const float* __restrict__ b1,
          const float* __restrict__ w2, const float* __restrict__ b2,
          float* __restrict__ out) {
    __shared__ float ms[NNODE * CH];
    __shared__ float h1[256];
    const int b = blockIdx.x, tid = threadIdx.x;
    for (int i = tid; i < NNODE * CH; i += 256) ms[i] = g_M[b * NNODE * CH + i];
    __syncthreads();
    double acc = (double)b1[tid];
    for (int i = 0; i < NNODE * CH; i++) acc += (double)ms[i] * (double)w1[i * 256 + tid];
    h1[tid] = fmaxf((float)acc, 0.f);
    __syncthreads();
    if (tid < 10) {
        double a2 = (double)b2[tid];
        for (int i = 0; i < 256; i++) a2 += (double)h1[i] * (double)w2[i * 10 + tid];
        out[b * 10 + tid] = (float)a2;
    }
}

// ---------------- launch ----------------
extern "C" void kernel_launch(void* const* d_in, const int* in_sizes, int n_in,
                              void* d_out, int out_size) {
    const float* x        = (const float*)d_in[0];
    const int*   ei       = (const int*)d_in[1];
    const float* s1_tc1_w = (const float*)d_in[2];
    const float* s1_tc1_b = (const float*)d_in[3];
    const float* s1_cheb_w= (const float*)d_in[4];
    const float* s1_cheb_b= (const float*)d_in[5];
    const float* s1_tc2_w = (const float*)d_in[6];
    const float* s1_tc2_b = (const float*)d_in[7];
    const float* s1_bn_g  = (const float*)d_in[8];
    const float* s1_bn_b  = (const float*)d_in[9];
    const float* s2_tc1_w = (const float*)d_in[10];
    const float* s2_tc1_b = (const float*)d_in[11];
    const float* s2_cheb_w= (const float*)d_in[12];
    const float* s2_cheb_b= (const float*)d_in[13];
    const float* s2_tc2_w = (const float*)d_in[14];
    const float* s2_tc2_b = (const float*)d_in[15];
    const float* s2_bn_g  = (const float*)d_in[16];
    const float* s2_bn_b  = (const float*)d_in[17];
    const float* fc1_w    = (const float*)d_in[18];
    const float* fc1_b    = (const float*)d_in[19];
    const float* fc2_w    = (const float*)d_in[20];
    const float* fc2_b    = (const float*)d_in[21];

    float *bufA, *bufB, *scl1, *shf1, *scl2, *shf2;
    u32 *Bw1, *Bw2, *Bw3;
    double *sum1, *sqs1, *sum2, *sqs2;
    cudaGetSymbolAddress((void**)&bufA, g_bufA);
    cudaGetSymbolAddress((void**)&bufB, g_bufB);
    cudaGetSymbolAddress((void**)&Bw1, g_Bw1);
    cudaGetSymbolAddress((void**)&Bw2, g_Bw2);
    cudaGetSymbolAddress((void**)&Bw3, g_Bw3);
    cudaGetSymbolAddress((void**)&scl1, g_scl1);
    cudaGetSymbolAddress((void**)&shf1, g_shf1);
    cudaGetSymbolAddress((void**)&scl2, g_scl2);
    cudaGetSymbolAddress((void**)&shf2, g_shf2);
    cudaGetSymbolAddress((void**)&sum1, g_sum1);
    cudaGetSymbolAddress((void**)&sqs1, g_sqs1);
    cudaGetSymbolAddress((void**)&sum2, g_sum2);
    cudaGetSymbolAddress((void**)&sqs2, g_sqs2);

    const size_t smC = (size_t)(3 * 64 * 64 + 64 + NPAD * NPAD + 3 * 4 * NPAD * 68) * sizeof(float);
    cudaFuncSetAttribute(cheb_kernel,      cudaFuncAttributeMaxDynamicSharedMemorySize, (int)smC);
    cudaFuncSetAttribute(tconv_mma_kernel, cudaFuncAttributeMaxDynamicSharedMemorySize, TC_SMEM);

    const int ne = in_sizes[1] / 2;
    const int GRID = 148;

    setup_kernel<<<1, 64>>>(ei, ne, s1_tc1_w);                                        // 0
    convert_w_kernel<<<144, 256>>>(s1_tc2_w, Bw1);                                    // 1
    convert_w_kernel<<<144, 256>>>(s2_tc1_w, Bw2);                                    // 2
    convert_w_kernel<<<144, 256>>>(s2_tc2_w, Bw3);                                    // 3

    // ---- STConv 1 ----
    tconv3_kernel<<<GRID, dim3(64, 8)>>>(x, s1_tc1_b, bufA);                          // 4: T=510
    cheb_kernel<<<GRID, 288, smC>>>(bufA, 510, s1_cheb_w, s1_cheb_b, bufB);           // 5 (profiled)
    tconv_mma_kernel<<<GRID, 256, TC_SMEM>>>(bufB, 510, Bw1, s1_tc2_b,
                                             nullptr, nullptr, 0, bufA);              // 6: T=508
    bnstats_kernel<<<dim3(NNODE, BATCH), 256>>>(bufA, 508, sum1, sqs1);               // 7
    finalize_bn_kernel<<<1, 64>>>(sum1, sqs1, s1_bn_g, s1_bn_b,
                                  (double)BATCH * 508.0 * 64.0, scl1, shf1);          // 8

    // ---- STConv 2 (BN1+relu fused into A-conversion) ----
    tconv_mma_kernel<<<GRID, 256, TC_SMEM>>>(bufA, 508, Bw2, s2_tc1_b,
                                             scl1, shf1, 1, bufB);                    // 9: T=506
    cheb_kernel<<<GRID, 288, smC>>>(bufB, 506, s2_cheb_w, s2_cheb_b, bufA);           // 10
    tconv_mma_kernel<<<GRID, 256, TC_SMEM>>>(bufA, 506, Bw3, s2_tc2_b,
                                             nullptr, nullptr, 0, bufB);              // 11: T=504
    bnstats_kernel<<<dim3(NNODE, BATCH), 256>>>(bufB, 504, sum2, sqs2);               // 12
    finalize_bn_kernel<<<1, 64>>>(sum2, sqs2, s2_bn_g, s2_bn_b,
                                  (double)BATCH * 504.0 * 64.0, scl2, shf2);          // 13

    // ---- head ----
    timemean_kernel<<<dim3(NNODE, BATCH), 64>>>(bufB, 504, scl2, shf2);               // 14
    fc_kernel<<<BATCH, 256>>>(fc1_w, fc1_b, fc2_w, fc2_b, (float*)d_out);             // 15
}

// round 6
// speedup vs baseline: 2.3503x; 1.1811x over previous
#include <cuda_runtime.h>
#include <cuda_bf16.h>
#include <math.h>

#define BATCH 32
#define NNODE 33
#define NSTR  40      // padded node stride: +1 time tap = +40 rows = 5120 B (swizzle-atom aligned)
#define NPAD  36
#define CH    64

typedef unsigned long long u64;
typedef unsigned int u32;
typedef unsigned short u16;

// ---------------- f32x2 helpers (SIMT kernels) ----------------
__device__ __forceinline__ u64 pk2(float lo, float hi) {
    u64 r;
    asm("mov.b64 %0, {%1, %2};" : "=l"(r) : "r"(__float_as_uint(lo)), "r"(__float_as_uint(hi)));
    return r;
}
__device__ __forceinline__ u64 dup2(float v) { return pk2(v, v); }
__device__ __forceinline__ void unpk2(u64 v, float& lo, float& hi) {
    u32 a, b;
    asm("mov.b64 {%0, %1}, %2;" : "=r"(a), "=r"(b) : "l"(v));
    lo = __uint_as_float(a);
    hi = __uint_as_float(b);
}
__device__ __forceinline__ void fma2(u64& d, u64 a, u64 b) {
    asm("fma.rn.f32x2 %0, %1, %2, %0;" : "+l"(d) : "l"(a), "l"(b));
}

// ---------------- mma.sync / ldmatrix helpers (arch-neutral PTX) ----------------
__device__ __forceinline__ u32 smem_u32(const void* p) {
    u32 a;
    asm("{ .reg .u64 t; cvta.to.shared.u64 t, %1; cvt.u32.u64 %0, t; }" : "=r"(a) : "l"(p));
    return a;
}
__device__ __forceinline__ void ldsm_x4(u32* r, u32 addr) {
    asm volatile("ldmatrix.sync.aligned.m8n8.x4.shared.b16 {%0,%1,%2,%3}, [%4];"
                 : "=r"(r[0]), "=r"(r[1]), "=r"(r[2]), "=r"(r[3]) : "r"(addr));
}
__device__ __forceinline__ void mma_bf16(float* c, const u32* a, u32 b0, u32 b1) {
    asm volatile("mma.sync.aligned.m16n8k16.row.col.f32.bf16.bf16.f32 "
                 "{%0,%1,%2,%3}, {%4,%5,%6,%7}, {%8,%9}, {%0,%1,%2,%3};"
                 : "+f"(c[0]), "+f"(c[1]), "+f"(c[2]), "+f"(c[3])
                 : "r"(a[0]), "r"(a[1]), "r"(a[2]), "r"(a[3]), "r"(b0), "r"(b1));
}
__device__ __forceinline__ u64 pack4bf(__nv_bfloat16 a, __nv_bfloat16 b,
                                       __nv_bfloat16 c, __nv_bfloat16 d) {
    u32 u0 = ((u32)__bfloat16_as_ushort(b) << 16) | (u32)__bfloat16_as_ushort(a);
    u32 u1 = ((u32)__bfloat16_as_ushort(d) << 16) | (u32)__bfloat16_as_ushort(c);
    return (u64)u0 | ((u64)u1 << 32);
}
__device__ __forceinline__ void bfsplit(float v, u16& h, u16& l) {
    __nv_bfloat16 hb = __float2bfloat16(v);
    h = __bfloat16_as_ushort(hb);
    l = __bfloat16_as_ushort(__float2bfloat16(v - __bfloat162float(hb)));
}

// ---------------- device scratch ----------------
#define BUF_ELEMS ((size_t)BATCH * 510 * NSTR * CH)
__device__ float g_bufA[BUF_ELEMS];
__device__ float g_bufB[BUF_ELEMS];
__device__ float g_L[NPAD * NPAD];
__device__ float g_w1a[3 * 3 * 3 * 64];
__device__ u32   g_Bw1[36864], g_Bw2[36864], g_Bw3[36864];
__device__ u32   g_Cw1[12288], g_Cw2[12288];
__device__ float g_scl1[NNODE], g_shf1[NNODE];
__device__ float g_scl2[NNODE], g_shf2[NNODE];
__device__ double g_sum1[NNODE], g_sqs1[NNODE];
__device__ double g_sum2[NNODE], g_sqs2[NNODE];
__device__ float g_M[BATCH * NNODE * CH];

// ---------------- setup ----------------
__global__ void setup_kernel(const int* __restrict__ ei, int ne, const float* __restrict__ w3) {
    int i = threadIdx.x;
    if (i < NNODE) { g_sum1[i] = 0.0; g_sqs1[i] = 0.0; g_sum2[i] = 0.0; g_sqs2[i] = 0.0; }
    for (int j = i; j < 3 * 3 * 3 * 64; j += 64) {
        int o  = j & 63;
        int k  = (j >> 6) % 3;
        int ci = (j / 192) % 3;
        int g  = j / (192 * 3);
        g_w1a[j] = w3[((g * 64 + o) * 3 + ci) * 3 + k];
    }
    if (i == 0) {
        double deg[NNODE];
        for (int k = 0; k < NNODE; k++) deg[k] = 0.0;
        for (int e = 0; e < ne; e++) deg[ei[e]] += 1.0;
        double dinv[NNODE];
        for (int k = 0; k < NNODE; k++) dinv[k] = (deg[k] > 0.0) ? (1.0 / sqrt(deg[k])) : 0.0;
        for (int k = 0; k < NPAD * NPAD; k++) g_L[k] = 0.0f;
        for (int e = 0; e < ne; e++) {
            int s = ei[e];
            int t = ei[ne + e];
            g_L[t * NPAD + s] += (float)(-dinv[s] * dinv[t]);
        }
    }
}

// ---- tconv weights -> bf16 hi/lo regions: region r=(g*3+k)*2+s, row=o, 32 ci-pair words
__global__ void convert_w_kernel(const float* __restrict__ w, u32* __restrict__ outw) {
    int i = blockIdx.x * blockDim.x + threadIdx.x;
    if (i >= 36864) return;
    int region = i >> 11;
    int rem    = i & 2047;
    int o      = rem >> 5;
    int c2     = rem & 31;
    int s  = region & 1;
    int gk = region >> 1;
    int g  = gk / 3, k = gk % 3;
    int ci0 = 2 * c2;
    float v0 = w[((g * 64 + o) * 64 + ci0) * 3 + k];
    float v1 = w[((g * 64 + o) * 64 + ci0 + 1) * 3 + k];
    u16 h0, l0, h1, l1;
    bfsplit(v0, h0, l0);
    bfsplit(v1, h1, l1);
    outw[i] = (s == 0) ? (((u32)h1 << 16) | (u32)h0) : (((u32)l1 << 16) | (u32)l0);
}

// ---- cheb weights (3,64,64)=[k][c][d] -> regions (k*2+s): row=d, 32 c-pair words; both layers
__global__ void convert_cw_kernel(const float* __restrict__ cw1, u32* __restrict__ o1,
                                  const float* __restrict__ cw2, u32* __restrict__ o2) {
    int i = blockIdx.x * blockDim.x + threadIdx.x;
    if (i >= 24576) return;
    const float* cw = (i < 12288) ? cw1 : cw2;
    u32* op = (i < 12288) ? o1 : o2;
    int j = (i < 12288) ? i : (i - 12288);
    int region = j >> 11, rem = j & 2047, d = rem >> 5, c2 = rem & 31;
    int k = region >> 1, s = region & 1, c0 = 2 * c2;
    float v0 = cw[(k * 64 + c0) * 64 + d];
    float v1 = cw[(k * 64 + c0 + 1) * 64 + d];
    u16 h0, l0, h1, l1;
    bfsplit(v0, h0, l0);
    bfsplit(v1, h1, l1);
    op[j] = (s == 0) ? (((u32)h1 << 16) | (u32)h0) : (((u32)l1 << 16) | (u32)l0);
}

// ---------------- SIMT gated tconv CI=3 (first layer), out stride NSTR ----------------
__global__ void __launch_bounds__(512)
tconv3_kernel(const float* __restrict__ xin,
              const float* __restrict__ bias,
              float* __restrict__ out) {
    constexpr int CI = 3, CT = 128, TO = 16, ST = CT + 4, HP = TO / 2;
    constexpr int Tin = 512, Tout = 510;
    __shared__ float ws[3 * CI * 3 * 64];
    __shared__ float xs[CI * ST];

    const int tid = threadIdx.y * 64 + threadIdx.x;
    const int ntch = (Tout + CT - 1) / CT;
    const int ntiles = ntch * NNODE * BATCH;

    for (int i = tid; i < 3 * CI * 3 * 64; i += 512) ws[i] = g_w1a[i];

    const int o  = threadIdx.x;
    const int tb = threadIdx.y * TO;
    const float bP = bias[o], bQ = bias[64 + o], bR = bias[128 + o];

    for (int tile = blockIdx.x; tile < ntiles; tile += gridDim.x) {
        const int tch = tile % ntch;
        const int rem = tile / ntch;
        const int n   = rem % NNODE;
        const int b   = rem / NNODE;
        const int t0  = tch * CT;

        __syncthreads();
        for (int i = tid; i < (CT + 2) * CI; i += 512) {
            int tt = i / CI, ci = i % CI;
            int t = t0 + tt;
            float v = 0.f;
            if (t < Tin) v = xin[(((size_t)b * Tin + t) * NNODE + n) * CI + ci];
            xs[ci * ST + tt] = v;
        }
        __syncthreads();

        u64 accP[3][HP];
#pragma unroll
        for (int g = 0; g < 3; g++)
#pragma unroll
            for (int p = 0; p < HP; p++) accP[g][p] = 0ull;

#pragma unroll
        for (int ci = 0; ci < CI; ci++) {
            const float* xp = &xs[ci * ST + tb];
            u64 ep[HP + 1];
#pragma unroll
            for (int p = 0; p <= HP; p++) ep[p] = *reinterpret_cast<const u64*>(xp + 2 * p);
            float xl[HP + 1], xh[HP + 1];
#pragma unroll
            for (int p = 0; p <= HP; p++) unpk2(ep[p], xl[p], xh[p]);
            u64 op[HP];
#pragma unroll
            for (int p = 0; p < HP; p++) op[p] = pk2(xh[p], xl[p + 1]);

#pragma unroll
            for (int g = 0; g < 3; g++) {
#pragma unroll
                for (int k = 0; k < 3; k++) {
                    u64 wd = dup2(ws[((g * CI + ci) * 3 + k) * 64 + o]);
                    const u64* xq = (k == 0) ? ep : (k == 1) ? op : (ep + 1);
#pragma unroll
                    for (int p = 0; p < HP; p++) fma2(accP[g][p], xq[p], wd);
                }
            }
        }

#pragma unroll
        for (int p = 0; p < HP; p++) {
            float P0, P1, Q0, Q1, R0, R1;
            unpk2(accP[0][p], P0, P1);
            unpk2(accP[1][p], Q0, Q1);
            unpk2(accP[2][p], R0, R1);
#pragma unroll
            for (int half = 0; half < 2; half++) {
                int t = t0 + tb + 2 * p + half;
                if (t < Tout) {
                    float P = (half ? P1 : P0) + bP;
                    float Q = (half ? Q1 : Q0) + bQ;
                    float R = (half ? R1 : R0) + bR;
                    float sg = 1.f / (1.f + __expf(-Q));
                    float h = fmaxf(fmaf(P, sg, R), 0.f);
                    out[(((size_t)b * Tout + t) * NSTR + n) * CH + o] = h;
                }
            }
        }
    }
}

// ---------------- mma.sync gated tconv CI=64 ----------------
#define ROWS_A 208
#define A_SPLIT_B (ROWS_A * 128)        // 26624
#define B_BYTES   (18 * 8192)           // 147456
#define OFF_B     1024
#define OFF_A     (OFF_B + B_BYTES)
#define TC_SMEM   (OFF_A + 2 * A_SPLIT_B + 1024)

__global__ void __launch_bounds__(256, 1)
tconv_mma_kernel(const float* __restrict__ xin, int Tin,
                 const u32* __restrict__ Bw,
                 const float* __restrict__ bias,
                 const float* __restrict__ scl, const float* __restrict__ shf, int mode,
                 float* __restrict__ out) {
    extern __shared__ char smraw[];
    __shared__ float sbias[192];

    const u32 sb0 = smem_u32(smraw);
    const u32 sbase = (sb0 + 1023) & ~1023u;
    char* sm = smraw + (sbase - sb0);

    const int tid = threadIdx.x;
    const int wid = tid >> 5, lane = tid & 31;
    const int Tout = Tin - 2;
    const int RowsIn = Tin * NSTR, RowsOut = Tout * NSTR;
    const int ntb = (RowsOut + 127) / 128;
    const int ntiles = ntb * BATCH;

    for (int i = tid; i < 36864; i += 256) {
        int r = i >> 11, rem = i & 2047, row = rem >> 5, c2 = rem & 31;
        u32 byte = row * 128 + c2 * 4;
        *(u32*)(sm + OFF_B + r * 8192 + (byte ^ ((byte >> 3) & 0x70))) = Bw[i];
    }
    if (tid < 192) sbias[tid] = bias[tid];
    __syncthreads();

    const int warp_m = wid & 3;
    const int o0 = (wid >> 2) * 32;

    const u32 a_row_l = lane & 15;
    const u32 a_koff  = (lane & 16) ? 16u : 0u;
    const u32 b_row_l = lane & 7;
    const u32 b_koff  = (lane & 8) ? 16u : 0u;
    const u32 b_sreg  = (lane & 16) ? 8192u : 0u;

    const int trow = lane >> 2;
    const int tcol = (lane & 3) * 2;

    for (int tile = blockIdx.x; tile < ntiles; tile += gridDim.x) {
        const int bidx = tile / ntb, tl = tile % ntb;
        const int local0 = tl * 128;
        const float* xb = xin + (size_t)bidx * RowsIn * 64;

        __syncthreads();

        for (int i4 = tid; i4 < ROWS_A * 16; i4 += 256) {
            int r = i4 >> 4, c4 = (i4 & 15) << 2;
            int il = local0 + r;
            float4 v = make_float4(0.f, 0.f, 0.f, 0.f);
            if (il < RowsIn) {
                int n = il % NSTR;
                if (n < NNODE) {
                    v = *(const float4*)(xb + (size_t)il * 64 + c4);
                    if (mode) {
                        float sc = scl[n], sh = shf[n];
                        v.x = fmaxf(fmaf(v.x, sc, sh), 0.f);
                        v.y = fmaxf(fmaf(v.y, sc, sh), 0.f);
                        v.z = fmaxf(fmaf(v.z, sc, sh), 0.f);
                        v.w = fmaxf(fmaf(v.w, sc, sh), 0.f);
                    }
                }
            }
            __nv_bfloat16 hx = __float2bfloat16(v.x), hy = __float2bfloat16(v.y);
            __nv_bfloat16 hz = __float2bfloat16(v.z), hw = __float2bfloat16(v.w);
            u32 byte = r * 128 + (c4 << 1);
            u32 sw = byte ^ ((byte >> 3) & 0x70);
            *(u64*)(sm + OFF_A + sw) = pack4bf(hx, hy, hz, hw);
            __nv_bfloat16 lx = __float2bfloat16(v.x - __bfloat162float(hx));
            __nv_bfloat16 ly = __float2bfloat16(v.y - __bfloat162float(hy));
            __nv_bfloat16 lz = __float2bfloat16(v.z - __bfloat162float(hz));
            __nv_bfloat16 lw = __float2bfloat16(v.w - __bfloat162float(hw));
            *(u64*)(sm + OFF_A + A_SPLIT_B + sw) = pack4bf(lx, ly, lz, lw);
        }
        __syncthreads();

        float acc[2][3][4][4];
#pragma unroll
        for (int h = 0; h < 2; h++)
#pragma unroll
            for (int g = 0; g < 3; g++)
#pragma unroll
                for (int ot = 0; ot < 4; ot++)
#pragma unroll
                    for (int c = 0; c < 4; c++) acc[h][g][ot][c] = 0.f;

#pragma unroll
        for (int tap = 0; tap < 3; tap++) {
#pragma unroll
            for (int kc = 0; kc < 4; kc++) {
                u32 ah[2][4], al[2][4];
#pragma unroll
                for (int h = 0; h < 2; h++) {
                    u32 rb = (u32)(tap * 40 + warp_m * 32 + h * 16) + a_row_l;
                    u32 byte = rb * 128 + (u32)(kc * 32) + a_koff;
                    u32 sw = byte ^ ((byte >> 3) & 0x70);
                    ldsm_x4(ah[h], sbase + OFF_A + sw);
                    ldsm_x4(al[h], sbase + OFF_A + A_SPLIT_B + sw);
                }
#pragma unroll
                for (int g = 0; g < 3; g++) {
                    u32 breg = sbase + OFF_B + (u32)((g * 3 + tap) * 2) * 8192 + b_sreg;
                    u32 bf[4][4];
#pragma unroll
                    for (int ot = 0; ot < 4; ot++) {
                        u32 byte = (u32)(o0 + 8 * ot + (int)b_row_l) * 128 + (u32)(kc * 32) + b_koff;
                        ldsm_x4(bf[ot], breg + (byte ^ ((byte >> 3) & 0x70)));
                    }
#pragma unroll
                    for (int ot = 0; ot < 4; ot++) {
                        mma_bf16(acc[0][g][ot], ah[0], bf[ot][0], bf[ot][1]);
                        mma_bf16(acc[1][g][ot], ah[1], bf[ot][0], bf[ot][1]);
                    }
#pragma unroll
                    for (int ot = 0; ot < 4; ot++) {
                        mma_bf16(acc[0][g][ot], al[0], bf[ot][0], bf[ot][1]);
                        mma_bf16(acc[1][g][ot], al[1], bf[ot][0], bf[ot][1]);
                    }
#pragma unroll
                    for (int ot = 0; ot < 4; ot++) {
                        mma_bf16(acc[0][g][ot], ah[0], bf[ot][2], bf[ot][3]);
                        mma_bf16(acc[1][g][ot], ah[1], bf[ot][2], bf[ot][3]);
                    }
                }
            }
        }

#pragma unroll
        for (int h = 0; h < 2; h++) {
#pragma unroll
            for (int rs = 0; rs < 2; rs++) {
                int row = warp_m * 32 + h * 16 + trow + rs * 8;
                int ol = local0 + row;
                if (ol < RowsOut) {
                    float* op = out + ((size_t)bidx * RowsOut + ol) * 64;
#pragma unroll
                    for (int ot = 0; ot < 4; ot++) {
                        int o = o0 + 8 * ot + tcol;
                        float2 hv;
#pragma unroll
                        for (int e = 0; e < 2; e++) {
                            float P = acc[h][0][ot][rs * 2 + e] + sbias[o + e];
                            float Q = acc[h][1][ot][rs * 2 + e] + sbias[64 + o + e];
                            float R = acc[h][2][ot][rs * 2 + e] + sbias[128 + o + e];
                            float sg = 1.f / (1.f + __expf(-Q));
                            float hval = fmaxf(fmaf(P, sg, R), 0.f);
                            if (e == 0) hv.x = hval; else hv.y = hval;
                        }
                        *(float2*)(op + o) = hv;
                    }
                }
            }
        }
    }
}

// ---------------- mma.sync ChebConv K=3 + relu ----------------
// Tile = 3 time steps (120 rows, NSTR layout). Props SIMT fp32; GEMM K=192 via mma bf16 hi/lo.
// A regions (128 rows x 128B each): [Zh, Zl, X1h, X1l, X2h, X2l]; W regions (64x128B): [k0h,k0l,k1h,k1l,k2h,k2l]
#define CW_OFF_W  0
#define CW_OFF_A  49152
#define CW_OFF_Z  147456
#define CW_OFF_X1 180224
#define CW_DYN    (212992 + 1024)

__global__ void __launch_bounds__(256, 1)
cheb_mma_kernel(const float* __restrict__ zin, int T,
                const u32* __restrict__ Cw, const float* __restrict__ cb,
                float* __restrict__ out) {
    extern __shared__ char smraw[];
    __shared__ float Lsm[NPAD * NPAD];
    __shared__ float sbias[64];

    const u32 sb0 = smem_u32(smraw);
    const u32 sbase = (sb0 + 1023) & ~1023u;
    char* sm = smraw + (sbase - sb0);
    float* Zf  = (float*)(sm + CW_OFF_Z);
    float* X1f = (float*)(sm + CW_OFF_X1);

    const int tid = threadIdx.x;
    const int wid = tid >> 5, lane = tid & 31;

    for (int i = tid; i < 12288; i += 256) {
        int region = i >> 11, rem = i & 2047, row = rem >> 5, c2 = rem & 31;
        u32 byte = row * 128 + c2 * 4;
        *(u32*)(sm + CW_OFF_W + region * 8192 + (byte ^ ((byte >> 3) & 0x70))) = Cw[i];
    }
    for (int i = tid; i < NPAD * NPAD; i += 256) Lsm[i] = g_L[i];
    if (tid < 64) sbias[tid] = cb[tid];
    __syncthreads();

    const int ntt = (T + 2) / 3;
    const int ntiles = ntt * BATCH;

    const int warp_m = wid & 3;
    const int o0 = (wid >> 2) * 32;
    const u32 a_row_l = lane & 15;
    const u32 a_koff  = (lane & 16) ? 16u : 0u;
    const u32 b_row_l = lane & 7;
    const u32 b_koff  = (lane & 8) ? 16u : 0u;
    const u32 b_sreg  = (lane & 16) ? 8192u : 0u;
    const int trow = lane >> 2, tcol = (lane & 3) * 2;

    const int cch = tid & 63;   // channel for props
    const int ng  = tid >> 6;   // node group (0..3), 9 nodes each

    for (int tile = blockIdx.x; tile < ntiles; tile += gridDim.x) {
        const int b  = tile / ntt;
        const int t0 = (tile % ntt) * 3;
        const size_t bbase = ((size_t)b * T + t0) * NSTR;

        __syncthreads();

        // ---- Z fill: 120 rows -> Zf (f32) + A-Z (bf16 hi/lo) ----
        for (int i4 = tid; i4 < 120 * 16; i4 += 256) {
            int r = i4 >> 4, c4 = (i4 & 15) << 2;
            float4 v = *(const float4*)(zin + (bbase + r) * 64 + c4);
            *(float4*)(Zf + r * 64 + c4) = v;
            __nv_bfloat16 hx = __float2bfloat16(v.x), hy = __float2bfloat16(v.y);
            __nv_bfloat16 hz = __float2bfloat16(v.z), hw = __float2bfloat16(v.w);
            u32 byte = r * 128 + (c4 << 1);
            u32 sw = byte ^ ((byte >> 3) & 0x70);
            *(u64*)(sm + CW_OFF_A + sw) = pack4bf(hx, hy, hz, hw);
            __nv_bfloat16 lx = __float2bfloat16(v.x - __bfloat162float(hx));
            __nv_bfloat16 ly = __float2bfloat16(v.y - __bfloat162float(hy));
            __nv_bfloat16 lz = __float2bfloat16(v.z - __bfloat162float(hz));
            __nv_bfloat16 lw = __float2bfloat16(v.w - __bfloat162float(hw));
            *(u64*)(sm + CW_OFF_A + 16384 + sw) = pack4bf(lx, ly, lz, lw);
        }
        __syncthreads();

        // ---- prop1: X1 = L * Z ----
#pragma unroll
        for (int t = 0; t < 3; t++) {
            float acc[9];
#pragma unroll
            for (int j = 0; j < 9; j++) acc[j] = 0.f;
            for (int m = 0; m < NNODE; m++) {
                float zv = Zf[(t * 40 + m) * 64 + cch];
#pragma unroll
                for (int j = 0; j < 9; j++)
                    acc[j] = fmaf(Lsm[(ng * 9 + j) * NPAD + m], zv, acc[j]);
            }
#pragma unroll
            for (int j = 0; j < 9; j++) {
                int r = t * 40 + ng * 9 + j;
                X1f[r * 64 + cch] = acc[j];
                u16 h, l;
                bfsplit(acc[j], h, l);
                u32 byte = r * 128 + cch * 2;
                u32 sw = byte ^ ((byte >> 3) & 0x70);
                *(u16*)(sm + CW_OFF_A + 32768 + sw) = h;
                *(u16*)(sm + CW_OFF_A + 49152 + sw) = l;
            }
        }
        __syncthreads();

        // ---- prop2: X2 = 2*(L * X1) - Z ----
#pragma unroll
        for (int t = 0; t < 3; t++) {
            float acc[9];
#pragma unroll
            for (int j = 0; j < 9; j++) acc[j] = 0.f;
            for (int m = 0; m < NNODE; m++) {
                float xv = X1f[(t * 40 + m) * 64 + cch];
#pragma unroll
                for (int j = 0; j < 9; j++)
                    acc[j] = fmaf(Lsm[(ng * 9 + j) * NPAD + m], xv, acc[j]);
            }
#pragma unroll
            for (int j = 0; j < 9; j++) {
                int r = t * 40 + ng * 9 + j;
                float v = 2.f * acc[j] - Zf[r * 64 + cch];
                u16 h, l;
                bfsplit(v, h, l);
                u32 byte = r * 128 + cch * 2;
                u32 sw = byte ^ ((byte >> 3) & 0x70);
                *(u16*)(sm + CW_OFF_A + 65536 + sw) = h;
                *(u16*)(sm + CW_OFF_A + 81920 + sw) = l;
            }
        }
        __syncthreads();

        // ---- GEMM: O = relu([Z|X1|X2] * W + bias), M=128, N=64, K=192 ----
        float acc[2][4][4];
#pragma unroll
        for (int h = 0; h < 2; h++)
#pragma unroll
            for (int ot = 0; ot < 4; ot++)
#pragma unroll
                for (int c = 0; c < 4; c++) acc[h][ot][c] = 0.f;

#pragma unroll
        for (int chunk = 0; chunk < 3; chunk++) {
            u32 aHiBase = CW_OFF_A + (u32)chunk * 32768u;
            u32 breg = sbase + CW_OFF_W + (u32)chunk * 16384u + b_sreg;
#pragma unroll
            for (int kc = 0; kc < 4; kc++) {
                u32 ah[2][4], al[2][4];
#pragma unroll
                for (int h = 0; h < 2; h++) {
                    u32 rb = (u32)(warp_m * 32 + h * 16) + a_row_l;
                    u32 byte = rb * 128 + (u32)(kc * 32) + a_koff;
                    u32 sw = byte ^ ((byte >> 3) & 0x70);
                    ldsm_x4(ah[h], sbase + aHiBase + sw);
                    ldsm_x4(al[h], sbase + aHiBase + 16384u + sw);
                }
                u32 bf[4][4];
#pragma unroll
                for (int ot = 0; ot < 4; ot++) {
                    u32 byte = (u32)(o0 + 8 * ot + (int)b_row_l) * 128 + (u32)(kc * 32) + b_koff;
                    ldsm_x4(bf[ot], breg + (byte ^ ((byte >> 3) & 0x70)));
                }
#pragma unroll
                for (int ot = 0; ot < 4; ot++) {
                    mma_bf16(acc[0][ot], ah[0], bf[ot][0], bf[ot][1]);
                    mma_bf16(acc[1][ot], ah[1], bf[ot][0], bf[ot][1]);
                }
#pragma unroll
                for (int ot = 0; ot < 4; ot++) {
                    mma_bf16(acc[0][ot], al[0], bf[ot][0], bf[ot][1]);
                    mma_bf16(acc[1][ot], al[1], bf[ot][0], bf[ot][1]);
                }
#pragma unroll
                for (int ot = 0; ot < 4; ot++) {
                    mma_bf16(acc[0][ot], ah[0], bf[ot][2], bf[ot][3]);
                    mma_bf16(acc[1][ot], ah[1], bf[ot][2], bf[ot][3]);
                }
            }
        }

        // ---- epilogue: relu(acc + bias), masked store ----
#pragma unroll
        for (int h = 0; h < 2; h++) {
#pragma unroll
            for (int rs = 0; rs < 2; rs++) {
                int r = warp_m * 32 + h * 16 + trow + rs * 8;
                if (r < 120) {
                    int n = r % 40;
                    int t = t0 + r / 40;
                    if (n < NNODE && t < T) {
                        float* op = out + (bbase + r) * 64;
#pragma unroll
                        for (int ot = 0; ot < 4; ot++) {
                            int o = o0 + 8 * ot + tcol;
                            float2 hv;
                            hv.x = fmaxf(acc[h][ot][rs * 2 + 0] + sbias[o + 0], 0.f);
                            hv.y = fmaxf(acc[h][ot][rs * 2 + 1] + sbias[o + 1], 0.f);
                            *(float2*)(op + o) = hv;
                        }
                    }
                }
            }
        }
    }
}

// ---------------- BN stats ----------------
__global__ void __launch_bounds__(256)
bnstats_kernel(const float* __restrict__ x, int T,
               double* __restrict__ bnsum, double* __restrict__ bnsqs) {
    const int n = blockIdx.x, b = blockIdx.y, tid = threadIdx.x;
    const float* xp = x + ((size_t)b * T * NSTR + n) * 64;
    double s = 0.0, q = 0.0;
    for (int i = tid; i < T * 16; i += 256) {
        int t = i >> 4, c4 = (i & 15) << 2;
        float4 v = *(const float4*)(xp + (size_t)t * NSTR * 64 + c4);
        s += (double)v.x + (double)v.y + (double)v.z + (double)v.w;
        q += (double)v.x * v.x + (double)v.y * v.y + (double)v.z * v.z + (double)v.w * v.w;
    }
    __shared__ double r1[256], r2[256];
    r1[tid] = s; r2[tid] = q;
    __syncthreads();
    for (int st = 128; st > 0; st >>= 1) {
        if (tid < st) { r1[tid] += r1[tid + st]; r2[tid] += r2[tid + st]; }
        __syncthreads();
    }
    if (tid == 0) {
        atomicAdd(&bnsum[n], r1[0]);
        atomicAdd(&bnsqs[n], r2[0]);
    }
}

// ---------------- BN finalize ----------------
__global__ void finalize_bn_kernel(const double* __restrict__ sum, const double* __restrict__ sqs,
                                   const float* __restrict__ gamma, const float* __restrict__ beta,
                                   double cnt, float* __restrict__ scl, float* __restrict__ shf) {
    int nn = threadIdx.x;
    if (nn < NNODE) {
        double m = sum[nn] / cnt;
        double v = sqs[nn] / cnt - m * m;
        double inv = 1.0 / sqrt(v + 1e-5);
        double sc = (double)gamma[nn] * inv;
        scl[nn] = (float)sc;
        shf[nn] = (float)((double)beta[nn] - m * sc);
    }
}

// ---------------- fused BN+relu+time-mean ----------------
__global__ void timemean_kernel(const float* __restrict__ x, int T,
                                const float* __restrict__ scl, const float* __restrict__ shf) {
    const int n = blockIdx.x, b = blockIdx.y, c = threadIdx.x;
    const float sc = scl[n], sh = shf[n];
    double s = 0.0;
#pragma unroll 4
    for (int t = 0; t < T; t++) {
        float v = x[(((size_t)b * T + t) * NSTR + n) * CH + c];
        v = fmaxf(fmaf(v, sc, sh), 0.f);
        s += (double)v;
    }
    g_M[(b * NNODE + n) * CH + c] = (float)(s / (double)T);
}

// ---------------- classifier ----------------
__global__ void __launch_bounds__(256)
fc_kernel(const float* __restrict__ w1, const float* __restrict__ b1,
          const float* __restrict__ w2, const float* __restrict__ b2,
          float* __restrict__ out) {
    __shared__ float ms[NNODE * CH];
    __shared__ float h1[256];
    const int b = blockIdx.x, tid = threadIdx.x;
    for (int i = tid; i < NNODE * CH; i += 256) ms[i] = g_M[b * NNODE * CH + i];
    __syncthreads();
    double acc = (double)b1[tid];
    for (int i = 0; i < NNODE * CH; i++) acc += (double)ms[i] * (double)w1[i * 256 + tid];
    h1[tid] = fmaxf((float)acc, 0.f);
    __syncthreads();
    if (tid < 10) {
        double a2 = (double)b2[tid];
        for (int i = 0; i < 256; i++) a2 += (double)h1[i] * (double)w2[i * 10 + tid];
        out[b * 10 + tid] = (float)a2;
    }
}

// ---------------- launch ----------------
extern "C" void kernel_launch(void* const* d_in, const int* in_sizes, int n_in,
                              void* d_out, int out_size) {
    const float* x        = (const float*)d_in[0];
    const int*   ei       = (const int*)d_in[1];
    const float* s1_tc1_w = (const float*)d_in[2];
    const float* s1_tc1_b = (const float*)d_in[3];
    const float* s1_cheb_w= (const float*)d_in[4];
    const float* s1_cheb_b= (const float*)d_in[5];
    const float* s1_tc2_w = (const float*)d_in[6];
    const float* s1_tc2_b = (const float*)d_in[7];
    const float* s1_bn_g  = (const float*)d_in[8];
    const float* s1_bn_b  = (const float*)d_in[9];
    const float* s2_tc1_w = (const float*)d_in[10];
    const float* s2_tc1_b = (const float*)d_in[11];
    const float* s2_cheb_w= (const float*)d_in[12];
    const float* s2_cheb_b= (const float*)d_in[13];
    const float* s2_tc2_w = (const float*)d_in[14];
    const float* s2_tc2_b = (const float*)d_in[15];
    const float* s2_bn_g  = (const float*)d_in[16];
    const float* s2_bn_b  = (const float*)d_in[17];
    const float* fc1_w    = (const float*)d_in[18];
    const float* fc1_b    = (const float*)d_in[19];
    const float* fc2_w    = (const float*)d_in[20];
    const float* fc2_b    = (const float*)d_in[21];

    float *bufA, *bufB, *scl1, *shf1, *scl2, *shf2;
    u32 *Bw1, *Bw2, *Bw3, *Cw1, *Cw2;
    double *sum1, *sqs1, *sum2, *sqs2;
    cudaGetSymbolAddress((void**)&bufA, g_bufA);
    cudaGetSymbolAddress((void**)&bufB, g_bufB);
    cudaGetSymbolAddress((void**)&Bw1, g_Bw1);
    cudaGetSymbolAddress((void**)&Bw2, g_Bw2);
    cudaGetSymbolAddress((void**)&Bw3, g_Bw3);
    cudaGetSymbolAddress((void**)&Cw1, g_Cw1);
    cudaGetSymbolAddress((void**)&Cw2, g_Cw2);
    cudaGetSymbolAddress((void**)&scl1, g_scl1);
    cudaGetSymbolAddress((void**)&shf1, g_shf1);
    cudaGetSymbolAddress((void**)&scl2, g_scl2);
    cudaGetSymbolAddress((void**)&shf2, g_shf2);
    cudaGetSymbolAddress((void**)&sum1, g_sum1);
    cudaGetSymbolAddress((void**)&sqs1, g_sqs1);
    cudaGetSymbolAddress((void**)&sum2, g_sum2);
    cudaGetSymbolAddress((void**)&sqs2, g_sqs2);

    cudaFuncSetAttribute(tconv_mma_kernel, cudaFuncAttributeMaxDynamicSharedMemorySize, TC_SMEM);
    cudaFuncSetAttribute(cheb_mma_kernel,  cudaFuncAttributeMaxDynamicSharedMemorySize, CW_DYN);

    const int ne = in_sizes[1] / 2;
    const int GRID = 148;

    setup_kernel<<<1, 64>>>(ei, ne, s1_tc1_w);                                        // 0
    convert_w_kernel<<<144, 256>>>(s1_tc2_w, Bw1);                                    // 1
    convert_w_kernel<<<144, 256>>>(s2_tc1_w, Bw2);                                    // 2
    convert_w_kernel<<<144, 256>>>(s2_tc2_w, Bw3);                                    // 3
    convert_cw_kernel<<<96, 256>>>(s1_cheb_w, Cw1, s2_cheb_w, Cw2);                   // 4

    // ---- STConv 1 ----
    tconv3_kernel<<<GRID, dim3(64, 8)>>>(x, s1_tc1_b, bufA);                          // 5: T=510
    cheb_mma_kernel<<<GRID, 256, CW_DYN>>>(bufA, 510, Cw1, s1_cheb_b, bufB);          // 6
    tconv_mma_kernel<<<GRID, 256, TC_SMEM>>>(bufB, 510, Bw1, s1_tc2_b,
                                             nullptr, nullptr, 0, bufA);              // 7: T=508
    bnstats_kernel<<<dim3(NNODE, BATCH), 256>>>(bufA, 508, sum1, sqs1);               // 8
    finalize_bn_kernel<<<1, 64>>>(sum1, sqs1, s1_bn_g, s1_bn_b,
                                  (double)BATCH * 508.0 * 64.0, scl1, shf1);          // 9

    // ---- STConv 2 (BN1+relu fused into A-conversion) ----
    tconv_mma_kernel<<<GRID, 256, TC_SMEM>>>(bufA, 508, Bw2, s2_tc1_b,
                                             scl1, shf1, 1, bufB);                    // 10: T=506
    cheb_mma_kernel<<<GRID, 256, CW_DYN>>>(bufB, 506, Cw2, s2_cheb_b, bufA);          // 11
    tconv_mma_kernel<<<GRID, 256, TC_SMEM>>>(bufA, 506, Bw3, s2_tc2_b,
                                             nullptr, nullptr, 0, bufB);              // 12: T=504
    bnstats_kernel<<<dim3(NNODE, BATCH), 256>>>(bufB, 504, sum2, sqs2);               // 13
    finalize_bn_kernel<<<1, 64>>>(sum2, sqs2, s2_bn_g, s2_bn_b,
                                  (double)BATCH * 504.0 * 64.0, scl2, shf2);          // 14

    // ---- head ----
    timemean_kernel<<<dim3(NNODE, BATCH), 64>>>(bufB, 504, scl2, shf2);               // 15
    fc_kernel<<<BATCH, 256>>>(fc1_w, fc1_b, fc2_w, fc2_b, (float*)d_out);             // 16
}

// round 7
// speedup vs baseline: 2.3731x; 1.0097x over previous
#include <cuda_runtime.h>
#include <cuda_bf16.h>
#include <math.h>

#define BATCH 32
#define NNODE 33
#define NSTR  40      // padded node stride: +1 time tap = +40 rows (swizzle-atom aligned)
#define NPAD  36
#define CH    64

typedef unsigned long long u64;
typedef unsigned int u32;
typedef unsigned short u16;

// ---------------- f32x2 helpers ----------------
__device__ __forceinline__ u64 pk2(float lo, float hi) {
    u64 r;
    asm("mov.b64 %0, {%1, %2};" : "=l"(r) : "r"(__float_as_uint(lo)), "r"(__float_as_uint(hi)));
    return r;
}
__device__ __forceinline__ u64 dup2(float v) { return pk2(v, v); }
__device__ __forceinline__ void unpk2(u64 v, float& lo, float& hi) {
    u32 a, b;
    asm("mov.b64 {%0, %1}, %2;" : "=r"(a), "=r"(b) : "l"(v));
    lo = __uint_as_float(a);
    hi = __uint_as_float(b);
}
__device__ __forceinline__ void fma2(u64& d, u64 a, u64 b) {
    asm("fma.rn.f32x2 %0, %1, %2, %0;" : "+l"(d) : "l"(a), "l"(b));
}

// ---------------- mma.sync / ldmatrix helpers ----------------
__device__ __forceinline__ u32 smem_u32(const void* p) {
    u32 a;
    asm("{ .reg .u64 t; cvta.to.shared.u64 t, %1; cvt.u32.u64 %0, t; }" : "=r"(a) : "l"(p));
    return a;
}
__device__ __forceinline__ void ldsm_x4(u32* r, u32 addr) {
    asm volatile("ldmatrix.sync.aligned.m8n8.x4.shared.b16 {%0,%1,%2,%3}, [%4];"
                 : "=r"(r[0]), "=r"(r[1]), "=r"(r[2]), "=r"(r[3]) : "r"(addr));
}
__device__ __forceinline__ void mma_bf16(float* c, const u32* a, u32 b0, u32 b1) {
    asm volatile("mma.sync.aligned.m16n8k16.row.col.f32.bf16.bf16.f32 "
                 "{%0,%1,%2,%3}, {%4,%5,%6,%7}, {%8,%9}, {%0,%1,%2,%3};"
                 : "+f"(c[0]), "+f"(c[1]), "+f"(c[2]), "+f"(c[3])
                 : "r"(a[0]), "r"(a[1]), "r"(a[2]), "r"(a[3]), "r"(b0), "r"(b1));
}
__device__ __forceinline__ u64 pack4bf(__nv_bfloat16 a, __nv_bfloat16 b,
                                       __nv_bfloat16 c, __nv_bfloat16 d) {
    u32 u0 = ((u32)__bfloat16_as_ushort(b) << 16) | (u32)__bfloat16_as_ushort(a);
    u32 u1 = ((u32)__bfloat16_as_ushort(d) << 16) | (u32)__bfloat16_as_ushort(c);
    return (u64)u0 | ((u64)u1 << 32);
}
__device__ __forceinline__ void bfsplit(float v, u16& h, u16& l) {
    __nv_bfloat16 hb = __float2bfloat16(v);
    h = __bfloat16_as_ushort(hb);
    l = __bfloat16_as_ushort(__float2bfloat16(v - __bfloat162float(hb)));
}

// ---------------- device scratch ----------------
#define BUF_ELEMS ((size_t)BATCH * 510 * NSTR * CH)
__device__ float g_bufA[BUF_ELEMS];
__device__ float g_bufB[BUF_ELEMS];
__device__ float g_L[NPAD * NPAD];
__device__ float g_L2[NPAD * NPAD];
__device__ float g_w1a[3 * 3 * 3 * 64];
__device__ u32   g_Bw1[36864], g_Bw2[36864], g_Bw3[36864];
__device__ u32   g_Cw1[12288], g_Cw2[12288];     // Veff hi/lo
__device__ float g_scl1[NNODE], g_shf1[NNODE];
__device__ float g_scl2[NNODE], g_shf2[NNODE];
__device__ double g_sum1[NNODE], g_sqs1[NNODE];
__device__ double g_sum2[NNODE], g_sqs2[NNODE];
__device__ float g_M[BATCH * NNODE * CH];

// ---------------- setup: BN acc zero + tconv3 reorder + L and L^2 ----------------
__global__ void setup_kernel(const int* __restrict__ ei, int ne, const float* __restrict__ w3) {
    __shared__ float sL[NPAD * NPAD];
    int i = threadIdx.x;
    if (i < NNODE) { g_sum1[i] = 0.0; g_sqs1[i] = 0.0; g_sum2[i] = 0.0; g_sqs2[i] = 0.0; }
    for (int j = i; j < 3 * 3 * 3 * 64; j += 64) {
        int o  = j & 63;
        int k  = (j >> 6) % 3;
        int ci = (j / 192) % 3;
        int g  = j / (192 * 3);
        g_w1a[j] = w3[((g * 64 + o) * 3 + ci) * 3 + k];
    }
    if (i == 0) {
        double deg[NNODE];
        for (int k = 0; k < NNODE; k++) deg[k] = 0.0;
        for (int e = 0; e < ne; e++) deg[ei[e]] += 1.0;
        double dinv[NNODE];
        for (int k = 0; k < NNODE; k++) dinv[k] = (deg[k] > 0.0) ? (1.0 / sqrt(deg[k])) : 0.0;
        for (int k = 0; k < NPAD * NPAD; k++) sL[k] = 0.0f;
        for (int e = 0; e < ne; e++) {
            int s = ei[e];
            int t = ei[ne + e];
            sL[t * NPAD + s] += (float)(-dinv[s] * dinv[t]);
        }
        for (int k = 0; k < NPAD * NPAD; k++) g_L[k] = sL[k];
    }
    __syncthreads();
    for (int idx = i; idx < NPAD * NPAD; idx += 64) {
        int r = idx / NPAD, c = idx % NPAD;
        float s = 0.f;
        for (int m = 0; m < NPAD; m++) s = fmaf(sL[r * NPAD + m], sL[m * NPAD + c], s);
        g_L2[idx] = s;
    }
}

// ---- tconv weights -> bf16 hi/lo regions ----
__global__ void convert_w_kernel(const float* __restrict__ w, u32* __restrict__ outw) {
    int i = blockIdx.x * blockDim.x + threadIdx.x;
    if (i >= 36864) return;
    int region = i >> 11;
    int rem    = i & 2047;
    int o      = rem >> 5;
    int c2     = rem & 31;
    int s  = region & 1;
    int gk = region >> 1;
    int g  = gk / 3, k = gk % 3;
    int ci0 = 2 * c2;
    float v0 = w[((g * 64 + o) * 64 + ci0) * 3 + k];
    float v1 = w[((g * 64 + o) * 64 + ci0 + 1) * 3 + k];
    u16 h0, l0, h1, l1;
    bfsplit(v0, h0, l0);
    bfsplit(v1, h1, l1);
    outw[i] = (s == 0) ? (((u32)h1 << 16) | (u32)h0) : (((u32)l1 << 16) | (u32)l0);
}

// ---- cheb weights -> Veff = [W0-W2, W1, 2*W2], bf16 hi/lo regions ----
__device__ __forceinline__ float veff(const float* cw, int k, int c, int d) {
    if (k == 0) return cw[(0 * 64 + c) * 64 + d] - cw[(2 * 64 + c) * 64 + d];
    if (k == 1) return cw[(1 * 64 + c) * 64 + d];
    return 2.f * cw[(2 * 64 + c) * 64 + d];
}
__global__ void convert_cw_kernel(const float* __restrict__ cw1, u32* __restrict__ o1,
                                  const float* __restrict__ cw2, u32* __restrict__ o2) {
    int i = blockIdx.x * blockDim.x + threadIdx.x;
    if (i >= 24576) return;
    const float* cw = (i < 12288) ? cw1 : cw2;
    u32* op = (i < 12288) ? o1 : o2;
    int j = (i < 12288) ? i : (i - 12288);
    int region = j >> 11, rem = j & 2047, d = rem >> 5, c2 = rem & 31;
    int k = region >> 1, s = region & 1, c0 = 2 * c2;
    float v0 = veff(cw, k, c0, d);
    float v1 = veff(cw, k, c0 + 1, d);
    u16 h0, l0, h1, l1;
    bfsplit(v0, h0, l0);
    bfsplit(v1, h1, l1);
    op[j] = (s == 0) ? (((u32)h1 << 16) | (u32)h0) : (((u32)l1 << 16) | (u32)l0);
}

// ---------------- SIMT gated tconv CI=3 (first layer) ----------------
__global__ void __launch_bounds__(512)
tconv3_kernel(const float* __restrict__ xin,
              const float* __restrict__ bias,
              float* __restrict__ out) {
    constexpr int CI = 3, CT = 128, TO = 16, ST = CT + 4, HP = TO / 2;
    constexpr int Tin = 512, Tout = 510;
    __shared__ float ws[3 * CI * 3 * 64];
    __shared__ float xs[CI * ST];

    const int tid = threadIdx.y * 64 + threadIdx.x;
    const int ntch = (Tout + CT - 1) / CT;
    const int ntiles = ntch * NNODE * BATCH;

    for (int i = tid; i < 3 * CI * 3 * 64; i += 512) ws[i] = g_w1a[i];

    const int o  = threadIdx.x;
    const int tb = threadIdx.y * TO;
    const float bP = bias[o], bQ = bias[64 + o], bR = bias[128 + o];

    for (int tile = blockIdx.x; tile < ntiles; tile += gridDim.x) {
        const int tch = tile % ntch;
        const int rem = tile / ntch;
        const int n   = rem % NNODE;
        const int b   = rem / NNODE;
        const int t0  = tch * CT;

        __syncthreads();
        for (int i = tid; i < (CT + 2) * CI; i += 512) {
            int tt = i / CI, ci = i % CI;
            int t = t0 + tt;
            float v = 0.f;
            if (t < Tin) v = xin[(((size_t)b * Tin + t) * NNODE + n) * CI + ci];
            xs[ci * ST + tt] = v;
        }
        __syncthreads();

        u64 accP[3][HP];
#pragma unroll
        for (int g = 0; g < 3; g++)
#pragma unroll
            for (int p = 0; p < HP; p++) accP[g][p] = 0ull;

#pragma unroll
        for (int ci = 0; ci < CI; ci++) {
            const float* xp = &xs[ci * ST + tb];
            u64 ep[HP + 1];
#pragma unroll
            for (int p = 0; p <= HP; p++) ep[p] = *reinterpret_cast<const u64*>(xp + 2 * p);
            float xl[HP + 1], xh[HP + 1];
#pragma unroll
            for (int p = 0; p <= HP; p++) unpk2(ep[p], xl[p], xh[p]);
            u64 op[HP];
#pragma unroll
            for (int p = 0; p < HP; p++) op[p] = pk2(xh[p], xl[p + 1]);

#pragma unroll
            for (int g = 0; g < 3; g++) {
#pragma unroll
                for (int k = 0; k < 3; k++) {
                    u64 wd = dup2(ws[((g * CI + ci) * 3 + k) * 64 + o]);
                    const u64* xq = (k == 0) ? ep : (k == 1) ? op : (ep + 1);
#pragma unroll
                    for (int p = 0; p < HP; p++) fma2(accP[g][p], xq[p], wd);
                }
            }
        }

#pragma unroll
        for (int p = 0; p < HP; p++) {
            float P0, P1, Q0, Q1, R0, R1;
            unpk2(accP[0][p], P0, P1);
            unpk2(accP[1][p], Q0, Q1);
            unpk2(accP[2][p], R0, R1);
#pragma unroll
            for (int half = 0; half < 2; half++) {
                int t = t0 + tb + 2 * p + half;
                if (t < Tout) {
                    float P = (half ? P1 : P0) + bP;
                    float Q = (half ? Q1 : Q0) + bQ;
                    float R = (half ? R1 : R0) + bR;
                    float sg = 1.f / (1.f + __expf(-Q));
                    float h = fmaxf(fmaf(P, sg, R), 0.f);
                    out[(((size_t)b * Tout + t) * NSTR + n) * CH + o] = h;
                }
            }
        }
    }
}

// ---------------- mma.sync gated tconv CI=64 ----------------
#define ROWS_A 208
#define A_SPLIT_B (ROWS_A * 128)
#define B_BYTES   (18 * 8192)
#define OFF_B     1024
#define OFF_A     (OFF_B + B_BYTES)
#define TC_SMEM   (OFF_A + 2 * A_SPLIT_B + 1024)

__global__ void __launch_bounds__(256, 1)
tconv_mma_kernel(const float* __restrict__ xin, int Tin,
                 const u32* __restrict__ Bw,
                 const float* __restrict__ bias,
                 const float* __restrict__ scl, const float* __restrict__ shf, int mode,
                 float* __restrict__ out) {
    extern __shared__ char smraw[];
    __shared__ float sbias[192];

    const u32 sb0 = smem_u32(smraw);
    const u32 sbase = (sb0 + 1023) & ~1023u;
    char* sm = smraw + (sbase - sb0);

    const int tid = threadIdx.x;
    const int wid = tid >> 5, lane = tid & 31;
    const int Tout = Tin - 2;
    const int RowsIn = Tin * NSTR, RowsOut = Tout * NSTR;
    const int ntb = (RowsOut + 127) / 128;
    const int ntiles = ntb * BATCH;

    for (int i = tid; i < 36864; i += 256) {
        int r = i >> 11, rem = i & 2047, row = rem >> 5, c2 = rem & 31;
        u32 byte = row * 128 + c2 * 4;
        *(u32*)(sm + OFF_B + r * 8192 + (byte ^ ((byte >> 3) & 0x70))) = Bw[i];
    }
    if (tid < 192) sbias[tid] = bias[tid];
    __syncthreads();

    const int warp_m = wid & 3;
    const int o0 = (wid >> 2) * 32;

    const u32 a_row_l = lane & 15;
    const u32 a_koff  = (lane & 16) ? 16u : 0u;
    const u32 b_row_l = lane & 7;
    const u32 b_koff  = (lane & 8) ? 16u : 0u;
    const u32 b_sreg  = (lane & 16) ? 8192u : 0u;

    const int trow = lane >> 2;
    const int tcol = (lane & 3) * 2;

    for (int tile = blockIdx.x; tile < ntiles; tile += gridDim.x) {
        const int bidx = tile / ntb, tl = tile % ntb;
        const int local0 = tl * 128;
        const float* xb = xin + (size_t)bidx * RowsIn * 64;

        __syncthreads();

        for (int i4 = tid; i4 < ROWS_A * 16; i4 += 256) {
            int r = i4 >> 4, c4 = (i4 & 15) << 2;
            int il = local0 + r;
            float4 v = make_float4(0.f, 0.f, 0.f, 0.f);
            if (il < RowsIn) {
                int n = il % NSTR;
                if (n < NNODE) {
                    v = *(const float4*)(xb + (size_t)il * 64 + c4);
                    if (mode) {
                        float sc = scl[n], sh = shf[n];
                        v.x = fmaxf(fmaf(v.x, sc, sh), 0.f);
                        v.y = fmaxf(fmaf(v.y, sc, sh), 0.f);
                        v.z = fmaxf(fmaf(v.z, sc, sh), 0.f);
                        v.w = fmaxf(fmaf(v.w, sc, sh), 0.f);
                    }
                }
            }
            __nv_bfloat16 hx = __float2bfloat16(v.x), hy = __float2bfloat16(v.y);
            __nv_bfloat16 hz = __float2bfloat16(v.z), hw = __float2bfloat16(v.w);
            u32 byte = r * 128 + (c4 << 1);
            u32 sw = byte ^ ((byte >> 3) & 0x70);
            *(u64*)(sm + OFF_A + sw) = pack4bf(hx, hy, hz, hw);
            __nv_bfloat16 lx = __float2bfloat16(v.x - __bfloat162float(hx));
            __nv_bfloat16 ly = __float2bfloat16(v.y - __bfloat162float(hy));
            __nv_bfloat16 lz = __float2bfloat16(v.z - __bfloat162float(hz));
            __nv_bfloat16 lw = __float2bfloat16(v.w - __bfloat162float(hw));
            *(u64*)(sm + OFF_A + A_SPLIT_B + sw) = pack4bf(lx, ly, lz, lw);
        }
        __syncthreads();

        float acc[2][3][4][4];
#pragma unroll
        for (int h = 0; h < 2; h++)
#pragma unroll
            for (int g = 0; g < 3; g++)
#pragma unroll
                for (int ot = 0; ot < 4; ot++)
#pragma unroll
                    for (int c = 0; c < 4; c++) acc[h][g][ot][c] = 0.f;

#pragma unroll
        for (int tap = 0; tap < 3; tap++) {
#pragma unroll
            for (int kc = 0; kc < 4; kc++) {
                u32 ah[2][4], al[2][4];
#pragma unroll
                for (int h = 0; h < 2; h++) {
                    u32 rb = (u32)(tap * 40 + warp_m * 32 + h * 16) + a_row_l;
                    u32 byte = rb * 128 + (u32)(kc * 32) + a_koff;
                    u32 sw = byte ^ ((byte >> 3) & 0x70);
                    ldsm_x4(ah[h], sbase + OFF_A + sw);
                    ldsm_x4(al[h], sbase + OFF_A + A_SPLIT_B + sw);
                }
#pragma unroll
                for (int g = 0; g < 3; g++) {
                    u32 breg = sbase + OFF_B + (u32)((g * 3 + tap) * 2) * 8192 + b_sreg;
                    u32 bf[4][4];
#pragma unroll
                    for (int ot = 0; ot < 4; ot++) {
                        u32 byte = (u32)(o0 + 8 * ot + (int)b_row_l) * 128 + (u32)(kc * 32) + b_koff;
                        ldsm_x4(bf[ot], breg + (byte ^ ((byte >> 3) & 0x70)));
                    }
#pragma unroll
                    for (int ot = 0; ot < 4; ot++) {
                        mma_bf16(acc[0][g][ot], ah[0], bf[ot][0], bf[ot][1]);
                        mma_bf16(acc[1][g][ot], ah[1], bf[ot][0], bf[ot][1]);
                    }
#pragma unroll
                    for (int ot = 0; ot < 4; ot++) {
                        mma_bf16(acc[0][g][ot], al[0], bf[ot][0], bf[ot][1]);
                        mma_bf16(acc[1][g][ot], al[1], bf[ot][0], bf[ot][1]);
                    }
#pragma unroll
                    for (int ot = 0; ot < 4; ot++) {
                        mma_bf16(acc[0][g][ot], ah[0], bf[ot][2], bf[ot][3]);
                        mma_bf16(acc[1][g][ot], ah[1], bf[ot][2], bf[ot][3]);
                    }
                }
            }
        }

#pragma unroll
        for (int h = 0; h < 2; h++) {
#pragma unroll
            for (int rs = 0; rs < 2; rs++) {
                int row = warp_m * 32 + h * 16 + trow + rs * 8;
                int ol = local0 + row;
                if (ol < RowsOut) {
                    float* op = out + ((size_t)bidx * RowsOut + ol) * 64;
#pragma unroll
                    for (int ot = 0; ot < 4; ot++) {
                        int o = o0 + 8 * ot + tcol;
                        float2 hv;
#pragma unroll
                        for (int e = 0; e < 2; e++) {
                            float P = acc[h][0][ot][rs * 2 + e] + sbias[o + e];
                            float Q = acc[h][1][ot][rs * 2 + e] + sbias[64 + o + e];
                            float R = acc[h][2][ot][rs * 2 + e] + sbias[128 + o + e];
                            float sg = 1.f / (1.f + __expf(-Q));
                            float hval = fmaxf(fmaf(P, sg, R), 0.f);
                            if (e == 0) hv.x = hval; else hv.y = hval;
                        }
                        *(float2*)(op + o) = hv;
                    }
                }
            }
        }
    }
}

// ---------------- cheb: merged SIMT prop (L, L^2) + mma GEMM with Veff ----------------
// A chunks: [Zh, Zl, X1h, X1l, X2h, X2l] (X1=LZ, X2=L^2 Z); W = Veff hi/lo per k.
#define CH_OFF_W  0
#define CH_OFF_A  49152
#define CH_OFF_ZF 147456
#define CH_DYN    (147456 + 30720 + 1024)

__global__ void __launch_bounds__(256, 1)
cheb_mma_kernel(const float* __restrict__ zin, int T,
                const u32* __restrict__ Cw, const float* __restrict__ cb,
                float* __restrict__ out) {
    extern __shared__ char smraw[];
    __shared__ float Lsm[NPAD * NPAD], L2sm[NPAD * NPAD];
    __shared__ float sbias[64];

    const u32 sb0 = smem_u32(smraw);
    const u32 sbase = (sb0 + 1023) & ~1023u;
    char* sm = smraw + (sbase - sb0);
    float* Zf = (float*)(sm + CH_OFF_ZF);

    const int tid = threadIdx.x;
    const int wid = tid >> 5, lane = tid & 31;

    for (int i = tid; i < 12288; i += 256) {
        int region = i >> 11, rem = i & 2047, row = rem >> 5, c2 = rem & 31;
        u32 byte = row * 128 + c2 * 4;
        *(u32*)(sm + CH_OFF_W + region * 8192 + (byte ^ ((byte >> 3) & 0x70))) = Cw[i];
    }
    for (int i = tid; i < NPAD * NPAD; i += 256) { Lsm[i] = g_L[i]; L2sm[i] = g_L2[i]; }
    if (tid < 64) sbias[tid] = cb[tid];
    __syncthreads();

    const int ntt = (T + 2) / 3;
    const int ntiles = ntt * BATCH;

    const int warp_m = wid & 3;
    const int o0 = (wid >> 2) * 32;
    const u32 a_row_l = lane & 15;
    const u32 a_koff  = (lane & 16) ? 16u : 0u;
    const u32 b_row_l = lane & 7;
    const u32 b_koff  = (lane & 8) ? 16u : 0u;
    const u32 b_sreg  = (lane & 16) ? 8192u : 0u;
    const int trow = lane >> 2, tcol = (lane & 3) * 2;

    // prop row assignment: warp w handles nodes w, w+8, w+16, w+24, (w+32 if <33)
    int nrow[5], nv = 0;
#pragma unroll
    for (int j = 0; j < 5; j++) {
        int n = wid + 8 * j;
        if (n < NNODE) nrow[nv++] = n;
    }

    for (int tile = blockIdx.x; tile < ntiles; tile += gridDim.x) {
        const int b  = tile / ntt;
        const int t0 = (tile % ntt) * 3;
        const size_t bbase = ((size_t)b * T + t0) * NSTR;

        __syncthreads();

        // ---- fill: Z fp32 + bf16 hi/lo chunks ----
        for (int i4 = tid; i4 < 120 * 16; i4 += 256) {
            int r = i4 >> 4, c4 = (i4 & 15) << 2;
            float4 v = *(const float4*)(zin + (bbase + r) * 64 + c4);
            *(float4*)(Zf + r * 64 + c4) = v;
            __nv_bfloat16 hx = __float2bfloat16(v.x), hy = __float2bfloat16(v.y);
            __nv_bfloat16 hz = __float2bfloat16(v.z), hw = __float2bfloat16(v.w);
            u32 byte = r * 128 + (c4 << 1);
            u32 sw = byte ^ ((byte >> 3) & 0x70);
            *(u64*)(sm + CH_OFF_A + sw) = pack4bf(hx, hy, hz, hw);
            __nv_bfloat16 lx = __float2bfloat16(v.x - __bfloat162float(hx));
            __nv_bfloat16 ly = __float2bfloat16(v.y - __bfloat162float(hy));
            __nv_bfloat16 lz = __float2bfloat16(v.z - __bfloat162float(hz));
            __nv_bfloat16 lw = __float2bfloat16(v.w - __bfloat162float(hw));
            *(u64*)(sm + CH_OFF_A + 16384 + sw) = pack4bf(lx, ly, lz, lw);
        }
        __syncthreads();

        // ---- merged prop: X1 = L*Z, X2 = L^2*Z (single pass over m) ----
#pragma unroll
        for (int t = 0; t < 3; t++) {
            u64 a1[5], a2[5];
#pragma unroll
            for (int j = 0; j < 5; j++) { a1[j] = 0ull; a2[j] = 0ull; }
            const float* zt = Zf + (t * 40) * 64 + 2 * lane;
            for (int m = 0; m < NNODE; m++) {
                u64 zz = *(const u64*)(zt + m * 64);
#pragma unroll
                for (int j = 0; j < 5; j++) {
                    if (j < nv) {
                        fma2(a1[j], zz, dup2(Lsm[nrow[j] * NPAD + m]));
                        fma2(a2[j], zz, dup2(L2sm[nrow[j] * NPAD + m]));
                    }
                }
            }
#pragma unroll
            for (int j = 0; j < 5; j++) {
                if (j < nv) {
                    int arow = t * 40 + nrow[j];
                    u32 byte = (u32)arow * 128 + (u32)lane * 4;
                    u32 sw = byte ^ ((byte >> 3) & 0x70);
                    float f0, f1;
                    u16 h0, l0, h1, l1;
                    unpk2(a1[j], f0, f1);
                    bfsplit(f0, h0, l0);
                    bfsplit(f1, h1, l1);
                    *(u32*)(sm + CH_OFF_A + 32768 + sw) = ((u32)h1 << 16) | h0;
                    *(u32*)(sm + CH_OFF_A + 49152 + sw) = ((u32)l1 << 16) | l0;
                    unpk2(a2[j], f0, f1);
                    bfsplit(f0, h0, l0);
                    bfsplit(f1, h1, l1);
                    *(u32*)(sm + CH_OFF_A + 65536 + sw) = ((u32)h1 << 16) | h0;
                    *(u32*)(sm + CH_OFF_A + 81920 + sw) = ((u32)l1 << 16) | l0;
                }
            }
        }
        __syncthreads();

        // ---- GEMM: O = relu([Z|X1|X2] * Veff + bias), M=128, N=64, K=192 ----
        float acc[2][4][4];
#pragma unroll
        for (int h = 0; h < 2; h++)
#pragma unroll
            for (int ot = 0; ot < 4; ot++)
#pragma unroll
                for (int c = 0; c < 4; c++) acc[h][ot][c] = 0.f;

#pragma unroll
        for (int chunk = 0; chunk < 3; chunk++) {
            u32 aHiBase = CH_OFF_A + (u32)chunk * 32768u;
            u32 breg = sbase + CH_OFF_W + (u32)chunk * 16384u + b_sreg;
#pragma unroll
            for (int kc = 0; kc < 4; kc++) {
                u32 ah[2][4], al[2][4];
#pragma unroll
                for (int h = 0; h < 2; h++) {
                    u32 rb = (u32)(warp_m * 32 + h * 16) + a_row_l;
                    u32 byte = rb * 128 + (u32)(kc * 32) + a_koff;
                    u32 sw = byte ^ ((byte >> 3) & 0x70);
                    ldsm_x4(ah[h], sbase + aHiBase + sw);
                    ldsm_x4(al[h], sbase + aHiBase + 16384u + sw);
                }
                u32 bf[4][4];
#pragma unroll
                for (int ot = 0; ot < 4; ot++) {
                    u32 byte = (u32)(o0 + 8 * ot + (int)b_row_l) * 128 + (u32)(kc * 32) + b_koff;
                    ldsm_x4(bf[ot], breg + (byte ^ ((byte >> 3) & 0x70)));
                }
#pragma unroll
                for (int ot = 0; ot < 4; ot++) {
                    mma_bf16(acc[0][ot], ah[0], bf[ot][0], bf[ot][1]);
                    mma_bf16(acc[1][ot], ah[1], bf[ot][0], bf[ot][1]);
                }
#pragma unroll
                for (int ot = 0; ot < 4; ot++) {
                    mma_bf16(acc[0][ot], al[0], bf[ot][0], bf[ot][1]);
                    mma_bf16(acc[1][ot], al[1], bf[ot][0], bf[ot][1]);
                }
#pragma unroll
                for (int ot = 0; ot < 4; ot++) {
                    mma_bf16(acc[0][ot], ah[0], bf[ot][2], bf[ot][3]);
                    mma_bf16(acc[1][ot], ah[1], bf[ot][2], bf[ot][3]);
                }
            }
        }

        // ---- epilogue ----
#pragma unroll
        for (int h = 0; h < 2; h++) {
#pragma unroll
            for (int rs = 0; rs < 2; rs++) {
                int r = warp_m * 32 + h * 16 + trow + rs * 8;
                if (r < 120) {
                    int n = r % 40;
                    int t = t0 + r / 40;
                    if (n < NNODE && t < T) {
                        float* op = out + (bbase + r) * 64;
#pragma unroll
                        for (int ot = 0; ot < 4; ot++) {
                            int o = o0 + 8 * ot + tcol;
                            float2 hv;
                            hv.x = fmaxf(acc[h][ot][rs * 2 + 0] + sbias[o + 0], 0.f);
                            hv.y = fmaxf(acc[h][ot][rs * 2 + 1] + sbias[o + 1], 0.f);
                            *(float2*)(op + o) = hv;
                        }
                    }
                }
            }
        }
    }
}

// ---------------- BN stats ----------------
__global__ void __launch_bounds__(256)
bnstats_kernel(const float* __restrict__ x, int T,
               double* __restrict__ bnsum, double* __restrict__ bnsqs) {
    const int n = blockIdx.x, b = blockIdx.y, tid = threadIdx.x;
    const float* xp = x + ((size_t)b * T * NSTR + n) * 64;
    double s = 0.0, q = 0.0;
    for (int i = tid; i < T * 16; i += 256) {
        int t = i >> 4, c4 = (i & 15) << 2;
        float4 v = *(const float4*)(xp + (size_t)t * NSTR * 64 + c4);
        s += (double)v.x + (double)v.y + (double)v.z + (double)v.w;
        q += (double)v.x * v.x + (double)v.y * v.y + (double)v.z * v.z + (double)v.w * v.w;
    }
    __shared__ double r1[256], r2[256];
    r1[tid] = s; r2[tid] = q;
    __syncthreads();
    for (int st = 128; st > 0; st >>= 1) {
        if (tid < st) { r1[tid] += r1[tid + st]; r2[tid] += r2[tid + st]; }
        __syncthreads();
    }
    if (tid == 0) {
        atomicAdd(&bnsum[n], r1[0]);
        atomicAdd(&bnsqs[n], r2[0]);
    }
}

// ---------------- BN finalize ----------------
__global__ void finalize_bn_kernel(const double* __restrict__ sum, const double* __restrict__ sqs,
                                   const float* __restrict__ gamma, const float* __restrict__ beta,
                                   double cnt, float* __restrict__ scl, float* __restrict__ shf) {
    int nn = threadIdx.x;
    if (nn < NNODE) {
        double m = sum[nn] / cnt;
        double v = sqs[nn] / cnt - m * m;
        double inv = 1.0 / sqrt(v + 1e-5);
        double sc = (double)gamma[nn] * inv;
        scl[nn] = (float)sc;
        shf[nn] = (float)((double)beta[nn] - m * sc);
    }
}

// ---------------- fused BN+relu+time-mean ----------------
__global__ void timemean_kernel(const float* __restrict__ x, int T,
                                const float* __restrict__ scl, const float* __restrict__ shf) {
    const int n = blockIdx.x, b = blockIdx.y, c = threadIdx.x;
    const float sc = scl[n], sh = shf[n];
    double s = 0.0;
#pragma unroll 4
    for (int t = 0; t < T; t++) {
        float v = x[(((size_t)b * T + t) * NSTR + n) * CH + c];
        v = fmaxf(fmaf(v, sc, sh), 0.f);
        s += (double)v;
    }
    g_M[(b * NNODE + n) * CH + c] = (float)(s / (double)T);
}

// ---------------- classifier ----------------
__global__ void __launch_bounds__(256)
fc_kernel(const float* __restrict__ w1, const float* __restrict__ b1,
          const float* __restrict__ w2, const float* __restrict__ b2,
          float* __restrict__ out) {
    __shared__ float ms[NNODE * CH];
    __shared__ float h1[256];
    const int b = blockIdx.x, tid = threadIdx.x;
    for (int i = tid; i < NNODE * CH; i += 256) ms[i] = g_M[b * NNODE * CH + i];
    __syncthreads();
    double acc = (double)b1[tid];
    for (int i = 0; i < NNODE * CH; i++) acc += (double)ms[i] * (double)w1[i * 256 + tid];
    h1[tid] = fmaxf((float)acc, 0.f);
    __syncthreads();
    if (tid < 10) {
        double a2 = (double)b2[tid];
        for (int i = 0; i < 256; i++) a2 += (double)h1[i] * (double)w2[i * 10 + tid];
        out[b * 10 + tid] = (float)a2;
    }
}

// ---------------- launch ----------------
extern "C" void kernel_launch(void* const* d_in, const int* in_sizes, int n_in,
                              void* d_out, int out_size) {
    const float* x        = (const float*)d_in[0];
    const int*   ei       = (const int*)d_in[1];
    const float* s1_tc1_w = (const float*)d_in[2];
    const float* s1_tc1_b = (const float*)d_in[3];
    const float* s1_cheb_w= (const float*)d_in[4];
    const float* s1_cheb_b= (const float*)d_in[5];
    const float* s1_tc2_w = (const float*)d_in[6];
    const float* s1_tc2_b = (const float*)d_in[7];
    const float* s1_bn_g  = (const float*)d_in[8];
    const float* s1_bn_b  = (const float*)d_in[9];
    const float* s2_tc1_w = (const float*)d_in[10];
    const float* s2_tc1_b = (const float*)d_in[11];
    const float* s2_cheb_w= (const float*)d_in[12];
    const float* s2_cheb_b= (const float*)d_in[13];
    const float* s2_tc2_w = (const float*)d_in[14];
    const float* s2_tc2_b = (const float*)d_in[15];
    const float* s2_bn_g  = (const float*)d_in[16];
    const float* s2_bn_b  = (const float*)d_in[17];
    const float* fc1_w    = (const float*)d_in[18];
    const float* fc1_b    = (const float*)d_in[19];
    const float* fc2_w    = (const float*)d_in[20];
    const float* fc2_b    = (const float*)d_in[21];

    float *bufA, *bufB, *scl1, *shf1, *scl2, *shf2;
    u32 *Bw1, *Bw2, *Bw3, *Cw1, *Cw2;
    double *sum1, *sqs1, *sum2, *sqs2;
    cudaGetSymbolAddress((void**)&bufA, g_bufA);
    cudaGetSymbolAddress((void**)&bufB, g_bufB);
    cudaGetSymbolAddress((void**)&Bw1, g_Bw1);
    cudaGetSymbolAddress((void**)&Bw2, g_Bw2);
    cudaGetSymbolAddress((void**)&Bw3, g_Bw3);
    cudaGetSymbolAddress((void**)&Cw1, g_Cw1);
    cudaGetSymbolAddress((void**)&Cw2, g_Cw2);
    cudaGetSymbolAddress((void**)&scl1, g_scl1);
    cudaGetSymbolAddress((void**)&shf1, g_shf1);
    cudaGetSymbolAddress((void**)&scl2, g_scl2);
    cudaGetSymbolAddress((void**)&shf2, g_shf2);
    cudaGetSymbolAddress((void**)&sum1, g_sum1);
    cudaGetSymbolAddress((void**)&sqs1, g_sqs1);
    cudaGetSymbolAddress((void**)&sum2, g_sum2);
    cudaGetSymbolAddress((void**)&sqs2, g_sqs2);

    cudaFuncSetAttribute(tconv_mma_kernel, cudaFuncAttributeMaxDynamicSharedMemorySize, TC_SMEM);
    cudaFuncSetAttribute(cheb_mma_kernel,  cudaFuncAttributeMaxDynamicSharedMemorySize, CH_DYN);

    const int ne = in_sizes[1] / 2;
    const int GRID = 148;

    setup_kernel<<<1, 64>>>(ei, ne, s1_tc1_w);
    convert_w_kernel<<<144, 256>>>(s1_tc2_w, Bw1);
    convert_w_kernel<<<144, 256>>>(s2_tc1_w, Bw2);
    convert_w_kernel<<<144, 256>>>(s2_tc2_w, Bw3);
    convert_cw_kernel<<<96, 256>>>(s1_cheb_w, Cw1, s2_cheb_w, Cw2);

    // ---- STConv 1 ----
    tconv3_kernel<<<GRID, dim3(64, 8)>>>(x, s1_tc1_b, bufA);                          // T=510
    cheb_mma_kernel<<<GRID, 256, CH_DYN>>>(bufA, 510, Cw1, s1_cheb_b, bufB);
    tconv_mma_kernel<<<GRID, 256, TC_SMEM>>>(bufB, 510, Bw1, s1_tc2_b,
                                             nullptr, nullptr, 0, bufA);              // T=508
    bnstats_kernel<<<dim3(NNODE, BATCH), 256>>>(bufA, 508, sum1, sqs1);
    finalize_bn_kernel<<<1, 64>>>(sum1, sqs1, s1_bn_g, s1_bn_b,
                                  (double)BATCH * 508.0 * 64.0, scl1, shf1);

    // ---- STConv 2 (BN1+relu fused into A-conversion) ----
    tconv_mma_kernel<<<GRID, 256, TC_SMEM>>>(bufA, 508, Bw2, s2_tc1_b,
                                             scl1, shf1, 1, bufB);                    // T=506
    cheb_mma_kernel<<<GRID, 256, CH_DYN>>>(bufB, 506, Cw2, s2_cheb_b, bufA);
    tconv_mma_kernel<<<GRID, 256, TC_SMEM>>>(bufA, 506, Bw3, s2_tc2_b,
                                             nullptr, nullptr, 0, bufB);              // T=504
    bnstats_kernel<<<dim3(NNODE, BATCH), 256>>>(bufB, 504, sum2, sqs2);
    finalize_bn_kernel<<<1, 64>>>(sum2, sqs2, s2_bn_g, s2_bn_b,
                                  (double)BATCH * 504.0 * 64.0, scl2, shf2);

    // ---- head ----
    timemean_kernel<<<dim3(NNODE, BATCH), 64>>>(bufB, 504, scl2, shf2);
    fc_kernel<<<BATCH, 256>>>(fc1_w, fc1_b, fc2_w, fc2_b, (float*)d_out);
}

// round 8
// speedup vs baseline: 2.6407x; 1.1127x over previous
#include <cuda_runtime.h>
#include <cuda_bf16.h>
#include <math.h>

#define BATCH 32
#define NNODE 33
#define NSTR  40
#define NPAD  36
#define CH    64

typedef unsigned long long u64;
typedef unsigned int u32;
typedef unsigned short u16;

// ---------------- f32x2 helpers ----------------
__device__ __forceinline__ u64 pk2(float lo, float hi) {
    u64 r;
    asm("mov.b64 %0, {%1, %2};" : "=l"(r) : "r"(__float_as_uint(lo)), "r"(__float_as_uint(hi)));
    return r;
}
__device__ __forceinline__ u64 dup2(float v) { return pk2(v, v); }
__device__ __forceinline__ void unpk2(u64 v, float& lo, float& hi) {
    u32 a, b;
    asm("mov.b64 {%0, %1}, %2;" : "=r"(a), "=r"(b) : "l"(v));
    lo = __uint_as_float(a);
    hi = __uint_as_float(b);
}
__device__ __forceinline__ void fma2(u64& d, u64 a, u64 b) {
    asm("fma.rn.f32x2 %0, %1, %2, %0;" : "+l"(d) : "l"(a), "l"(b));
}

// ---------------- mma.sync / ldmatrix helpers ----------------
__device__ __forceinline__ u32 smem_u32(const void* p) {
    u32 a;
    asm("{ .reg .u64 t; cvta.to.shared.u64 t, %1; cvt.u32.u64 %0, t; }" : "=r"(a) : "l"(p));
    return a;
}
__device__ __forceinline__ void ldsm_x4(u32* r, u32 addr) {
    asm volatile("ldmatrix.sync.aligned.m8n8.x4.shared.b16 {%0,%1,%2,%3}, [%4];"
                 : "=r"(r[0]), "=r"(r[1]), "=r"(r[2]), "=r"(r[3]) : "r"(addr));
}
__device__ __forceinline__ void mma_bf16(float* c, const u32* a, u32 b0, u32 b1) {
    asm volatile("mma.sync.aligned.m16n8k16.row.col.f32.bf16.bf16.f32 "
                 "{%0,%1,%2,%3}, {%4,%5,%6,%7}, {%8,%9}, {%0,%1,%2,%3};"
                 : "+f"(c[0]), "+f"(c[1]), "+f"(c[2]), "+f"(c[3])
                 : "r"(a[0]), "r"(a[1]), "r"(a[2]), "r"(a[3]), "r"(b0), "r"(b1));
}
__device__ __forceinline__ u64 pack4bf(__nv_bfloat16 a, __nv_bfloat16 b,
                                       __nv_bfloat16 c, __nv_bfloat16 d) {
    u32 u0 = ((u32)__bfloat16_as_ushort(b) << 16) | (u32)__bfloat16_as_ushort(a);
    u32 u1 = ((u32)__bfloat16_as_ushort(d) << 16) | (u32)__bfloat16_as_ushort(c);
    return (u64)u0 | ((u64)u1 << 32);
}
__device__ __forceinline__ void bfsplit(float v, u16& h, u16& l) {
    __nv_bfloat16 hb = __float2bfloat16(v);
    h = __bfloat16_as_ushort(hb);
    l = __bfloat16_as_ushort(__float2bfloat16(v - __bfloat162float(hb)));
}

// ---------------- device scratch ----------------
#define BUF_ELEMS ((size_t)BATCH * 510 * NSTR * CH)
__device__ float g_bufA[BUF_ELEMS];
__device__ float g_bufB[BUF_ELEMS];
__device__ float g_L[NPAD * NPAD];
__device__ float g_L2[NPAD * NPAD];
__device__ float g_w1a[3 * 3 * 3 * 64];
__device__ u32   g_Bw1[36864], g_Bw2[36864], g_Bw3[36864];
__device__ u32   g_Cw1[12288], g_Cw2[12288];
__device__ float g_scl1[NNODE], g_shf1[NNODE];
__device__ float g_scl2[NNODE], g_shf2[NNODE];
__device__ double g_sum1[NNODE], g_sqs1[NNODE];
__device__ double g_sum2[NNODE], g_sqs2[NNODE];
__device__ float g_M[BATCH * NNODE * CH];

// ---------------- setup ----------------
__global__ void setup_kernel(const int* __restrict__ ei, int ne, const float* __restrict__ w3) {
    __shared__ float sL[NPAD * NPAD];
    int i = threadIdx.x;
    if (i < NNODE) { g_sum1[i] = 0.0; g_sqs1[i] = 0.0; g_sum2[i] = 0.0; g_sqs2[i] = 0.0; }
    for (int j = i; j < 3 * 3 * 3 * 64; j += 64) {
        int o  = j & 63;
        int k  = (j >> 6) % 3;
        int ci = (j / 192) % 3;
        int g  = j / (192 * 3);
        g_w1a[j] = w3[((g * 64 + o) * 3 + ci) * 3 + k];
    }
    if (i == 0) {
        double deg[NNODE];
        for (int k = 0; k < NNODE; k++) deg[k] = 0.0;
        for (int e = 0; e < ne; e++) deg[ei[e]] += 1.0;
        double dinv[NNODE];
        for (int k = 0; k < NNODE; k++) dinv[k] = (deg[k] > 0.0) ? (1.0 / sqrt(deg[k])) : 0.0;
        for (int k = 0; k < NPAD * NPAD; k++) sL[k] = 0.0f;
        for (int e = 0; e < ne; e++) {
            int s = ei[e];
            int t = ei[ne + e];
            sL[t * NPAD + s] += (float)(-dinv[s] * dinv[t]);
        }
        for (int k = 0; k < NPAD * NPAD; k++) g_L[k] = sL[k];
    }
    __syncthreads();
    for (int idx = i; idx < NPAD * NPAD; idx += 64) {
        int r = idx / NPAD, c = idx % NPAD;
        float s = 0.f;
        for (int m = 0; m < NPAD; m++) s = fmaf(sL[r * NPAD + m], sL[m * NPAD + c], s);
        g_L2[idx] = s;
    }
}

// ---- tconv weights -> bf16 hi/lo regions ----
__global__ void convert_w_kernel(const float* __restrict__ w, u32* __restrict__ outw) {
    int i = blockIdx.x * blockDim.x + threadIdx.x;
    if (i >= 36864) return;
    int region = i >> 11;
    int rem    = i & 2047;
    int o      = rem >> 5;
    int c2     = rem & 31;
    int s  = region & 1;
    int gk = region >> 1;
    int g  = gk / 3, k = gk % 3;
    int ci0 = 2 * c2;
    float v0 = w[((g * 64 + o) * 64 + ci0) * 3 + k];
    float v1 = w[((g * 64 + o) * 64 + ci0 + 1) * 3 + k];
    u16 h0, l0, h1, l1;
    bfsplit(v0, h0, l0);
    bfsplit(v1, h1, l1);
    outw[i] = (s == 0) ? (((u32)h1 << 16) | (u32)h0) : (((u32)l1 << 16) | (u32)l0);
}

// ---- cheb weights -> Veff = [W0-W2, W1, 2*W2], bf16 hi/lo regions ----
__device__ __forceinline__ float veff(const float* cw, int k, int c, int d) {
    if (k == 0) return cw[(0 * 64 + c) * 64 + d] - cw[(2 * 64 + c) * 64 + d];
    if (k == 1) return cw[(1 * 64 + c) * 64 + d];
    return 2.f * cw[(2 * 64 + c) * 64 + d];
}
__global__ void convert_cw_kernel(const float* __restrict__ cw1, u32* __restrict__ o1,
                                  const float* __restrict__ cw2, u32* __restrict__ o2) {
    int i = blockIdx.x * blockDim.x + threadIdx.x;
    if (i >= 24576) return;
    const float* cw = (i < 12288) ? cw1 : cw2;
    u32* op = (i < 12288) ? o1 : o2;
    int j = (i < 12288) ? i : (i - 12288);
    int region = j >> 11, rem = j & 2047, d = rem >> 5, c2 = rem & 31;
    int k = region >> 1, s = region & 1, c0 = 2 * c2;
    float v0 = veff(cw, k, c0, d);
    float v1 = veff(cw, k, c0 + 1, d);
    u16 h0, l0, h1, l1;
    bfsplit(v0, h0, l0);
    bfsplit(v1, h1, l1);
    op[j] = (s == 0) ? (((u32)h1 << 16) | (u32)h0) : (((u32)l1 << 16) | (u32)l0);
}

// ---------------- SIMT gated tconv CI=3 (first layer) ----------------
__global__ void __launch_bounds__(512)
tconv3_kernel(const float* __restrict__ xin,
              const float* __restrict__ bias,
              float* __restrict__ out) {
    constexpr int CI = 3, CT = 128, TO = 16, ST = CT + 4, HP = TO / 2;
    constexpr int Tin = 512, Tout = 510;
    __shared__ float ws[3 * CI * 3 * 64];
    __shared__ float xs[CI * ST];

    const int tid = threadIdx.y * 64 + threadIdx.x;
    const int ntch = (Tout + CT - 1) / CT;
    const int ntiles = ntch * NNODE * BATCH;

    for (int i = tid; i < 3 * CI * 3 * 64; i += 512) ws[i] = g_w1a[i];

    const int o  = threadIdx.x;
    const int tb = threadIdx.y * TO;
    const float bP = bias[o], bQ = bias[64 + o], bR = bias[128 + o];

    for (int tile = blockIdx.x; tile < ntiles; tile += gridDim.x) {
        const int tch = tile % ntch;
        const int rem = tile / ntch;
        const int n   = rem % NNODE;
        const int b   = rem / NNODE;
        const int t0  = tch * CT;

        __syncthreads();
        for (int i = tid; i < (CT + 2) * CI; i += 512) {
            int tt = i / CI, ci = i % CI;
            int t = t0 + tt;
            float v = 0.f;
            if (t < Tin) v = xin[(((size_t)b * Tin + t) * NNODE + n) * CI + ci];
            xs[ci * ST + tt] = v;
        }
        __syncthreads();

        u64 accP[3][HP];
#pragma unroll
        for (int g = 0; g < 3; g++)
#pragma unroll
            for (int p = 0; p < HP; p++) accP[g][p] = 0ull;

#pragma unroll
        for (int ci = 0; ci < CI; ci++) {
            const float* xp = &xs[ci * ST + tb];
            u64 ep[HP + 1];
#pragma unroll
            for (int p = 0; p <= HP; p++) ep[p] = *reinterpret_cast<const u64*>(xp + 2 * p);
            float xl[HP + 1], xh[HP + 1];
#pragma unroll
            for (int p = 0; p <= HP; p++) unpk2(ep[p], xl[p], xh[p]);
            u64 op[HP];
#pragma unroll
            for (int p = 0; p < HP; p++) op[p] = pk2(xh[p], xl[p + 1]);

#pragma unroll
            for (int g = 0; g < 3; g++) {
#pragma unroll
                for (int k = 0; k < 3; k++) {
                    u64 wd = dup2(ws[((g * CI + ci) * 3 + k) * 64 + o]);
                    const u64* xq = (k == 0) ? ep : (k == 1) ? op : (ep + 1);
#pragma unroll
                    for (int p = 0; p < HP; p++) fma2(accP[g][p], xq[p], wd);
                }
            }
        }

#pragma unroll
        for (int p = 0; p < HP; p++) {
            float P0, P1, Q0, Q1, R0, R1;
            unpk2(accP[0][p], P0, P1);
            unpk2(accP[1][p], Q0, Q1);
            unpk2(accP[2][p], R0, R1);
#pragma unroll
            for (int half = 0; half < 2; half++) {
                int t = t0 + tb + 2 * p + half;
                if (t < Tout) {
                    float P = (half ? P1 : P0) + bP;
                    float Q = (half ? Q1 : Q0) + bQ;
                    float R = (half ? R1 : R0) + bR;
                    float sg = 1.f / (1.f + __expf(-Q));
                    float h = fmaxf(fmaf(P, sg, R), 0.f);
                    out[(((size_t)b * Tout + t) * NSTR + n) * CH + o] = h;
                }
            }
        }
    }
}

// ---------------- mma.sync gated tconv CI=64 (512 threads, 16 warps, m16 warp tiles) ----------------
#define ROWS_A 208
#define A_SPLIT_B (ROWS_A * 128)
#define B_BYTES   (18 * 8192)
#define OFF_B     1024
#define OFF_A     (OFF_B + B_BYTES)
#define TC_SMEM   (OFF_A + 2 * A_SPLIT_B + 1024)

__global__ void __launch_bounds__(512, 1)
tconv_mma_kernel(const float* __restrict__ xin, int Tin,
                 const u32* __restrict__ Bw,
                 const float* __restrict__ bias,
                 const float* __restrict__ scl, const float* __restrict__ shf, int mode,
                 float* __restrict__ out) {
    extern __shared__ char smraw[];
    __shared__ float sbias[192];

    const u32 sb0 = smem_u32(smraw);
    const u32 sbase = (sb0 + 1023) & ~1023u;
    char* sm = smraw + (sbase - sb0);

    const int tid = threadIdx.x;
    const int wid = tid >> 5, lane = tid & 31;
    const int Tout = Tin - 2;
    const int RowsIn = Tin * NSTR, RowsOut = Tout * NSTR;
    const int ntb = (RowsOut + 127) / 128;
    const int ntiles = ntb * BATCH;

    for (int i = tid; i < 36864; i += 512) {
        int r = i >> 11, rem = i & 2047, row = rem >> 5, c2 = rem & 31;
        u32 byte = row * 128 + c2 * 4;
        *(u32*)(sm + OFF_B + r * 8192 + (byte ^ ((byte >> 3) & 0x70))) = Bw[i];
    }
    if (tid < 192) sbias[tid] = bias[tid];
    __syncthreads();

    const int warp_m = wid & 7;          // 8 × m16 blocks = 128 rows
    const int o0 = (wid >> 3) * 32;      // 2 × o32 halves

    const u32 a_row_l = lane & 15;
    const u32 a_koff  = (lane & 16) ? 16u : 0u;
    const u32 b_row_l = lane & 7;
    const u32 b_koff  = (lane & 8) ? 16u : 0u;
    const u32 b_sreg  = (lane & 16) ? 8192u : 0u;

    const int trow = lane >> 2;
    const int tcol = (lane & 3) * 2;

    for (int tile = blockIdx.x; tile < ntiles; tile += gridDim.x) {
        const int bidx = tile / ntb, tl = tile % ntb;
        const int local0 = tl * 128;
        const float* xb = xin + (size_t)bidx * RowsIn * 64;

        __syncthreads();

        for (int i4 = tid; i4 < ROWS_A * 16; i4 += 512) {
            int r = i4 >> 4, c4 = (i4 & 15) << 2;
            int il = local0 + r;
            float4 v = make_float4(0.f, 0.f, 0.f, 0.f);
            if (il < RowsIn) {
                int n = il % NSTR;
                if (n < NNODE) {
                    v = *(const float4*)(xb + (size_t)il * 64 + c4);
                    if (mode) {
                        float sc = scl[n], sh = shf[n];
                        v.x = fmaxf(fmaf(v.x, sc, sh), 0.f);
                        v.y = fmaxf(fmaf(v.y, sc, sh), 0.f);
                        v.z = fmaxf(fmaf(v.z, sc, sh), 0.f);
                        v.w = fmaxf(fmaf(v.w, sc, sh), 0.f);
                    }
                }
            }
            __nv_bfloat16 hx = __float2bfloat16(v.x), hy = __float2bfloat16(v.y);
            __nv_bfloat16 hz = __float2bfloat16(v.z), hw = __float2bfloat16(v.w);
            u32 byte = r * 128 + (c4 << 1);
            u32 sw = byte ^ ((byte >> 3) & 0x70);
            *(u64*)(sm + OFF_A + sw) = pack4bf(hx, hy, hz, hw);
            __nv_bfloat16 lx = __float2bfloat16(v.x - __bfloat162float(hx));
            __nv_bfloat16 ly = __float2bfloat16(v.y - __bfloat162float(hy));
            __nv_bfloat16 lz = __float2bfloat16(v.z - __bfloat162float(hz));
            __nv_bfloat16 lw = __float2bfloat16(v.w - __bfloat162float(hw));
            *(u64*)(sm + OFF_A + A_SPLIT_B + sw) = pack4bf(lx, ly, lz, lw);
        }
        __syncthreads();

        float acc[3][4][4];
#pragma unroll
        for (int g = 0; g < 3; g++)
#pragma unroll
            for (int ot = 0; ot < 4; ot++)
#pragma unroll
                for (int c = 0; c < 4; c++) acc[g][ot][c] = 0.f;

#pragma unroll
        for (int tap = 0; tap < 3; tap++) {
#pragma unroll
            for (int kc = 0; kc < 4; kc++) {
                u32 ah[4], al[4];
                {
                    u32 rb = (u32)(tap * 40 + warp_m * 16) + a_row_l;
                    u32 byte = rb * 128 + (u32)(kc * 32) + a_koff;
                    u32 sw = byte ^ ((byte >> 3) & 0x70);
                    ldsm_x4(ah, sbase + OFF_A + sw);
                    ldsm_x4(al, sbase + OFF_A + A_SPLIT_B + sw);
                }
#pragma unroll
                for (int g = 0; g < 3; g++) {
                    u32 breg = sbase + OFF_B + (u32)((g * 3 + tap) * 2) * 8192 + b_sreg;
                    u32 bf[4][4];
#pragma unroll
                    for (int ot = 0; ot < 4; ot++) {
                        u32 byte = (u32)(o0 + 8 * ot + (int)b_row_l) * 128 + (u32)(kc * 32) + b_koff;
                        ldsm_x4(bf[ot], breg + (byte ^ ((byte >> 3) & 0x70)));
                    }
#pragma unroll
                    for (int ot = 0; ot < 4; ot++)
                        mma_bf16(acc[g][ot], ah, bf[ot][0], bf[ot][1]);
#pragma unroll
                    for (int ot = 0; ot < 4; ot++)
                        mma_bf16(acc[g][ot], al, bf[ot][0], bf[ot][1]);
#pragma unroll
                    for (int ot = 0; ot < 4; ot++)
                        mma_bf16(acc[g][ot], ah, bf[ot][2], bf[ot][3]);
                }
            }
        }

#pragma unroll
        for (int rs = 0; rs < 2; rs++) {
            int row = warp_m * 16 + trow + rs * 8;
            int ol = local0 + row;
            if (ol < RowsOut) {
                float* op = out + ((size_t)bidx * RowsOut + ol) * 64;
#pragma unroll
                for (int ot = 0; ot < 4; ot++) {
                    int o = o0 + 8 * ot + tcol;
                    float2 hv;
#pragma unroll
                    for (int e = 0; e < 2; e++) {
                        float P = acc[0][ot][rs * 2 + e] + sbias[o + e];
                        float Q = acc[1][ot][rs * 2 + e] + sbias[64 + o + e];
                        float R = acc[2][ot][rs * 2 + e] + sbias[128 + o + e];
                        float sg = 1.f / (1.f + __expf(-Q));
                        float hval = fmaxf(fmaf(P, sg, R), 0.f);
                        if (e == 0) hv.x = hval; else hv.y = hval;
                    }
                    *(float2*)(op + o) = hv;
                }
            }
        }
    }
}

// ---------------- cheb: merged SIMT prop (L, L^2) + mma GEMM (512 threads, 16 warps) ----------------
#define CH_OFF_W  0
#define CH_OFF_A  49152
#define CH_OFF_ZF 147456
#define CH_DYN    (147456 + 30720 + 1024)

__global__ void __launch_bounds__(512, 1)
cheb_mma_kernel(const float* __restrict__ zin, int T,
                const u32* __restrict__ Cw, const float* __restrict__ cb,
                float* __restrict__ out) {
    extern __shared__ char smraw[];
    __shared__ float Lsm[NPAD * NPAD], L2sm[NPAD * NPAD];
    __shared__ float sbias[64];

    const u32 sb0 = smem_u32(smraw);
    const u32 sbase = (sb0 + 1023) & ~1023u;
    char* sm = smraw + (sbase - sb0);
    float* Zf = (float*)(sm + CH_OFF_ZF);

    const int tid = threadIdx.x;
    const int wid = tid >> 5, lane = tid & 31;

    for (int i = tid; i < 12288; i += 512) {
        int region = i >> 11, rem = i & 2047, row = rem >> 5, c2 = rem & 31;
        u32 byte = row * 128 + c2 * 4;
        *(u32*)(sm + CH_OFF_W + region * 8192 + (byte ^ ((byte >> 3) & 0x70))) = Cw[i];
    }
    for (int i = tid; i < NPAD * NPAD; i += 512) { Lsm[i] = g_L[i]; L2sm[i] = g_L2[i]; }
    if (tid < 64) sbias[tid] = cb[tid];
    __syncthreads();

    const int ntt = (T + 2) / 3;
    const int ntiles = ntt * BATCH;

    const int warp_m = wid & 7;
    const int o0 = (wid >> 3) * 32;
    const u32 a_row_l = lane & 15;
    const u32 a_koff  = (lane & 16) ? 16u : 0u;
    const u32 b_row_l = lane & 7;
    const u32 b_koff  = (lane & 8) ? 16u : 0u;
    const u32 b_sreg  = (lane & 16) ? 8192u : 0u;
    const int trow = lane >> 2, tcol = (lane & 3) * 2;

    // prop row assignment: warp w handles nodes w, w+16, w+32(if<33)
    int nrow[3], nv = 0;
#pragma unroll
    for (int j = 0; j < 3; j++) {
        int n = wid + 16 * j;
        if (n < NNODE) nrow[nv++] = n;
    }

    for (int tile = blockIdx.x; tile < ntiles; tile += gridDim.x) {
        const int b  = tile / ntt;
        const int t0 = (tile % ntt) * 3;
        const size_t bbase = ((size_t)b * T + t0) * NSTR;

        __syncthreads();

        for (int i4 = tid; i4 < 120 * 16; i4 += 512) {
            int r = i4 >> 4, c4 = (i4 & 15) << 2;
            float4 v = *(const float4*)(zin + (bbase + r) * 64 + c4);
            *(float4*)(Zf + r * 64 + c4) = v;
            __nv_bfloat16 hx = __float2bfloat16(v.x), hy = __float2bfloat16(v.y);
            __nv_bfloat16 hz = __float2bfloat16(v.z), hw = __float2bfloat16(v.w);
            u32 byte = r * 128 + (c4 << 1);
            u32 sw = byte ^ ((byte >> 3) & 0x70);
            *(u64*)(sm + CH_OFF_A + sw) = pack4bf(hx, hy, hz, hw);
            __nv_bfloat16 lx = __float2bfloat16(v.x - __bfloat162float(hx));
            __nv_bfloat16 ly = __float2bfloat16(v.y - __bfloat162float(hy));
            __nv_bfloat16 lz = __float2bfloat16(v.z - __bfloat162float(hz));
            __nv_bfloat16 lw = __float2bfloat16(v.w - __bfloat162float(hw));
            *(u64*)(sm + CH_OFF_A + 16384 + sw) = pack4bf(lx, ly, lz, lw);
        }
        __syncthreads();

        // merged prop: X1 = L*Z, X2 = L^2*Z
#pragma unroll
        for (int t = 0; t < 3; t++) {
            u64 a1[3], a2[3];
#pragma unroll
            for (int j = 0; j < 3; j++) { a1[j] = 0ull; a2[j] = 0ull; }
            const float* zt = Zf + (t * 40) * 64 + 2 * lane;
            for (int m = 0; m < NNODE; m++) {
                u64 zz = *(const u64*)(zt + m * 64);
#pragma unroll
                for (int j = 0; j < 3; j++) {
                    if (j < nv) {
                        fma2(a1[j], zz, dup2(Lsm[nrow[j] * NPAD + m]));
                        fma2(a2[j], zz, dup2(L2sm[nrow[j] * NPAD + m]));
                    }
                }
            }
#pragma unroll
            for (int j = 0; j < 3; j++) {
                if (j < nv) {
                    int arow = t * 40 + nrow[j];
                    u32 byte = (u32)arow * 128 + (u32)lane * 4;
                    u32 sw = byte ^ ((byte >> 3) & 0x70);
                    float f0, f1;
                    u16 h0, l0, h1, l1;
                    unpk2(a1[j], f0, f1);
                    bfsplit(f0, h0, l0);
                    bfsplit(f1, h1, l1);
                    *(u32*)(sm + CH_OFF_A + 32768 + sw) = ((u32)h1 << 16) | h0;
                    *(u32*)(sm + CH_OFF_A + 49152 + sw) = ((u32)l1 << 16) | l0;
                    unpk2(a2[j], f0, f1);
                    bfsplit(f0, h0, l0);
                    bfsplit(f1, h1, l1);
                    *(u32*)(sm + CH_OFF_A + 65536 + sw) = ((u32)h1 << 16) | h0;
                    *(u32*)(sm + CH_OFF_A + 81920 + sw) = ((u32)l1 << 16) | l0;
                }
            }
        }
        __syncthreads();

        // GEMM: O = relu([Z|X1|X2] * Veff + bias), M=128(120 valid), N=64, K=192
        float acc[4][4];
#pragma unroll
        for (int ot = 0; ot < 4; ot++)
#pragma unroll
            for (int c = 0; c < 4; c++) acc[ot][c] = 0.f;

#pragma unroll
        for (int chunk = 0; chunk < 3; chunk++) {
            u32 aHiBase = CH_OFF_A + (u32)chunk * 32768u;
            u32 breg = sbase + CH_OFF_W + (u32)chunk * 16384u + b_sreg;
#pragma unroll
            for (int kc = 0; kc < 4; kc++) {
                u32 ah[4], al[4];
                {
                    u32 rb = (u32)(warp_m * 16) + a_row_l;
                    u32 byte = rb * 128 + (u32)(kc * 32) + a_koff;
                    u32 sw = byte ^ ((byte >> 3) & 0x70);
                    ldsm_x4(ah, sbase + aHiBase + sw);
                    ldsm_x4(al, sbase + aHiBase + 16384u + sw);
                }
                u32 bf[4][4];
#pragma unroll
                for (int ot = 0; ot < 4; ot++) {
                    u32 byte = (u32)(o0 + 8 * ot + (int)b_row_l) * 128 + (u32)(kc * 32) + b_koff;
                    ldsm_x4(bf[ot], breg + (byte ^ ((byte >> 3) & 0x70)));
                }
#pragma unroll
                for (int ot = 0; ot < 4; ot++)
                    mma_bf16(acc[ot], ah, bf[ot][0], bf[ot][1]);
#pragma unroll
                for (int ot = 0; ot < 4; ot++)
                    mma_bf16(acc[ot], al, bf[ot][0], bf[ot][1]);
#pragma unroll
                for (int ot = 0; ot < 4; ot++)
                    mma_bf16(acc[ot], ah, bf[ot][2], bf[ot][3]);
            }
        }

#pragma unroll
        for (int rs = 0; rs < 2; rs++) {
            int r = warp_m * 16 + trow + rs * 8;
            if (r < 120) {
                int n = r % 40;
                int t = t0 + r / 40;
                if (n < NNODE && t < T) {
                    float* op = out + (bbase + r) * 64;
#pragma unroll
                    for (int ot = 0; ot < 4; ot++) {
                        int o = o0 + 8 * ot + tcol;
                        float2 hv;
                        hv.x = fmaxf(acc[ot][rs * 2 + 0] + sbias[o + 0], 0.f);
                        hv.y = fmaxf(acc[ot][rs * 2 + 1] + sbias[o + 1], 0.f);
                        *(float2*)(op + o) = hv;
                    }
                }
            }
        }
    }
}

// ---------------- BN stats ----------------
__global__ void __launch_bounds__(256)
bnstats_kernel(const float* __restrict__ x, int T,
               double* __restrict__ bnsum, double* __restrict__ bnsqs) {
    const int n = blockIdx.x, b = blockIdx.y, tid = threadIdx.x;
    const float* xp = x + ((size_t)b * T * NSTR + n) * 64;
    double s = 0.0, q = 0.0;
    for (int i = tid; i < T * 16; i += 256) {
        int t = i >> 4, c4 = (i & 15) << 2;
        float4 v = *(const float4*)(xp + (size_t)t * NSTR * 64 + c4);
        s += (double)v.x + (double)v.y + (double)v.z + (double)v.w;
        q += (double)v.x * v.x + (double)v.y * v.y + (double)v.z * v.z + (double)v.w * v.w;
    }
    __shared__ double r1[256], r2[256];
    r1[tid] = s; r2[tid] = q;
    __syncthreads();
    for (int st = 128; st > 0; st >>= 1) {
        if (tid < st) { r1[tid] += r1[tid + st]; r2[tid] += r2[tid + st]; }
        __syncthreads();
    }
    if (tid == 0) {
        atomicAdd(&bnsum[n], r1[0]);
        atomicAdd(&bnsqs[n], r2[0]);
    }
}

// ---------------- BN finalize ----------------
__global__ void finalize_bn_kernel(const double* __restrict__ sum, const double* __restrict__ sqs,
                                   const float* __restrict__ gamma, const float* __restrict__ beta,
                                   double cnt, float* __restrict__ scl, float* __restrict__ shf) {
    int nn = threadIdx.x;
    if (nn < NNODE) {
        double m = sum[nn] / cnt;
        double v = sqs[nn] / cnt - m * m;
        double inv = 1.0 / sqrt(v + 1e-5);
        double sc = (double)gamma[nn] * inv;
        scl[nn] = (float)sc;
        shf[nn] = (float)((double)beta[nn] - m * sc);
    }
}

// ---------------- fused BN+relu+time-mean ----------------
__global__ void timemean_kernel(const float* __restrict__ x, int T,
                                const float* __restrict__ scl, const float* __restrict__ shf) {
    const int n = blockIdx.x, b = blockIdx.y, c = threadIdx.x;
    const float sc = scl[n], sh = shf[n];
    double s = 0.0;
#pragma unroll 4
    for (int t = 0; t < T; t++) {
        float v = x[(((size_t)b * T + t) * NSTR + n) * CH + c];
        v = fmaxf(fmaf(v, sc, sh), 0.f);
        s += (double)v;
    }
    g_M[(b * NNODE + n) * CH + c] = (float)(s / (double)T);
}

// ---------------- classifier ----------------
__global__ void __launch_bounds__(256)
fc_kernel(const float* __restrict__ w1, const float* __restrict__ b1,
          const float* __restrict__ w2, const float* __restrict__ b2,
          float* __restrict__ out) {
    __shared__ float ms[NNODE * CH];
    __shared__ float h1[256];
    const int b = blockIdx.x, tid = threadIdx.x;
    for (int i = tid; i < NNODE * CH; i += 256) ms[i] = g_M[b * NNODE * CH + i];
    __syncthreads();
    double acc = (double)b1[tid];
    for (int i = 0; i < NNODE * CH; i++) acc += (double)ms[i] * (double)w1[i * 256 + tid];
    h1[tid] = fmaxf((float)acc, 0.f);
    __syncthreads();
    if (tid < 10) {
        double a2 = (double)b2[tid];
        for (int i = 0; i < 256; i++) a2 += (double)h1[i] * (double)w2[i * 10 + tid];
        out[b * 10 + tid] = (float)a2;
    }
}

// ---------------- launch ----------------
extern "C" void kernel_launch(void* const* d_in, const int* in_sizes, int n_in,
                              void* d_out, int out_size) {
    const float* x        = (const float*)d_in[0];
    const int*   ei       = (const int*)d_in[1];
    const float* s1_tc1_w = (const float*)d_in[2];
    const float* s1_tc1_b = (const float*)d_in[3];
    const float* s1_cheb_w= (const float*)d_in[4];
    const float* s1_cheb_b= (const float*)d_in[5];
    const float* s1_tc2_w = (const float*)d_in[6];
    const float* s1_tc2_b = (const float*)d_in[7];
    const float* s1_bn_g  = (const float*)d_in[8];
    const float* s1_bn_b  = (const float*)d_in[9];
    const float* s2_tc1_w = (const float*)d_in[10];
    const float* s2_tc1_b = (const float*)d_in[11];
    const float* s2_cheb_w= (const float*)d_in[12];
    const float* s2_cheb_b= (const float*)d_in[13];
    const float* s2_tc2_w = (const float*)d_in[14];
    const float* s2_tc2_b = (const float*)d_in[15];
    const float* s2_bn_g  = (const float*)d_in[16];
    const float* s2_bn_b  = (const float*)d_in[17];
    const float* fc1_w    = (const float*)d_in[18];
    const float* fc1_b    = (const float*)d_in[19];
    const float* fc2_w    = (const float*)d_in[20];
    const float* fc2_b    = (const float*)d_in[21];

    float *bufA, *bufB, *scl1, *shf1, *scl2, *shf2;
    u32 *Bw1, *Bw2, *Bw3, *Cw1, *Cw2;
    double *sum1, *sqs1, *sum2, *sqs2;
    cudaGetSymbolAddress((void**)&bufA, g_bufA);
    cudaGetSymbolAddress((void**)&bufB, g_bufB);
    cudaGetSymbolAddress((void**)&Bw1, g_Bw1);
    cudaGetSymbolAddress((void**)&Bw2, g_Bw2);
    cudaGetSymbolAddress((void**)&Bw3, g_Bw3);
    cudaGetSymbolAddress((void**)&Cw1, g_Cw1);
    cudaGetSymbolAddress((void**)&Cw2, g_Cw2);
    cudaGetSymbolAddress((void**)&scl1, g_scl1);
    cudaGetSymbolAddress((void**)&shf1, g_shf1);
    cudaGetSymbolAddress((void**)&scl2, g_scl2);
    cudaGetSymbolAddress((void**)&shf2, g_shf2);
    cudaGetSymbolAddress((void**)&sum1, g_sum1);
    cudaGetSymbolAddress((void**)&sqs1, g_sqs1);
    cudaGetSymbolAddress((void**)&sum2, g_sum2);
    cudaGetSymbolAddress((void**)&sqs2, g_sqs2);

    cudaFuncSetAttribute(tconv_mma_kernel, cudaFuncAttributeMaxDynamicSharedMemorySize, TC_SMEM);
    cudaFuncSetAttribute(cheb_mma_kernel,  cudaFuncAttributeMaxDynamicSharedMemorySize, CH_DYN);

    const int ne = in_sizes[1] / 2;
    const int GRID = 148;

    // launch order: index 5 = first cheb_mma (profiled by ncu -s 5 -c 1)
    setup_kernel<<<1, 64>>>(ei, ne, s1_tc1_w);                                        // 0
    convert_cw_kernel<<<96, 256>>>(s1_cheb_w, Cw1, s2_cheb_w, Cw2);                   // 1
    convert_w_kernel<<<144, 256>>>(s1_tc2_w, Bw1);                                    // 2
    tconv3_kernel<<<GRID, dim3(64, 8)>>>(x, s1_tc1_b, bufA);                          // 3: T=510
    convert_w_kernel<<<144, 256>>>(s2_tc1_w, Bw2);                                    // 4
    cheb_mma_kernel<<<GRID, 512, CH_DYN>>>(bufA, 510, Cw1, s1_cheb_b, bufB);          // 5 (profiled)
    tconv_mma_kernel<<<GRID, 512, TC_SMEM>>>(bufB, 510, Bw1, s1_tc2_b,
                                             nullptr, nullptr, 0, bufA);              // 6: T=508
    convert_w_kernel<<<144, 256>>>(s2_tc2_w, Bw3);                                    // 7
    bnstats_kernel<<<dim3(NNODE, BATCH), 256>>>(bufA, 508, sum1, sqs1);               // 8
    finalize_bn_kernel<<<1, 64>>>(sum1, sqs1, s1_bn_g, s1_bn_b,
                                  (double)BATCH * 508.0 * 64.0, scl1, shf1);          // 9

    // ---- STConv 2 (BN1+relu fused into A-conversion) ----
    tconv_mma_kernel<<<GRID, 512, TC_SMEM>>>(bufA, 508, Bw2, s2_tc1_b,
                                             scl1, shf1, 1, bufB);                    // 10: T=506
    cheb_mma_kernel<<<GRID, 512, CH_DYN>>>(bufB, 506, Cw2, s2_cheb_b, bufA);          // 11
    tconv_mma_kernel<<<GRID, 512, TC_SMEM>>>(bufA, 506, Bw3, s2_tc2_b,
                                             nullptr, nullptr, 0, bufB);              // 12: T=504
    bnstats_kernel<<<dim3(NNODE, BATCH), 256>>>(bufB, 504, sum2, sqs2);               // 13
    finalize_bn_kernel<<<1, 64>>>(sum2, sqs2, s2_bn_g, s2_bn_b,
                                  (double)BATCH * 504.0 * 64.0, scl2, shf2);          // 14

    // ---- head ----
    timemean_kernel<<<dim3(NNODE, BATCH), 64>>>(bufB, 504, scl2, shf2);               // 15
    fc_kernel<<<BATCH, 256>>>(fc1_w, fc1_b, fc2_w, fc2_b, (float*)d_out);             // 16
}